// round 1
// baseline (speedup 1.0000x reference)
#include <cuda_runtime.h>
#include <cuda_bf16.h>
#include <cstdint>

#define BATCH 2
#define NSEQ  4096
#define CDIM  384
#define NH    6
#define HD    64
#define QK_SCALE 0.125f
#define L2E 1.4426950408889634f

// ---- scratch (allocation-free: __device__ globals) ----
__device__ float g_q[BATCH * NH * NSEQ * HD];     // [B,H,N,D]
__device__ float g_k[BATCH * NH * NSEQ * HD];
__device__ float g_v[BATCH * NH * NSEQ * HD];
__device__ float g_attn[BATCH * NSEQ * CDIM];     // [B,N,C] pre-proj

__device__ __forceinline__ float ex2f_fast(float x) {
    float y;
    asm("ex2.approx.f32 %0, %1;" : "=f"(y) : "f"(x));
    return y;
}

__device__ __forceinline__ float rmax16(float v) {
#pragma unroll
    for (int off = 8; off; off >>= 1)
        v = fmaxf(v, __shfl_xor_sync(0xffffffffu, v, off));
    return v;
}
__device__ __forceinline__ float rsum16(float v) {
#pragma unroll
    for (int off = 8; off; off >>= 1)
        v += __shfl_xor_sync(0xffffffffu, v, off);
    return v;
}

// ============================================================
// Kernel 1: QKV GEMM  [8192,384] @ [384,1152] -> Q/K/V [B,H,N,D]
// 64x64 tile, BK=16, 256 threads, 4x4 microtile.
// ============================================================
__global__ __launch_bounds__(256) void qkv_gemm_kernel(
    const float* __restrict__ x, const float* __restrict__ w)
{
    __shared__ float As[16][68];   // [k][m]  (X transposed)
    __shared__ float Bs[16][68];   // [k][n]

    const int tid = threadIdx.x;
    const int tx = tid & 15, ty = tid >> 4;
    const int row0 = blockIdx.y * 64;
    const int col0 = blockIdx.x * 64;

    const int xr = tid >> 2, xc4 = tid & 3;    // X tile: 64 rows x 4 float4
    const int wr = tid >> 4, wc4 = tid & 15;   // W tile: 16 rows x 16 float4

    float acc[4][4] = {};

    for (int k0 = 0; k0 < CDIM; k0 += 16) {
        float4 xv = *(const float4*)&x[(size_t)(row0 + xr) * CDIM + k0 + xc4 * 4];
        float4 wv = *(const float4*)&w[(size_t)(k0 + wr) * (3 * CDIM) + col0 + wc4 * 4];
        __syncthreads();
        As[xc4 * 4 + 0][xr] = xv.x;
        As[xc4 * 4 + 1][xr] = xv.y;
        As[xc4 * 4 + 2][xr] = xv.z;
        As[xc4 * 4 + 3][xr] = xv.w;
        *(float4*)&Bs[wr][wc4 * 4] = wv;
        __syncthreads();
#pragma unroll
        for (int k = 0; k < 16; k++) {
            float4 a = *(const float4*)&As[k][ty * 4];
            float4 b = *(const float4*)&Bs[k][tx * 4];
            acc[0][0] = fmaf(a.x, b.x, acc[0][0]);
            acc[0][1] = fmaf(a.x, b.y, acc[0][1]);
            acc[0][2] = fmaf(a.x, b.z, acc[0][2]);
            acc[0][3] = fmaf(a.x, b.w, acc[0][3]);
            acc[1][0] = fmaf(a.y, b.x, acc[1][0]);
            acc[1][1] = fmaf(a.y, b.y, acc[1][1]);
            acc[1][2] = fmaf(a.y, b.z, acc[1][2]);
            acc[1][3] = fmaf(a.y, b.w, acc[1][3]);
            acc[2][0] = fmaf(a.z, b.x, acc[2][0]);
            acc[2][1] = fmaf(a.z, b.y, acc[2][1]);
            acc[2][2] = fmaf(a.z, b.z, acc[2][2]);
            acc[2][3] = fmaf(a.z, b.w, acc[2][3]);
            acc[3][0] = fmaf(a.w, b.x, acc[3][0]);
            acc[3][1] = fmaf(a.w, b.y, acc[3][1]);
            acc[3][2] = fmaf(a.w, b.z, acc[3][2]);
            acc[3][3] = fmaf(a.w, b.w, acc[3][3]);
        }
    }

    // epilogue: each 64-col tile is entirely within one (which, head) region
    const int which = col0 / CDIM;             // 0=q, 1=k, 2=v
    const int h = (col0 % CDIM) / HD;
    float* dst = (which == 0) ? g_q : (which == 1) ? g_k : g_v;
#pragma unroll
    for (int i = 0; i < 4; i++) {
        int m = row0 + ty * 4 + i;
        int b = m >> 12;
        int n = m & (NSEQ - 1);
        float4 o = make_float4(acc[i][0], acc[i][1], acc[i][2], acc[i][3]);
        *(float4*)&dst[(((size_t)(b * NH + h)) * NSEQ + n) * HD + tx * 4] = o;
    }
}

// ============================================================
// Kernel 2: flash attention per (64 Q-rows, b*h).
// Online softmax, 64-key blocks, 16x16 threads x 4x4 microtile.
// Dynamic smem: Qs,Ks (d-major), Vs (key-major), Ps (key-major, P^T)
// ============================================================
#define ATTN_SMEM_FLOATS (4 * 64 * 68)
#define ATTN_SMEM_BYTES  (ATTN_SMEM_FLOATS * 4)

__global__ __launch_bounds__(256) void attn_kernel()
{
    extern __shared__ float sm[];
    float* Qs = sm;                 // Qs[d*68 + row], pre-scaled by QK_SCALE
    float* Ks = sm + 64 * 68;       // Ks[d*68 + key]
    float* Vs = sm + 2 * 64 * 68;   // Vs[key*68 + d]
    float* Ps = sm + 3 * 64 * 68;   // Ps[key*68 + row]  (P transposed)

    const int tid = threadIdx.x;
    const int tx = tid & 15, ty = tid >> 4;
    const int bh = blockIdx.y;
    const int r0 = blockIdx.x * 64;

    const float* Qg = g_q + (size_t)bh * NSEQ * HD;
    const float* Kg = g_k + (size_t)bh * NSEQ * HD;
    const float* Vg = g_v + (size_t)bh * NSEQ * HD;

    // load Q tile transposed + pre-scaled
#pragma unroll
    for (int it = 0; it < 4; it++) {
        int idx = tid + it * 256;
        int r = idx >> 4, c4 = idx & 15;
        float4 v = *(const float4*)&Qg[(size_t)(r0 + r) * HD + c4 * 4];
        Qs[(c4 * 4 + 0) * 68 + r] = v.x * QK_SCALE;
        Qs[(c4 * 4 + 1) * 68 + r] = v.y * QK_SCALE;
        Qs[(c4 * 4 + 2) * 68 + r] = v.z * QK_SCALE;
        Qs[(c4 * 4 + 3) * 68 + r] = v.w * QK_SCALE;
    }

    float m_i[4], l_i[4], acc[4][4];
#pragma unroll
    for (int i = 0; i < 4; i++) {
        m_i[i] = -1e30f;
        l_i[i] = 0.0f;
#pragma unroll
        for (int j = 0; j < 4; j++) acc[i][j] = 0.0f;
    }

    for (int kb = 0; kb < NSEQ / 64; kb++) {
        __syncthreads();  // prior iteration's reads of Ks/Vs/Ps done (also covers Qs writes)
        const int kr0 = kb * 64;
#pragma unroll
        for (int it = 0; it < 4; it++) {
            int idx = tid + it * 256;
            int r = idx >> 4, c4 = idx & 15;
            float4 kv = *(const float4*)&Kg[(size_t)(kr0 + r) * HD + c4 * 4];
            Ks[(c4 * 4 + 0) * 68 + r] = kv.x;
            Ks[(c4 * 4 + 1) * 68 + r] = kv.y;
            Ks[(c4 * 4 + 2) * 68 + r] = kv.z;
            Ks[(c4 * 4 + 3) * 68 + r] = kv.w;
            float4 vv = *(const float4*)&Vg[(size_t)(kr0 + r) * HD + c4 * 4];
            *(float4*)&Vs[r * 68 + c4 * 4] = vv;
        }
        __syncthreads();

        // S = (Q*scale) K^T  : 4x4 per thread
        float s[4][4] = {};
#pragma unroll 8
        for (int d = 0; d < 64; d++) {
            float4 a = *(const float4*)&Qs[d * 68 + ty * 4];
            float4 b = *(const float4*)&Ks[d * 68 + tx * 4];
            s[0][0] = fmaf(a.x, b.x, s[0][0]);
            s[0][1] = fmaf(a.x, b.y, s[0][1]);
            s[0][2] = fmaf(a.x, b.z, s[0][2]);
            s[0][3] = fmaf(a.x, b.w, s[0][3]);
            s[1][0] = fmaf(a.y, b.x, s[1][0]);
            s[1][1] = fmaf(a.y, b.y, s[1][1]);
            s[1][2] = fmaf(a.y, b.z, s[1][2]);
            s[1][3] = fmaf(a.y, b.w, s[1][3]);
            s[2][0] = fmaf(a.z, b.x, s[2][0]);
            s[2][1] = fmaf(a.z, b.y, s[2][1]);
            s[2][2] = fmaf(a.z, b.z, s[2][2]);
            s[2][3] = fmaf(a.z, b.w, s[2][3]);
            s[3][0] = fmaf(a.w, b.x, s[3][0]);
            s[3][1] = fmaf(a.w, b.y, s[3][1]);
            s[3][2] = fmaf(a.w, b.z, s[3][2]);
            s[3][3] = fmaf(a.w, b.w, s[3][3]);
        }

        // online softmax per row (reduce across the 16 tx lanes)
#pragma unroll
        for (int i = 0; i < 4; i++) {
            float mx = fmaxf(fmaxf(s[i][0], s[i][1]), fmaxf(s[i][2], s[i][3]));
            mx = rmax16(mx);
            float mnew = fmaxf(m_i[i], mx);
            float corr = ex2f_fast((m_i[i] - mnew) * L2E);
            m_i[i] = mnew;
            float rs = 0.0f;
#pragma unroll
            for (int j = 0; j < 4; j++) {
                s[i][j] = ex2f_fast((s[i][j] - mnew) * L2E);
                rs += s[i][j];
            }
            rs = rsum16(rs);
            l_i[i] = l_i[i] * corr + rs;
            acc[i][0] *= corr;
            acc[i][1] *= corr;
            acc[i][2] *= corr;
            acc[i][3] *= corr;
            // store P transposed: Ps[key][row]
#pragma unroll
            for (int j = 0; j < 4; j++)
                Ps[(tx * 4 + j) * 68 + ty * 4 + i] = s[i][j];
        }
        __syncthreads();

        // O += P V : acc[r][d] += sum_k Ps[k][r] * Vs[k][d]
#pragma unroll 8
        for (int k = 0; k < 64; k++) {
            float4 a = *(const float4*)&Ps[k * 68 + ty * 4];
            float4 b = *(const float4*)&Vs[k * 68 + tx * 4];
            acc[0][0] = fmaf(a.x, b.x, acc[0][0]);
            acc[0][1] = fmaf(a.x, b.y, acc[0][1]);
            acc[0][2] = fmaf(a.x, b.z, acc[0][2]);
            acc[0][3] = fmaf(a.x, b.w, acc[0][3]);
            acc[1][0] = fmaf(a.y, b.x, acc[1][0]);
            acc[1][1] = fmaf(a.y, b.y, acc[1][1]);
            acc[1][2] = fmaf(a.y, b.z, acc[1][2]);
            acc[1][3] = fmaf(a.y, b.w, acc[1][3]);
            acc[2][0] = fmaf(a.z, b.x, acc[2][0]);
            acc[2][1] = fmaf(a.z, b.y, acc[2][1]);
            acc[2][2] = fmaf(a.z, b.z, acc[2][2]);
            acc[2][3] = fmaf(a.z, b.w, acc[2][3]);
            acc[3][0] = fmaf(a.w, b.x, acc[3][0]);
            acc[3][1] = fmaf(a.w, b.y, acc[3][1]);
            acc[3][2] = fmaf(a.w, b.z, acc[3][2]);
            acc[3][3] = fmaf(a.w, b.w, acc[3][3]);
        }
    }

    // epilogue: O /= l, write [B,N,C] layout
    const int b = bh / NH, h = bh % NH;
#pragma unroll
    for (int i = 0; i < 4; i++) {
        float inv = 1.0f / l_i[i];
        int n = r0 + ty * 4 + i;
        float4 o = make_float4(acc[i][0] * inv, acc[i][1] * inv,
                               acc[i][2] * inv, acc[i][3] * inv);
        *(float4*)&g_attn[((size_t)b * NSEQ + n) * CDIM + h * HD + tx * 4] = o;
    }
}

// ============================================================
// Kernel 3: proj GEMM + bias  [8192,384] @ [384,384] + b -> out
// ============================================================
__global__ __launch_bounds__(256) void proj_gemm_kernel(
    const float* __restrict__ w, const float* __restrict__ bias,
    float* __restrict__ out)
{
    __shared__ float As[16][68];
    __shared__ float Bs[16][68];

    const int tid = threadIdx.x;
    const int tx = tid & 15, ty = tid >> 4;
    const int row0 = blockIdx.y * 64;
    const int col0 = blockIdx.x * 64;

    const int xr = tid >> 2, xc4 = tid & 3;
    const int wr = tid >> 4, wc4 = tid & 15;

    float acc[4][4] = {};

    for (int k0 = 0; k0 < CDIM; k0 += 16) {
        float4 xv = *(const float4*)&g_attn[(size_t)(row0 + xr) * CDIM + k0 + xc4 * 4];
        float4 wv = *(const float4*)&w[(size_t)(k0 + wr) * CDIM + col0 + wc4 * 4];
        __syncthreads();
        As[xc4 * 4 + 0][xr] = xv.x;
        As[xc4 * 4 + 1][xr] = xv.y;
        As[xc4 * 4 + 2][xr] = xv.z;
        As[xc4 * 4 + 3][xr] = xv.w;
        *(float4*)&Bs[wr][wc4 * 4] = wv;
        __syncthreads();
#pragma unroll
        for (int k = 0; k < 16; k++) {
            float4 a = *(const float4*)&As[k][ty * 4];
            float4 b = *(const float4*)&Bs[k][tx * 4];
            acc[0][0] = fmaf(a.x, b.x, acc[0][0]);
            acc[0][1] = fmaf(a.x, b.y, acc[0][1]);
            acc[0][2] = fmaf(a.x, b.z, acc[0][2]);
            acc[0][3] = fmaf(a.x, b.w, acc[0][3]);
            acc[1][0] = fmaf(a.y, b.x, acc[1][0]);
            acc[1][1] = fmaf(a.y, b.y, acc[1][1]);
            acc[1][2] = fmaf(a.y, b.z, acc[1][2]);
            acc[1][3] = fmaf(a.y, b.w, acc[1][3]);
            acc[2][0] = fmaf(a.z, b.x, acc[2][0]);
            acc[2][1] = fmaf(a.z, b.y, acc[2][1]);
            acc[2][2] = fmaf(a.z, b.z, acc[2][2]);
            acc[2][3] = fmaf(a.z, b.w, acc[2][3]);
            acc[3][0] = fmaf(a.w, b.x, acc[3][0]);
            acc[3][1] = fmaf(a.w, b.y, acc[3][1]);
            acc[3][2] = fmaf(a.w, b.z, acc[3][2]);
            acc[3][3] = fmaf(a.w, b.w, acc[3][3]);
        }
    }

    float4 bv = *(const float4*)&bias[col0 + tx * 4];
#pragma unroll
    for (int i = 0; i < 4; i++) {
        int m = row0 + ty * 4 + i;
        float4 o = make_float4(acc[i][0] + bv.x, acc[i][1] + bv.y,
                               acc[i][2] + bv.z, acc[i][3] + bv.w);
        *(float4*)&out[(size_t)m * CDIM + col0 + tx * 4] = o;
    }
}

// ============================================================
extern "C" void kernel_launch(void* const* d_in, const int* in_sizes, int n_in,
                              void* d_out, int out_size)
{
    const float* x      = (const float*)d_in[0];
    const float* w_qkv  = (const float*)d_in[1];
    const float* w_proj = (const float*)d_in[2];
    const float* b_proj = (const float*)d_in[3];
    float* out = (float*)d_out;

    (void)in_sizes; (void)n_in; (void)out_size;

    // opt-in to >48KB dynamic smem for the attention kernel (idempotent, not a stream op)
    cudaFuncSetAttribute(attn_kernel,
                         cudaFuncAttributeMaxDynamicSharedMemorySize,
                         ATTN_SMEM_BYTES);

    // 1) QKV projection
    qkv_gemm_kernel<<<dim3(3 * CDIM / 64, (BATCH * NSEQ) / 64), 256>>>(x, w_qkv);

    // 2) flash attention per (row-tile, b*h)
    attn_kernel<<<dim3(NSEQ / 64, BATCH * NH), 256, ATTN_SMEM_BYTES>>>();

    // 3) output projection + bias
    proj_gemm_kernel<<<dim3(CDIM / 64, (BATCH * NSEQ) / 64), 256>>>(w_proj, b_proj, out);
}

// round 3
// speedup vs baseline: 2.3993x; 2.3993x over previous
#include <cuda_runtime.h>
#include <cuda_bf16.h>
#include <cstdint>

#define BATCH 2
#define NSEQ  4096
#define CDIM  384
#define NH    6
#define HD    64
#define BH_TOT (BATCH * NH)
#define QK_SCALE 0.125f
#define L2E 1.4426950408889634f

// ================= scratch (allocation-free: __device__ globals) =============
__device__ __nv_bfloat16 g_qh[BH_TOT * NSEQ * HD];   // [BH,N,64]  pre-scaled by 0.125
__device__ __nv_bfloat16 g_ql[BH_TOT * NSEQ * HD];
__device__ __nv_bfloat16 g_kh[BH_TOT * NSEQ * HD];   // [BH,N,64]
__device__ __nv_bfloat16 g_kl[BH_TOT * NSEQ * HD];
__device__ __nv_bfloat16 g_vh[BH_TOT * NSEQ * HD];   // [BH,N,64]
__device__ __nv_bfloat16 g_vl[BH_TOT * NSEQ * HD];
__device__ float g_attn[BATCH * NSEQ * CDIM];        // [B,N,C] pre-proj

__device__ __forceinline__ float ex2f_fast(float x) {
    float y;
    asm("ex2.approx.f32 %0, %1;" : "=f"(y) : "f"(x));
    return y;
}

__device__ __forceinline__ uint32_t bfpack(__nv_bfloat16 a, __nv_bfloat16 b) {
    return ((uint32_t)__bfloat16_as_ushort(b) << 16) | (uint32_t)__bfloat16_as_ushort(a);
}

// split two floats into packed bf16 hi pair + bf16 lo (residual) pair
__device__ __forceinline__ void split2(float a, float b, uint32_t& hi, uint32_t& lo) {
    __nv_bfloat16 ah = __float2bfloat16(a);
    __nv_bfloat16 bh = __float2bfloat16(b);
    __nv_bfloat16 al = __float2bfloat16(a - __bfloat162float(ah));
    __nv_bfloat16 bl = __float2bfloat16(b - __bfloat162float(bh));
    hi = bfpack(ah, bh);
    lo = bfpack(al, bl);
}

__device__ __forceinline__ uint32_t smem_u32(const void* p) {
    uint32_t a;
    asm("{ .reg .u64 t; cvta.to.shared.u64 t, %1; cvt.u32.u64 %0, t; }" : "=r"(a) : "l"(p));
    return a;
}

__device__ __forceinline__ void ldsm_x2(uint32_t& r0, uint32_t& r1, uint32_t addr) {
    asm volatile("ldmatrix.sync.aligned.m8n8.x2.shared.b16 {%0,%1}, [%2];"
                 : "=r"(r0), "=r"(r1) : "r"(addr));
}
__device__ __forceinline__ void ldsm_x2_t(uint32_t& r0, uint32_t& r1, uint32_t addr) {
    asm volatile("ldmatrix.sync.aligned.m8n8.x2.trans.shared.b16 {%0,%1}, [%2];"
                 : "=r"(r0), "=r"(r1) : "r"(addr));
}

#define MMA16816(d, a, b) \
    asm volatile( \
        "mma.sync.aligned.m16n8k16.row.col.f32.bf16.bf16.f32 " \
        "{%0,%1,%2,%3}, {%4,%5,%6,%7}, {%8,%9}, {%0,%1,%2,%3};" \
        : "+f"((d)[0]), "+f"((d)[1]), "+f"((d)[2]), "+f"((d)[3]) \
        : "r"((a)[0]), "r"((a)[1]), "r"((a)[2]), "r"((a)[3]), \
          "r"((b)[0]), "r"((b)[1]))

// ============================================================
// Kernel 1: QKV GEMM  [8192,384] @ [384,1152]
// epilogue: Q(x0.125)/K/V -> bf16 hi/lo [BH,N,64]
// ============================================================
__global__ __launch_bounds__(256) void qkv_gemm_kernel(
    const float* __restrict__ x, const float* __restrict__ w)
{
    __shared__ float As[16][68];
    __shared__ float Bs[16][68];

    const int tid = threadIdx.x;
    const int tx = tid & 15, ty = tid >> 4;
    const int row0 = blockIdx.y * 64;
    const int col0 = blockIdx.x * 64;

    const int xr = tid >> 2, xc4 = tid & 3;
    const int wr = tid >> 4, wc4 = tid & 15;

    float acc[4][4] = {};

    for (int k0 = 0; k0 < CDIM; k0 += 16) {
        float4 xv = *(const float4*)&x[(size_t)(row0 + xr) * CDIM + k0 + xc4 * 4];
        float4 wv = *(const float4*)&w[(size_t)(k0 + wr) * (3 * CDIM) + col0 + wc4 * 4];
        __syncthreads();
        As[xc4 * 4 + 0][xr] = xv.x;
        As[xc4 * 4 + 1][xr] = xv.y;
        As[xc4 * 4 + 2][xr] = xv.z;
        As[xc4 * 4 + 3][xr] = xv.w;
        *(float4*)&Bs[wr][wc4 * 4] = wv;
        __syncthreads();
#pragma unroll
        for (int k = 0; k < 16; k++) {
            float4 a = *(const float4*)&As[k][ty * 4];
            float4 b = *(const float4*)&Bs[k][tx * 4];
            acc[0][0] = fmaf(a.x, b.x, acc[0][0]);
            acc[0][1] = fmaf(a.x, b.y, acc[0][1]);
            acc[0][2] = fmaf(a.x, b.z, acc[0][2]);
            acc[0][3] = fmaf(a.x, b.w, acc[0][3]);
            acc[1][0] = fmaf(a.y, b.x, acc[1][0]);
            acc[1][1] = fmaf(a.y, b.y, acc[1][1]);
            acc[1][2] = fmaf(a.y, b.z, acc[1][2]);
            acc[1][3] = fmaf(a.y, b.w, acc[1][3]);
            acc[2][0] = fmaf(a.z, b.x, acc[2][0]);
            acc[2][1] = fmaf(a.z, b.y, acc[2][1]);
            acc[2][2] = fmaf(a.z, b.z, acc[2][2]);
            acc[2][3] = fmaf(a.z, b.w, acc[2][3]);
            acc[3][0] = fmaf(a.w, b.x, acc[3][0]);
            acc[3][1] = fmaf(a.w, b.y, acc[3][1]);
            acc[3][2] = fmaf(a.w, b.z, acc[3][2]);
            acc[3][3] = fmaf(a.w, b.w, acc[3][3]);
        }
    }

    const int which = col0 / CDIM;               // 0=q, 1=k, 2=v
    const int h = (col0 % CDIM) / HD;
    const float sc = (which == 0) ? QK_SCALE : 1.0f;
    __nv_bfloat16* hp = (which == 0) ? g_qh : (which == 1) ? g_kh : g_vh;
    __nv_bfloat16* lp = (which == 0) ? g_ql : (which == 1) ? g_kl : g_vl;
#pragma unroll
    for (int i = 0; i < 4; i++) {
        int m = row0 + ty * 4 + i;
        int b = m >> 12, n = m & (NSEQ - 1);
        int bh = b * NH + h;
        uint32_t h01, l01, h23, l23;
        split2(acc[i][0] * sc, acc[i][1] * sc, h01, l01);
        split2(acc[i][2] * sc, acc[i][3] * sc, h23, l23);
        size_t base = ((size_t)bh * NSEQ + n) * HD + tx * 4;
        uint2 uh; uh.x = h01; uh.y = h23;
        uint2 ul; ul.x = l01; ul.y = l23;
        *reinterpret_cast<uint2*>(&hp[base]) = uh;
        *reinterpret_cast<uint2*>(&lp[base]) = ul;
    }
}

// ============================================================
// Kernel 2: flash attention via mma.sync (bf16 hi/lo split).
// CTA = 128 Q rows x one (b,h), 8 warps, 64-key blocks.
// smem: Kh/Kl/Vh/Vl 64x64 bf16, XOR-swizzled rows of 128B.
// ============================================================
#define SK_H 0
#define SK_L 8192
#define SV_H 16384
#define SV_L 24576

__global__ __launch_bounds__(256) void attn_mma_kernel()
{
    __shared__ char smem[32768];
    const uint32_t sbase = smem_u32(smem);

    const int tid = threadIdx.x;
    const int warp = tid >> 5, lane = tid & 31;
    const int bh = blockIdx.y;
    const int r0 = blockIdx.x * 128;
    const int R = r0 + warp * 16;

    const int l8 = lane & 7;            // ldmatrix row-within-tile
    const int hseg = (lane >> 3) & 1;   // ldmatrix tile select (x2)
    const int rA = R + (lane >> 2);     // fragment row A (row B = rA+8)
    const int kcol = (lane & 3) * 2;

    const __nv_bfloat16* Qh = g_qh + (size_t)bh * NSEQ * HD;
    const __nv_bfloat16* Ql = g_ql + (size_t)bh * NSEQ * HD;
    const __nv_bfloat16* Kh = g_kh + (size_t)bh * NSEQ * HD;
    const __nv_bfloat16* Kl = g_kl + (size_t)bh * NSEQ * HD;
    const __nv_bfloat16* Vh = g_vh + (size_t)bh * NSEQ * HD;
    const __nv_bfloat16* Vl = g_vl + (size_t)bh * NSEQ * HD;

    // ---- Q a-fragments in registers (hi/lo), 4 k-steps ----
    uint32_t qah[4][4], qal[4][4];
#pragma unroll
    for (int s = 0; s < 4; s++) {
        qah[s][0] = *(const uint32_t*)&Qh[(size_t)rA * HD + s * 16 + kcol];
        qah[s][1] = *(const uint32_t*)&Qh[(size_t)(rA + 8) * HD + s * 16 + kcol];
        qah[s][2] = *(const uint32_t*)&Qh[(size_t)rA * HD + s * 16 + 8 + kcol];
        qah[s][3] = *(const uint32_t*)&Qh[(size_t)(rA + 8) * HD + s * 16 + 8 + kcol];
        qal[s][0] = *(const uint32_t*)&Ql[(size_t)rA * HD + s * 16 + kcol];
        qal[s][1] = *(const uint32_t*)&Ql[(size_t)(rA + 8) * HD + s * 16 + kcol];
        qal[s][2] = *(const uint32_t*)&Ql[(size_t)rA * HD + s * 16 + 8 + kcol];
        qal[s][3] = *(const uint32_t*)&Ql[(size_t)(rA + 8) * HD + s * 16 + 8 + kcol];
    }

    float of[8][4];
#pragma unroll
    for (int j = 0; j < 8; j++)
#pragma unroll
        for (int i = 0; i < 4; i++) of[j][i] = 0.0f;
    float mA = -1e30f, mB = -1e30f, lA = 0.0f, lB = 0.0f;

    // swizzled smem offsets for ldmatrix (per-lane constants)
    // K b-frag (j=key frag, s=kstep):  addr = SK + j*1024 + l8*128 + (((2s+hseg)^l8)<<4)
    // V b-frag (j=d frag, s=kstep):    addr = SV + (16s + 8*hseg + l8)*128 + ((j^l8)<<4)
    const uint32_t krow = (uint32_t)(l8 * 128);
    const uint32_t vsw = (uint32_t)((l8 * 128) + 0);

    for (int kb = 0; kb < NSEQ / 64; kb++) {
        const int kr0 = kb * 64;

        __syncthreads();
        // ---- stage K/V hi/lo tiles (64 rows x 128B, XOR-8 chunk swizzle) ----
#pragma unroll
        for (int it = 0; it < 2; it++) {
            int idx = tid + it * 256;          // 0..511
            int row = idx >> 3, ch = idx & 7;
            uint32_t sw = (uint32_t)(row * 128 + ((ch ^ (row & 7)) << 4));
            size_t g = (size_t)(kr0 + row) * HD + ch * 8;
            *(uint4*)(smem + SK_H + sw) = *(const uint4*)&Kh[g];
            *(uint4*)(smem + SK_L + sw) = *(const uint4*)&Kl[g];
            *(uint4*)(smem + SV_H + sw) = *(const uint4*)&Vh[g];
            *(uint4*)(smem + SV_L + sw) = *(const uint4*)&Vl[g];
        }
        __syncthreads();

        // ---- S = Q K^T (3 chains: hh, lh, hl) ----
        float sf[8][4];
#pragma unroll
        for (int j = 0; j < 8; j++)
#pragma unroll
            for (int i = 0; i < 4; i++) sf[j][i] = 0.0f;

#pragma unroll
        for (int s = 0; s < 4; s++) {
            uint32_t kbf[8][2];
            uint32_t chsw = (uint32_t)((((2 * s + hseg) ^ l8) << 4));
#pragma unroll
            for (int j = 0; j < 8; j++)
                ldsm_x2(kbf[j][0], kbf[j][1],
                        sbase + SK_H + (uint32_t)(j * 1024) + krow + chsw);
#pragma unroll
            for (int j = 0; j < 8; j++) MMA16816(sf[j], qah[s], kbf[j]);
#pragma unroll
            for (int j = 0; j < 8; j++) MMA16816(sf[j], qal[s], kbf[j]);
#pragma unroll
            for (int j = 0; j < 8; j++)
                ldsm_x2(kbf[j][0], kbf[j][1],
                        sbase + SK_L + (uint32_t)(j * 1024) + krow + chsw);
#pragma unroll
            for (int j = 0; j < 8; j++) MMA16816(sf[j], qah[s], kbf[j]);
        }

        // ---- online softmax (rows rA, rA+8; stats shared by 4-lane group) ----
        float mxA = sf[0][0], mxB = sf[0][2];
#pragma unroll
        for (int j = 0; j < 8; j++) {
            mxA = fmaxf(mxA, fmaxf(sf[j][0], sf[j][1]));
            mxB = fmaxf(mxB, fmaxf(sf[j][2], sf[j][3]));
        }
        mxA = fmaxf(mxA, __shfl_xor_sync(0xffffffffu, mxA, 1));
        mxA = fmaxf(mxA, __shfl_xor_sync(0xffffffffu, mxA, 2));
        mxB = fmaxf(mxB, __shfl_xor_sync(0xffffffffu, mxB, 1));
        mxB = fmaxf(mxB, __shfl_xor_sync(0xffffffffu, mxB, 2));

        float mnA = fmaxf(mA, mxA), mnB = fmaxf(mB, mxB);
        float corrA = ex2f_fast((mA - mnA) * L2E);
        float corrB = ex2f_fast((mB - mnB) * L2E);
        mA = mnA; mB = mnB;
        const float nlA = mnA * L2E, nlB = mnB * L2E;

        float sumA = 0.0f, sumB = 0.0f;
#pragma unroll
        for (int j = 0; j < 8; j++) {
            float p0 = ex2f_fast(fmaf(sf[j][0], L2E, -nlA));
            float p1 = ex2f_fast(fmaf(sf[j][1], L2E, -nlA));
            float p2 = ex2f_fast(fmaf(sf[j][2], L2E, -nlB));
            float p3 = ex2f_fast(fmaf(sf[j][3], L2E, -nlB));
            sumA += p0 + p1; sumB += p2 + p3;
            sf[j][0] = p0; sf[j][1] = p1; sf[j][2] = p2; sf[j][3] = p3;
        }
        lA = lA * corrA + sumA;
        lB = lB * corrB + sumB;

        // rescale O
#pragma unroll
        for (int j = 0; j < 8; j++) {
            of[j][0] *= corrA; of[j][1] *= corrA;
            of[j][2] *= corrB; of[j][3] *= corrB;
        }

        // ---- O += P V (3 chains: hh, lh, hl) ----
#pragma unroll
        for (int s = 0; s < 4; s++) {
            uint32_t pah[4], pal[4];
            split2(sf[2 * s][0], sf[2 * s][1], pah[0], pal[0]);
            split2(sf[2 * s][2], sf[2 * s][3], pah[1], pal[1]);
            split2(sf[2 * s + 1][0], sf[2 * s + 1][1], pah[2], pal[2]);
            split2(sf[2 * s + 1][2], sf[2 * s + 1][3], pah[3], pal[3]);

            uint32_t vrow = (uint32_t)((16 * s + 8 * hseg + l8) * 128);
            uint32_t vbf[8][2];
#pragma unroll
            for (int j = 0; j < 8; j++)
                ldsm_x2_t(vbf[j][0], vbf[j][1],
                          sbase + SV_H + vrow + (uint32_t)(((j ^ l8) << 4)));
#pragma unroll
            for (int j = 0; j < 8; j++) MMA16816(of[j], pah, vbf[j]);
#pragma unroll
            for (int j = 0; j < 8; j++) MMA16816(of[j], pal, vbf[j]);
#pragma unroll
            for (int j = 0; j < 8; j++)
                ldsm_x2_t(vbf[j][0], vbf[j][1],
                          sbase + SV_L + vrow + (uint32_t)(((j ^ l8) << 4)));
#pragma unroll
            for (int j = 0; j < 8; j++) MMA16816(of[j], pah, vbf[j]);
        }
    }

    // ---- epilogue ----
    lA += __shfl_xor_sync(0xffffffffu, lA, 1);
    lA += __shfl_xor_sync(0xffffffffu, lA, 2);
    lB += __shfl_xor_sync(0xffffffffu, lB, 1);
    lB += __shfl_xor_sync(0xffffffffu, lB, 2);
    const float invA = 1.0f / lA, invB = 1.0f / lB;

    const int b = bh / NH, h = bh % NH;
    float* dstA = g_attn + ((size_t)b * NSEQ + rA) * CDIM + h * HD;
    float* dstB = g_attn + ((size_t)b * NSEQ + rA + 8) * CDIM + h * HD;
#pragma unroll
    for (int j = 0; j < 8; j++) {
        int c = j * 8 + kcol;
        float2 oa = make_float2(of[j][0] * invA, of[j][1] * invA);
        float2 ob = make_float2(of[j][2] * invB, of[j][3] * invB);
        *(float2*)&dstA[c] = oa;
        *(float2*)&dstB[c] = ob;
    }
}

// ============================================================
// Kernel 3: proj GEMM + bias  [8192,384] @ [384,384] + b -> out
// ============================================================
__global__ __launch_bounds__(256) void proj_gemm_kernel(
    const float* __restrict__ w, const float* __restrict__ bias,
    float* __restrict__ out)
{
    __shared__ float As[16][68];
    __shared__ float Bs[16][68];

    const int tid = threadIdx.x;
    const int tx = tid & 15, ty = tid >> 4;
    const int row0 = blockIdx.y * 64;
    const int col0 = blockIdx.x * 64;

    const int xr = tid >> 2, xc4 = tid & 3;
    const int wr = tid >> 4, wc4 = tid & 15;

    float acc[4][4] = {};

    for (int k0 = 0; k0 < CDIM; k0 += 16) {
        float4 xv = *(const float4*)&g_attn[(size_t)(row0 + xr) * CDIM + k0 + xc4 * 4];
        float4 wv = *(const float4*)&w[(size_t)(k0 + wr) * CDIM + col0 + wc4 * 4];
        __syncthreads();
        As[xc4 * 4 + 0][xr] = xv.x;
        As[xc4 * 4 + 1][xr] = xv.y;
        As[xc4 * 4 + 2][xr] = xv.z;
        As[xc4 * 4 + 3][xr] = xv.w;
        *(float4*)&Bs[wr][wc4 * 4] = wv;
        __syncthreads();
#pragma unroll
        for (int k = 0; k < 16; k++) {
            float4 a = *(const float4*)&As[k][ty * 4];
            float4 b = *(const float4*)&Bs[k][tx * 4];
            acc[0][0] = fmaf(a.x, b.x, acc[0][0]);
            acc[0][1] = fmaf(a.x, b.y, acc[0][1]);
            acc[0][2] = fmaf(a.x, b.z, acc[0][2]);
            acc[0][3] = fmaf(a.x, b.w, acc[0][3]);
            acc[1][0] = fmaf(a.y, b.x, acc[1][0]);
            acc[1][1] = fmaf(a.y, b.y, acc[1][1]);
            acc[1][2] = fmaf(a.y, b.z, acc[1][2]);
            acc[1][3] = fmaf(a.y, b.w, acc[1][3]);
            acc[2][0] = fmaf(a.z, b.x, acc[2][0]);
            acc[2][1] = fmaf(a.z, b.y, acc[2][1]);
            acc[2][2] = fmaf(a.z, b.z, acc[2][2]);
            acc[2][3] = fmaf(a.z, b.w, acc[2][3]);
            acc[3][0] = fmaf(a.w, b.x, acc[3][0]);
            acc[3][1] = fmaf(a.w, b.y, acc[3][1]);
            acc[3][2] = fmaf(a.w, b.z, acc[3][2]);
            acc[3][3] = fmaf(a.w, b.w, acc[3][3]);
        }
    }

    float4 bv = *(const float4*)&bias[col0 + tx * 4];
#pragma unroll
    for (int i = 0; i < 4; i++) {
        int m = row0 + ty * 4 + i;
        float4 o = make_float4(acc[i][0] + bv.x, acc[i][1] + bv.y,
                               acc[i][2] + bv.z, acc[i][3] + bv.w);
        *(float4*)&out[(size_t)m * CDIM + col0 + tx * 4] = o;
    }
}

// ============================================================
extern "C" void kernel_launch(void* const* d_in, const int* in_sizes, int n_in,
                              void* d_out, int out_size)
{
    const float* x      = (const float*)d_in[0];
    const float* w_qkv  = (const float*)d_in[1];
    const float* w_proj = (const float*)d_in[2];
    const float* b_proj = (const float*)d_in[3];
    float* out = (float*)d_out;

    (void)in_sizes; (void)n_in; (void)out_size;

    qkv_gemm_kernel<<<dim3(3 * CDIM / 64, (BATCH * NSEQ) / 64), 256>>>(x, w_qkv);

    attn_mma_kernel<<<dim3(NSEQ / 128, BH_TOT), 256>>>();

    proj_gemm_kernel<<<dim3(CDIM / 64, (BATCH * NSEQ) / 64), 256>>>(w_proj, b_proj, out);
}

// round 4
// speedup vs baseline: 3.1457x; 1.3111x over previous
#include <cuda_runtime.h>
#include <cuda_bf16.h>
#include <cstdint>

#define BATCH 2
#define NSEQ  4096
#define CDIM  384
#define NH    6
#define HD    64
#define BH_TOT (BATCH * NH)
#define QK_SCALE 0.125f
#define L2E 1.4426950408889634f

// ================= scratch (allocation-free: __device__ globals) =============
__device__ __nv_bfloat16 g_qh[BH_TOT * NSEQ * HD];   // [BH,N,64]  pre-scaled by 0.125
__device__ __nv_bfloat16 g_ql[BH_TOT * NSEQ * HD];
__device__ __nv_bfloat16 g_kh[BH_TOT * NSEQ * HD];
__device__ __nv_bfloat16 g_kl[BH_TOT * NSEQ * HD];
__device__ __nv_bfloat16 g_vh[BH_TOT * NSEQ * HD];
__device__ __nv_bfloat16 g_vl[BH_TOT * NSEQ * HD];
__device__ __nv_bfloat16 g_oh[BATCH * NSEQ * CDIM];  // attention out [B,N,C] hi/lo
__device__ __nv_bfloat16 g_ol[BATCH * NSEQ * CDIM];

__device__ __forceinline__ float ex2f_fast(float x) {
    float y;
    asm("ex2.approx.f32 %0, %1;" : "=f"(y) : "f"(x));
    return y;
}

__device__ __forceinline__ uint32_t bfpack(__nv_bfloat16 a, __nv_bfloat16 b) {
    return ((uint32_t)__bfloat16_as_ushort(b) << 16) | (uint32_t)__bfloat16_as_ushort(a);
}

__device__ __forceinline__ void split2(float a, float b, uint32_t& hi, uint32_t& lo) {
    __nv_bfloat16 ah = __float2bfloat16(a);
    __nv_bfloat16 bh = __float2bfloat16(b);
    __nv_bfloat16 al = __float2bfloat16(a - __bfloat162float(ah));
    __nv_bfloat16 bl = __float2bfloat16(b - __bfloat162float(bh));
    hi = bfpack(ah, bh);
    lo = bfpack(al, bl);
}

__device__ __forceinline__ uint32_t smem_u32(const void* p) {
    uint32_t a;
    asm("{ .reg .u64 t; cvta.to.shared.u64 t, %1; cvt.u32.u64 %0, t; }" : "=r"(a) : "l"(p));
    return a;
}

__device__ __forceinline__ void ldsm_x2(uint32_t& r0, uint32_t& r1, uint32_t addr) {
    asm volatile("ldmatrix.sync.aligned.m8n8.x2.shared.b16 {%0,%1}, [%2];"
                 : "=r"(r0), "=r"(r1) : "r"(addr));
}
__device__ __forceinline__ void ldsm_x2_t(uint32_t& r0, uint32_t& r1, uint32_t addr) {
    asm volatile("ldmatrix.sync.aligned.m8n8.x2.trans.shared.b16 {%0,%1}, [%2];"
                 : "=r"(r0), "=r"(r1) : "r"(addr));
}
__device__ __forceinline__ void ldsm_x4(uint32_t* r, uint32_t addr) {
    asm volatile("ldmatrix.sync.aligned.m8n8.x4.shared.b16 {%0,%1,%2,%3}, [%4];"
                 : "=r"(r[0]), "=r"(r[1]), "=r"(r[2]), "=r"(r[3]) : "r"(addr));
}

#define MMA16816(d, a, b) \
    asm volatile( \
        "mma.sync.aligned.m16n8k16.row.col.f32.bf16.bf16.f32 " \
        "{%0,%1,%2,%3}, {%4,%5,%6,%7}, {%8,%9}, {%0,%1,%2,%3};" \
        : "+f"((d)[0]), "+f"((d)[1]), "+f"((d)[2]), "+f"((d)[3]) \
        : "r"((a)[0]), "r"((a)[1]), "r"((a)[2]), "r"((a)[3]), \
          "r"((b)[0]), "r"((b)[1]))

#define CP16(dst_u32, src_ptr) \
    asm volatile("cp.async.cg.shared.global [%0], [%1], 16;" :: "r"(dst_u32), "l"(src_ptr))
#define CP_COMMIT() asm volatile("cp.async.commit_group;" ::: "memory")
#define CP_WAIT1()  asm volatile("cp.async.wait_group 1;" ::: "memory")
#define CP_WAIT0()  asm volatile("cp.async.wait_group 0;" ::: "memory")

// ============================================================
// Kernel 1: QKV GEMM on tensor cores (bf16 hi/lo x 3 chains)
// [8192,384] @ [384,1152] -> Q(x0.125)/K/V bf16 hi/lo [BH,N,64]
// CTA 128x128, 8 warps (4m x 2n), K-step 32.
// ============================================================
__global__ __launch_bounds__(256) void qkv_tc_kernel(
    const float* __restrict__ x, const float* __restrict__ w)
{
    __shared__ char sm[36864];
    const int AH = 0, AL = 10240, BHo = 20480, BLo = 28672;  // A rows 80B, B rows 256B

    const int tid = threadIdx.x, warp = tid >> 5, lane = tid & 31;
    const int wm = (warp & 3) * 32, wn = (warp >> 2) * 64;
    const int row0 = blockIdx.y * 128, col0 = blockIdx.x * 128;
    const uint32_t sb = smem_u32(sm);
    const int l16 = lane & 15, l8 = lane & 7;

    float acc[2][8][4];
#pragma unroll
    for (int mi = 0; mi < 2; mi++)
#pragma unroll
        for (int j = 0; j < 8; j++)
#pragma unroll
            for (int i = 0; i < 4; i++) acc[mi][j][i] = 0.0f;

    for (int k0 = 0; k0 < CDIM; k0 += 32) {
        __syncthreads();
        // stage A: x fp32 -> bf16 hi/lo, [m][k] rows of 64B data, 80B stride
#pragma unroll
        for (int it = 0; it < 2; it++) {
            int idx = tid + it * 256;
            int row = idx >> 2, ch = idx & 3;
            const float* src = &x[(size_t)(row0 + row) * CDIM + k0 + ch * 8];
            float4 f0 = *(const float4*)src, f1 = *(const float4*)(src + 4);
            uint4 hv, lv;
            split2(f0.x, f0.y, hv.x, lv.x); split2(f0.z, f0.w, hv.y, lv.y);
            split2(f1.x, f1.y, hv.z, lv.z); split2(f1.z, f1.w, hv.w, lv.w);
            *(uint4*)(sm + AH + row * 80 + ch * 16) = hv;
            *(uint4*)(sm + AL + row * 80 + ch * 16) = lv;
        }
        // stage B: w fp32 -> bf16 hi/lo, [k][n] rows of 256B, XOR-8 swizzle
#pragma unroll
        for (int it = 0; it < 2; it++) {
            int idx = tid + it * 256;
            int row = idx >> 4, ch = idx & 15;
            const float* src = &w[(size_t)(k0 + row) * (3 * CDIM) + col0 + ch * 8];
            float4 f0 = *(const float4*)src, f1 = *(const float4*)(src + 4);
            uint4 hv, lv;
            split2(f0.x, f0.y, hv.x, lv.x); split2(f0.z, f0.w, hv.y, lv.y);
            split2(f1.x, f1.y, hv.z, lv.z); split2(f1.z, f1.w, hv.w, lv.w);
            int sw = row * 256 + ((ch ^ (row & 7)) << 4);
            *(uint4*)(sm + BHo + sw) = hv;
            *(uint4*)(sm + BLo + sw) = lv;
        }
        __syncthreads();

#pragma unroll
        for (int s = 0; s < 2; s++) {
            uint32_t ah[2][4], al[2][4];
            uint32_t arow = (uint32_t)((wm + l8 + 8 * ((lane >> 3) & 1)) * 80 +
                                       (2 * s + (lane >> 4)) * 16);
            ldsm_x4(ah[0], sb + AH + arow);
            ldsm_x4(ah[1], sb + AH + arow + 16 * 80);
            ldsm_x4(al[0], sb + AL + arow);
            ldsm_x4(al[1], sb + AL + arow + 16 * 80);

            uint32_t bf[8][2];
            const uint32_t brow = (uint32_t)((s * 16 + l16) * 256);
#pragma unroll
            for (int j = 0; j < 8; j++) {
                int jj = (wn >> 3) + j;
                ldsm_x2_t(bf[j][0], bf[j][1],
                          sb + BHo + brow + (uint32_t)(((jj ^ l8) << 4)));
            }
#pragma unroll
            for (int j = 0; j < 8; j++) {
                MMA16816(acc[0][j], ah[0], bf[j]);
                MMA16816(acc[1][j], ah[1], bf[j]);
            }
#pragma unroll
            for (int j = 0; j < 8; j++) {
                MMA16816(acc[0][j], al[0], bf[j]);
                MMA16816(acc[1][j], al[1], bf[j]);
            }
#pragma unroll
            for (int j = 0; j < 8; j++) {
                int jj = (wn >> 3) + j;
                ldsm_x2_t(bf[j][0], bf[j][1],
                          sb + BLo + brow + (uint32_t)(((jj ^ l8) << 4)));
            }
#pragma unroll
            for (int j = 0; j < 8; j++) {
                MMA16816(acc[0][j], ah[0], bf[j]);
                MMA16816(acc[1][j], ah[1], bf[j]);
            }
        }
    }

    // epilogue: split to q/k/v hi/lo [BH,N,64]
    const int gid = lane >> 2, tq = lane & 3;
#pragma unroll
    for (int j = 0; j < 8; j++) {
        int col = col0 + wn + j * 8 + tq * 2;
        int which = col / CDIM, cm = col % CDIM;
        int h = cm / HD, d = cm % HD;
        float sc = (which == 0) ? QK_SCALE : 1.0f;
        __nv_bfloat16* hp = (which == 0) ? g_qh : (which == 1) ? g_kh : g_vh;
        __nv_bfloat16* lp = (which == 0) ? g_ql : (which == 1) ? g_kl : g_vl;
#pragma unroll
        for (int mi = 0; mi < 2; mi++) {
#pragma unroll
            for (int rg = 0; rg < 2; rg++) {
                int m = row0 + wm + mi * 16 + gid + rg * 8;
                int b = m >> 12, n = m & (NSEQ - 1);
                size_t base = (((size_t)(b * NH + h)) * NSEQ + n) * HD + d;
                uint32_t hv, lv;
                split2(acc[mi][j][rg * 2] * sc, acc[mi][j][rg * 2 + 1] * sc, hv, lv);
                *(uint32_t*)&hp[base] = hv;
                *(uint32_t*)&lp[base] = lv;
            }
        }
    }
}

// ============================================================
// Kernel 2: flash attention via mma.sync, cp.async double-buffered K/V.
// CTA = 128 Q rows x one (b,h), 8 warps, 64-key blocks.
// ============================================================
#define STG 32768
#define SKH 0
#define SKL 8192
#define SVH 16384
#define SVL 24576
#define ATT_SMEM (2 * STG)

__global__ __launch_bounds__(256) void attn_mma_kernel()
{
    extern __shared__ char smem[];
    const uint32_t sbase = smem_u32(smem);

    const int tid = threadIdx.x;
    const int warp = tid >> 5, lane = tid & 31;
    const int bh = blockIdx.y;
    const int r0 = blockIdx.x * 128;
    const int R = r0 + warp * 16;

    const int l8 = lane & 7;
    const int hseg = (lane >> 3) & 1;
    const int rA = R + (lane >> 2);
    const int kcol = (lane & 3) * 2;

    const __nv_bfloat16* Qh = g_qh + (size_t)bh * NSEQ * HD;
    const __nv_bfloat16* Ql = g_ql + (size_t)bh * NSEQ * HD;
    const __nv_bfloat16* Kh = g_kh + (size_t)bh * NSEQ * HD;
    const __nv_bfloat16* Kl = g_kl + (size_t)bh * NSEQ * HD;
    const __nv_bfloat16* Vh = g_vh + (size_t)bh * NSEQ * HD;
    const __nv_bfloat16* Vl = g_vl + (size_t)bh * NSEQ * HD;

    // Q a-fragments in registers (hi/lo), 4 k-steps
    uint32_t qah[4][4], qal[4][4];
#pragma unroll
    for (int s = 0; s < 4; s++) {
        qah[s][0] = *(const uint32_t*)&Qh[(size_t)rA * HD + s * 16 + kcol];
        qah[s][1] = *(const uint32_t*)&Qh[(size_t)(rA + 8) * HD + s * 16 + kcol];
        qah[s][2] = *(const uint32_t*)&Qh[(size_t)rA * HD + s * 16 + 8 + kcol];
        qah[s][3] = *(const uint32_t*)&Qh[(size_t)(rA + 8) * HD + s * 16 + 8 + kcol];
        qal[s][0] = *(const uint32_t*)&Ql[(size_t)rA * HD + s * 16 + kcol];
        qal[s][1] = *(const uint32_t*)&Ql[(size_t)(rA + 8) * HD + s * 16 + kcol];
        qal[s][2] = *(const uint32_t*)&Ql[(size_t)rA * HD + s * 16 + 8 + kcol];
        qal[s][3] = *(const uint32_t*)&Ql[(size_t)(rA + 8) * HD + s * 16 + 8 + kcol];
    }

    float of[8][4];
#pragma unroll
    for (int j = 0; j < 8; j++)
#pragma unroll
        for (int i = 0; i < 4; i++) of[j][i] = 0.0f;
    float mA = -1e30f, mB = -1e30f, lA = 0.0f, lB = 0.0f;

    const uint32_t krow = (uint32_t)(l8 * 128);

    auto stage = [&](int st, int kr0) {
#pragma unroll
        for (int it = 0; it < 2; it++) {
            int idx = tid + it * 256;
            int row = idx >> 3, ch = idx & 7;
            uint32_t sw = (uint32_t)(st * STG + row * 128 + ((ch ^ (row & 7)) << 4));
            size_t g = (size_t)(kr0 + row) * HD + ch * 8;
            CP16(sbase + sw + SKH, Kh + g);
            CP16(sbase + sw + SKL, Kl + g);
            CP16(sbase + sw + SVH, Vh + g);
            CP16(sbase + sw + SVL, Vl + g);
        }
    };

    stage(0, 0);
    CP_COMMIT();

    for (int kb = 0; kb < NSEQ / 64; kb++) {
        if (kb < NSEQ / 64 - 1) {
            stage((kb + 1) & 1, (kb + 1) * 64);
            CP_COMMIT();
            CP_WAIT1();
        } else {
            CP_WAIT0();
        }
        __syncthreads();
        const uint32_t stb = sbase + (uint32_t)((kb & 1) * STG);

        // ---- S = Q K^T (3 chains) ----
        float sf[8][4];
#pragma unroll
        for (int j = 0; j < 8; j++)
#pragma unroll
            for (int i = 0; i < 4; i++) sf[j][i] = 0.0f;

#pragma unroll
        for (int s = 0; s < 4; s++) {
            uint32_t kbf[8][2];
            uint32_t chsw = (uint32_t)((((2 * s + hseg) ^ l8) << 4));
#pragma unroll
            for (int j = 0; j < 8; j++)
                ldsm_x2(kbf[j][0], kbf[j][1],
                        stb + SKH + (uint32_t)(j * 1024) + krow + chsw);
#pragma unroll
            for (int j = 0; j < 8; j++) MMA16816(sf[j], qah[s], kbf[j]);
#pragma unroll
            for (int j = 0; j < 8; j++) MMA16816(sf[j], qal[s], kbf[j]);
#pragma unroll
            for (int j = 0; j < 8; j++)
                ldsm_x2(kbf[j][0], kbf[j][1],
                        stb + SKL + (uint32_t)(j * 1024) + krow + chsw);
#pragma unroll
            for (int j = 0; j < 8; j++) MMA16816(sf[j], qah[s], kbf[j]);
        }

        // ---- online softmax ----
        float mxA = sf[0][0], mxB = sf[0][2];
#pragma unroll
        for (int j = 0; j < 8; j++) {
            mxA = fmaxf(mxA, fmaxf(sf[j][0], sf[j][1]));
            mxB = fmaxf(mxB, fmaxf(sf[j][2], sf[j][3]));
        }
        mxA = fmaxf(mxA, __shfl_xor_sync(0xffffffffu, mxA, 1));
        mxA = fmaxf(mxA, __shfl_xor_sync(0xffffffffu, mxA, 2));
        mxB = fmaxf(mxB, __shfl_xor_sync(0xffffffffu, mxB, 1));
        mxB = fmaxf(mxB, __shfl_xor_sync(0xffffffffu, mxB, 2));

        float mnA = fmaxf(mA, mxA), mnB = fmaxf(mB, mxB);
        float corrA = ex2f_fast((mA - mnA) * L2E);
        float corrB = ex2f_fast((mB - mnB) * L2E);
        mA = mnA; mB = mnB;
        const float nlA = mnA * L2E, nlB = mnB * L2E;

        float sumA = 0.0f, sumB = 0.0f;
#pragma unroll
        for (int j = 0; j < 8; j++) {
            float p0 = ex2f_fast(fmaf(sf[j][0], L2E, -nlA));
            float p1 = ex2f_fast(fmaf(sf[j][1], L2E, -nlA));
            float p2 = ex2f_fast(fmaf(sf[j][2], L2E, -nlB));
            float p3 = ex2f_fast(fmaf(sf[j][3], L2E, -nlB));
            sumA += p0 + p1; sumB += p2 + p3;
            sf[j][0] = p0; sf[j][1] = p1; sf[j][2] = p2; sf[j][3] = p3;
        }
        lA = lA * corrA + sumA;
        lB = lB * corrB + sumB;

#pragma unroll
        for (int j = 0; j < 8; j++) {
            of[j][0] *= corrA; of[j][1] *= corrA;
            of[j][2] *= corrB; of[j][3] *= corrB;
        }

        // ---- O += P V (3 chains) ----
#pragma unroll
        for (int s = 0; s < 4; s++) {
            uint32_t pah[4], pal[4];
            split2(sf[2 * s][0], sf[2 * s][1], pah[0], pal[0]);
            split2(sf[2 * s][2], sf[2 * s][3], pah[1], pal[1]);
            split2(sf[2 * s + 1][0], sf[2 * s + 1][1], pah[2], pal[2]);
            split2(sf[2 * s + 1][2], sf[2 * s + 1][3], pah[3], pal[3]);

            uint32_t vrow = (uint32_t)((16 * s + 8 * hseg + l8) * 128);
            uint32_t vbf[8][2];
#pragma unroll
            for (int j = 0; j < 8; j++)
                ldsm_x2_t(vbf[j][0], vbf[j][1],
                          stb + SVH + vrow + (uint32_t)(((j ^ l8) << 4)));
#pragma unroll
            for (int j = 0; j < 8; j++) MMA16816(of[j], pah, vbf[j]);
#pragma unroll
            for (int j = 0; j < 8; j++) MMA16816(of[j], pal, vbf[j]);
#pragma unroll
            for (int j = 0; j < 8; j++)
                ldsm_x2_t(vbf[j][0], vbf[j][1],
                          stb + SVL + vrow + (uint32_t)(((j ^ l8) << 4)));
#pragma unroll
            for (int j = 0; j < 8; j++) MMA16816(of[j], pah, vbf[j]);
        }
        __syncthreads();
    }

    // ---- epilogue: write O as bf16 hi/lo [B,N,C] ----
    lA += __shfl_xor_sync(0xffffffffu, lA, 1);
    lA += __shfl_xor_sync(0xffffffffu, lA, 2);
    lB += __shfl_xor_sync(0xffffffffu, lB, 1);
    lB += __shfl_xor_sync(0xffffffffu, lB, 2);
    const float invA = 1.0f / lA, invB = 1.0f / lB;

    const int b = bh / NH, h = bh % NH;
    size_t baseA = ((size_t)b * NSEQ + rA) * CDIM + h * HD;
    size_t baseB = ((size_t)b * NSEQ + rA + 8) * CDIM + h * HD;
#pragma unroll
    for (int j = 0; j < 8; j++) {
        int c = j * 8 + kcol;
        uint32_t hv, lv;
        split2(of[j][0] * invA, of[j][1] * invA, hv, lv);
        *(uint32_t*)&g_oh[baseA + c] = hv;
        *(uint32_t*)&g_ol[baseA + c] = lv;
        split2(of[j][2] * invB, of[j][3] * invB, hv, lv);
        *(uint32_t*)&g_oh[baseB + c] = hv;
        *(uint32_t*)&g_ol[baseB + c] = lv;
    }
}

// ============================================================
// Kernel 3: proj GEMM on tensor cores + bias -> out fp32
// A = g_oh/g_ol [8192,384] bf16, B = w_proj fp32 (split on stage)
// ============================================================
__global__ __launch_bounds__(256) void proj_tc_kernel(
    const float* __restrict__ w, const float* __restrict__ bias,
    float* __restrict__ out)
{
    __shared__ char sm[36864];
    const int AH = 0, AL = 10240, BHo = 20480, BLo = 28672;

    const int tid = threadIdx.x, warp = tid >> 5, lane = tid & 31;
    const int wm = (warp & 3) * 32, wn = (warp >> 2) * 64;
    const int row0 = blockIdx.y * 128, col0 = blockIdx.x * 128;
    const uint32_t sb = smem_u32(sm);
    const int l16 = lane & 15, l8 = lane & 7;

    float acc[2][8][4];
#pragma unroll
    for (int mi = 0; mi < 2; mi++)
#pragma unroll
        for (int j = 0; j < 8; j++)
#pragma unroll
            for (int i = 0; i < 4; i++) acc[mi][j][i] = 0.0f;

    for (int k0 = 0; k0 < CDIM; k0 += 32) {
        __syncthreads();
        // stage A: already bf16 hi/lo, straight copies
#pragma unroll
        for (int it = 0; it < 2; it++) {
            int idx = tid + it * 256;
            int row = idx >> 2, ch = idx & 3;
            size_t g = (size_t)(row0 + row) * CDIM + k0 + ch * 8;
            *(uint4*)(sm + AH + row * 80 + ch * 16) = *(const uint4*)&g_oh[g];
            *(uint4*)(sm + AL + row * 80 + ch * 16) = *(const uint4*)&g_ol[g];
        }
        // stage B: w fp32 -> bf16 hi/lo
#pragma unroll
        for (int it = 0; it < 2; it++) {
            int idx = tid + it * 256;
            int row = idx >> 4, ch = idx & 15;
            const float* src = &w[(size_t)(k0 + row) * CDIM + col0 + ch * 8];
            float4 f0 = *(const float4*)src, f1 = *(const float4*)(src + 4);
            uint4 hv, lv;
            split2(f0.x, f0.y, hv.x, lv.x); split2(f0.z, f0.w, hv.y, lv.y);
            split2(f1.x, f1.y, hv.z, lv.z); split2(f1.z, f1.w, hv.w, lv.w);
            int sw = row * 256 + ((ch ^ (row & 7)) << 4);
            *(uint4*)(sm + BHo + sw) = hv;
            *(uint4*)(sm + BLo + sw) = lv;
        }
        __syncthreads();

#pragma unroll
        for (int s = 0; s < 2; s++) {
            uint32_t ah[2][4], al[2][4];
            uint32_t arow = (uint32_t)((wm + l8 + 8 * ((lane >> 3) & 1)) * 80 +
                                       (2 * s + (lane >> 4)) * 16);
            ldsm_x4(ah[0], sb + AH + arow);
            ldsm_x4(ah[1], sb + AH + arow + 16 * 80);
            ldsm_x4(al[0], sb + AL + arow);
            ldsm_x4(al[1], sb + AL + arow + 16 * 80);

            uint32_t bf[8][2];
            const uint32_t brow = (uint32_t)((s * 16 + l16) * 256);
#pragma unroll
            for (int j = 0; j < 8; j++) {
                int jj = (wn >> 3) + j;
                ldsm_x2_t(bf[j][0], bf[j][1],
                          sb + BHo + brow + (uint32_t)(((jj ^ l8) << 4)));
            }
#pragma unroll
            for (int j = 0; j < 8; j++) {
                MMA16816(acc[0][j], ah[0], bf[j]);
                MMA16816(acc[1][j], ah[1], bf[j]);
            }
#pragma unroll
            for (int j = 0; j < 8; j++) {
                MMA16816(acc[0][j], al[0], bf[j]);
                MMA16816(acc[1][j], al[1], bf[j]);
            }
#pragma unroll
            for (int j = 0; j < 8; j++) {
                int jj = (wn >> 3) + j;
                ldsm_x2_t(bf[j][0], bf[j][1],
                          sb + BLo + brow + (uint32_t)(((jj ^ l8) << 4)));
            }
#pragma unroll
            for (int j = 0; j < 8; j++) {
                MMA16816(acc[0][j], ah[0], bf[j]);
                MMA16816(acc[1][j], ah[1], bf[j]);
            }
        }
    }

    const int gid = lane >> 2, tq = lane & 3;
#pragma unroll
    for (int j = 0; j < 8; j++) {
        int col = col0 + wn + j * 8 + tq * 2;
        float2 bv = *(const float2*)&bias[col];
#pragma unroll
        for (int mi = 0; mi < 2; mi++) {
#pragma unroll
            for (int rg = 0; rg < 2; rg++) {
                int m = row0 + wm + mi * 16 + gid + rg * 8;
                float2 o = make_float2(acc[mi][j][rg * 2] + bv.x,
                                       acc[mi][j][rg * 2 + 1] + bv.y);
                *(float2*)&out[(size_t)m * CDIM + col] = o;
            }
        }
    }
}

// ============================================================
extern "C" void kernel_launch(void* const* d_in, const int* in_sizes, int n_in,
                              void* d_out, int out_size)
{
    const float* x      = (const float*)d_in[0];
    const float* w_qkv  = (const float*)d_in[1];
    const float* w_proj = (const float*)d_in[2];
    const float* b_proj = (const float*)d_in[3];
    float* out = (float*)d_out;

    (void)in_sizes; (void)n_in; (void)out_size;

    cudaFuncSetAttribute(attn_mma_kernel,
                         cudaFuncAttributeMaxDynamicSharedMemorySize, ATT_SMEM);

    qkv_tc_kernel<<<dim3(3 * CDIM / 128, (BATCH * NSEQ) / 128), 256>>>(x, w_qkv);

    attn_mma_kernel<<<dim3(NSEQ / 128, BH_TOT), 256, ATT_SMEM>>>();

    proj_tc_kernel<<<dim3(CDIM / 128, (BATCH * NSEQ) / 128), 256>>>(w_proj, b_proj, out);
}

// round 6
// speedup vs baseline: 3.6251x; 1.1524x over previous
#include <cuda_runtime.h>
#include <cuda_bf16.h>
#include <cstdint>

#define BATCH 2
#define NSEQ  4096
#define CDIM  384
#define NH    6
#define HD    64
#define BH_TOT (BATCH * NH)
#define QK_SCALE 0.125f
#define L2E 1.4426950408889634f

// ================= scratch (allocation-free: __device__ globals) =============
__device__ __nv_bfloat16 g_xh[BATCH * NSEQ * CDIM];  // x as bf16 hi/lo
__device__ __nv_bfloat16 g_xl[BATCH * NSEQ * CDIM];
__device__ __nv_bfloat16 g_wqh[CDIM * 3 * CDIM];     // w_qkv hi/lo
__device__ __nv_bfloat16 g_wql[CDIM * 3 * CDIM];
__device__ __nv_bfloat16 g_wph[CDIM * CDIM];         // w_proj hi/lo
__device__ __nv_bfloat16 g_wpl[CDIM * CDIM];

__device__ __nv_bfloat16 g_qh[BH_TOT * NSEQ * HD];   // [BH,N,64] pre-scaled
__device__ __nv_bfloat16 g_ql[BH_TOT * NSEQ * HD];
__device__ __nv_bfloat16 g_kh[BH_TOT * NSEQ * HD];
__device__ __nv_bfloat16 g_kl[BH_TOT * NSEQ * HD];
__device__ __nv_bfloat16 g_vh[BH_TOT * NSEQ * HD];
__device__ __nv_bfloat16 g_vl[BH_TOT * NSEQ * HD];
__device__ __nv_bfloat16 g_oh[BATCH * NSEQ * CDIM];  // attention out hi/lo
__device__ __nv_bfloat16 g_ol[BATCH * NSEQ * CDIM];

__device__ __forceinline__ float ex2f_fast(float x) {
    float y;
    asm("ex2.approx.f32 %0, %1;" : "=f"(y) : "f"(x));
    return y;
}

__device__ __forceinline__ uint32_t bfpack(__nv_bfloat16 a, __nv_bfloat16 b) {
    return ((uint32_t)__bfloat16_as_ushort(b) << 16) | (uint32_t)__bfloat16_as_ushort(a);
}

__device__ __forceinline__ void split2(float a, float b, uint32_t& hi, uint32_t& lo) {
    __nv_bfloat16 ah = __float2bfloat16(a);
    __nv_bfloat16 bh = __float2bfloat16(b);
    __nv_bfloat16 al = __float2bfloat16(a - __bfloat162float(ah));
    __nv_bfloat16 bl = __float2bfloat16(b - __bfloat162float(bh));
    hi = bfpack(ah, bh);
    lo = bfpack(al, bl);
}

__device__ __forceinline__ uint32_t smem_u32(const void* p) {
    uint32_t a;
    asm("{ .reg .u64 t; cvta.to.shared.u64 t, %1; cvt.u32.u64 %0, t; }" : "=r"(a) : "l"(p));
    return a;
}

__device__ __forceinline__ void ldsm_x2(uint32_t& r0, uint32_t& r1, uint32_t addr) {
    asm volatile("ldmatrix.sync.aligned.m8n8.x2.shared.b16 {%0,%1}, [%2];"
                 : "=r"(r0), "=r"(r1) : "r"(addr));
}
__device__ __forceinline__ void ldsm_x2_t(uint32_t& r0, uint32_t& r1, uint32_t addr) {
    asm volatile("ldmatrix.sync.aligned.m8n8.x2.trans.shared.b16 {%0,%1}, [%2];"
                 : "=r"(r0), "=r"(r1) : "r"(addr));
}
__device__ __forceinline__ void ldsm_x4(uint32_t* r, uint32_t addr) {
    asm volatile("ldmatrix.sync.aligned.m8n8.x4.shared.b16 {%0,%1,%2,%3}, [%4];"
                 : "=r"(r[0]), "=r"(r[1]), "=r"(r[2]), "=r"(r[3]) : "r"(addr));
}

#define MMA16816(d, a, b) \
    asm volatile( \
        "mma.sync.aligned.m16n8k16.row.col.f32.bf16.bf16.f32 " \
        "{%0,%1,%2,%3}, {%4,%5,%6,%7}, {%8,%9}, {%0,%1,%2,%3};" \
        : "+f"((d)[0]), "+f"((d)[1]), "+f"((d)[2]), "+f"((d)[3]) \
        : "r"((a)[0]), "r"((a)[1]), "r"((a)[2]), "r"((a)[3]), \
          "r"((b)[0]), "r"((b)[1]))

#define CP16(dst_u32, src_ptr) \
    asm volatile("cp.async.cg.shared.global [%0], [%1], 16;" :: "r"(dst_u32), "l"(src_ptr))
#define CP_COMMIT() asm volatile("cp.async.commit_group;" ::: "memory")
#define CP_WAIT1()  asm volatile("cp.async.wait_group 1;" ::: "memory")
#define CP_WAIT0()  asm volatile("cp.async.wait_group 0;" ::: "memory")

// ============================================================
// Kernel 0: fp32 -> bf16 hi/lo conversion (x, w_qkv, w_proj)
// ============================================================
#define NX4  (BATCH * NSEQ * CDIM / 4)
#define NWQ4 (CDIM * 3 * CDIM / 4)
#define NWP4 (CDIM * CDIM / 4)
#define NCONV_BLOCKS ((NX4 + NWQ4 + NWP4 + 255) / 256)

__global__ __launch_bounds__(256) void convert_kernel(
    const float* __restrict__ x, const float* __restrict__ wq,
    const float* __restrict__ wp)
{
    int i = blockIdx.x * 256 + threadIdx.x;
    const float* src;
    __nv_bfloat16 *hp, *lp;
    int off;
    if (i < NX4) { src = x; hp = g_xh; lp = g_xl; off = i; }
    else if (i < NX4 + NWQ4) { src = wq; hp = g_wqh; lp = g_wql; off = i - NX4; }
    else if (i < NX4 + NWQ4 + NWP4) { src = wp; hp = g_wph; lp = g_wpl; off = i - NX4 - NWQ4; }
    else return;
    float4 f = *(const float4*)(src + (size_t)off * 4);
    uint2 h, l;
    split2(f.x, f.y, h.x, l.x);
    split2(f.z, f.w, h.y, l.y);
    *(uint2*)(hp + (size_t)off * 4) = h;
    *(uint2*)(lp + (size_t)off * 4) = l;
}

// ============================================================
// Shared GEMM compute: 128x128 CTA, 8 warps (4m x 2n), K-step 32,
// bf16 hi/lo, cp.async double-buffered. Buffer layout (per buf):
//   AH row*80, AL +10240, BH swizzled 256B rows +20480, BL +28672
// ============================================================
#define GBUF 36864
#define GAH 0
#define GAL 10240
#define GBH 20480
#define GBL 28672
#define GEMM_SMEM (2 * GBUF)

__device__ __forceinline__ void gemm_compute_step(
    float acc[2][8][4], uint32_t bb, int wm, int wn, int lane)
{
    const int l8 = lane & 7, l16 = lane & 15;
#pragma unroll
    for (int s = 0; s < 2; s++) {
        uint32_t ah[2][4], al[2][4];
        uint32_t arow = (uint32_t)((wm + l8 + 8 * ((lane >> 3) & 1)) * 80 +
                                   (2 * s + (lane >> 4)) * 16);
        ldsm_x4(ah[0], bb + GAH + arow);
        ldsm_x4(ah[1], bb + GAH + arow + 16 * 80);
        ldsm_x4(al[0], bb + GAL + arow);
        ldsm_x4(al[1], bb + GAL + arow + 16 * 80);

        uint32_t bf[8][2];
        const uint32_t brow = (uint32_t)((s * 16 + l16) * 256);
#pragma unroll
        for (int j = 0; j < 8; j++) {
            int jj = (wn >> 3) + j;
            ldsm_x2_t(bf[j][0], bf[j][1],
                      bb + GBH + brow + (uint32_t)(((jj ^ l8) << 4)));
        }
#pragma unroll
        for (int j = 0; j < 8; j++) {
            MMA16816(acc[0][j], ah[0], bf[j]);
            MMA16816(acc[1][j], ah[1], bf[j]);
        }
#pragma unroll
        for (int j = 0; j < 8; j++) {
            MMA16816(acc[0][j], al[0], bf[j]);
            MMA16816(acc[1][j], al[1], bf[j]);
        }
#pragma unroll
        for (int j = 0; j < 8; j++) {
            int jj = (wn >> 3) + j;
            ldsm_x2_t(bf[j][0], bf[j][1],
                      bb + GBL + brow + (uint32_t)(((jj ^ l8) << 4)));
        }
#pragma unroll
        for (int j = 0; j < 8; j++) {
            MMA16816(acc[0][j], ah[0], bf[j]);
            MMA16816(acc[1][j], ah[1], bf[j]);
        }
    }
}

// ============================================================
// Kernel 1: QKV GEMM (bf16 inputs) -> Q(x0.125)/K/V hi/lo [BH,N,64]
// ============================================================
__global__ __launch_bounds__(256, 2) void qkv_tc_kernel()
{
    extern __shared__ char sm[];
    const uint32_t sb = smem_u32(sm);
    const int tid = threadIdx.x, warp = tid >> 5, lane = tid & 31;
    const int wm = (warp & 3) * 32, wn = (warp >> 2) * 64;
    const int row0 = blockIdx.y * 128, col0 = blockIdx.x * 128;

    float acc[2][8][4];
#pragma unroll
    for (int mi = 0; mi < 2; mi++)
#pragma unroll
        for (int j = 0; j < 8; j++)
#pragma unroll
            for (int i = 0; i < 4; i++) acc[mi][j][i] = 0.0f;

    auto stage = [&](int buf, int k0) {
        uint32_t base = sb + buf * GBUF;
#pragma unroll
        for (int it = 0; it < 2; it++) {
            int idx = tid + it * 256;
            int row = idx >> 2, ch = idx & 3;
            size_t g = (size_t)(row0 + row) * CDIM + k0 + ch * 8;
            CP16(base + GAH + row * 80 + ch * 16, g_xh + g);
            CP16(base + GAL + row * 80 + ch * 16, g_xl + g);
        }
#pragma unroll
        for (int it = 0; it < 2; it++) {
            int idx = tid + it * 256;
            int row = idx >> 4, ch = idx & 15;
            size_t g = (size_t)(k0 + row) * (3 * CDIM) + col0 + ch * 8;
            uint32_t sw = (uint32_t)(row * 256 + ((ch ^ (row & 7)) << 4));
            CP16(base + GBH + sw, g_wqh + g);
            CP16(base + GBL + sw, g_wql + g);
        }
    };

    stage(0, 0);
    CP_COMMIT();

    const int NIT = CDIM / 32;
    for (int kt = 0; kt < NIT; kt++) {
        if (kt < NIT - 1) {
            stage((kt + 1) & 1, (kt + 1) * 32);
            CP_COMMIT();
            CP_WAIT1();
        } else {
            CP_WAIT0();
        }
        __syncthreads();
        gemm_compute_step(acc, sb + (uint32_t)((kt & 1) * GBUF), wm, wn, lane);
        __syncthreads();
    }

    // epilogue: split to q/k/v hi/lo [BH,N,64]
    const int gid = lane >> 2, tq = lane & 3;
#pragma unroll
    for (int j = 0; j < 8; j++) {
        int col = col0 + wn + j * 8 + tq * 2;
        int which = col / CDIM, cm = col % CDIM;
        int h = cm / HD, d = cm % HD;
        float sc = (which == 0) ? QK_SCALE : 1.0f;
        __nv_bfloat16* hp = (which == 0) ? g_qh : (which == 1) ? g_kh : g_vh;
        __nv_bfloat16* lp = (which == 0) ? g_ql : (which == 1) ? g_kl : g_vl;
#pragma unroll
        for (int mi = 0; mi < 2; mi++) {
#pragma unroll
            for (int rg = 0; rg < 2; rg++) {
                int m = row0 + wm + mi * 16 + gid + rg * 8;
                int b = m >> 12, n = m & (NSEQ - 1);
                size_t base = (((size_t)(b * NH + h)) * NSEQ + n) * HD + d;
                uint32_t hv, lv;
                split2(acc[mi][j][rg * 2] * sc, acc[mi][j][rg * 2 + 1] * sc, hv, lv);
                *(uint32_t*)&hp[base] = hv;
                *(uint32_t*)&lp[base] = lv;
            }
        }
    }
}

// ============================================================
// Kernel 2: flash attention via mma.sync, cp.async double-buffered K/V,
// Q-lo fragments in smem, 2 CTAs/SM.
// ============================================================
#define STG 32768
#define SKH 0
#define SKL 8192
#define SVH 16384
#define SVL 24576
#define QAL_OFF 65536
#define ATT_SMEM (2 * STG + 16384)

__global__ __launch_bounds__(256, 2) void attn_mma_kernel()
{
    extern __shared__ char smem[];
    const uint32_t sbase = smem_u32(smem);

    const int tid = threadIdx.x;
    const int warp = tid >> 5, lane = tid & 31;
    const int bh = blockIdx.y;
    const int r0 = blockIdx.x * 128;
    const int R = r0 + warp * 16;

    const int l8 = lane & 7;
    const int hseg = (lane >> 3) & 1;
    const int rA = R + (lane >> 2);
    const int kcol = (lane & 3) * 2;

    const __nv_bfloat16* Qh = g_qh + (size_t)bh * NSEQ * HD;
    const __nv_bfloat16* Ql = g_ql + (size_t)bh * NSEQ * HD;
    const __nv_bfloat16* Kh = g_kh + (size_t)bh * NSEQ * HD;
    const __nv_bfloat16* Kl = g_kl + (size_t)bh * NSEQ * HD;
    const __nv_bfloat16* Vh = g_vh + (size_t)bh * NSEQ * HD;
    const __nv_bfloat16* Vl = g_vl + (size_t)bh * NSEQ * HD;

    // Q hi a-fragments in registers; Q lo a-fragments parked in smem
    uint32_t qah[4][4];
#pragma unroll
    for (int s = 0; s < 4; s++) {
        qah[s][0] = *(const uint32_t*)&Qh[(size_t)rA * HD + s * 16 + kcol];
        qah[s][1] = *(const uint32_t*)&Qh[(size_t)(rA + 8) * HD + s * 16 + kcol];
        qah[s][2] = *(const uint32_t*)&Qh[(size_t)rA * HD + s * 16 + 8 + kcol];
        qah[s][3] = *(const uint32_t*)&Qh[(size_t)(rA + 8) * HD + s * 16 + 8 + kcol];
        uint4 v;
        v.x = *(const uint32_t*)&Ql[(size_t)rA * HD + s * 16 + kcol];
        v.y = *(const uint32_t*)&Ql[(size_t)(rA + 8) * HD + s * 16 + kcol];
        v.z = *(const uint32_t*)&Ql[(size_t)rA * HD + s * 16 + 8 + kcol];
        v.w = *(const uint32_t*)&Ql[(size_t)(rA + 8) * HD + s * 16 + 8 + kcol];
        *(uint4*)(smem + QAL_OFF + warp * 2048 + s * 512 + lane * 16) = v;
    }

    float of[8][4];
#pragma unroll
    for (int j = 0; j < 8; j++)
#pragma unroll
        for (int i = 0; i < 4; i++) of[j][i] = 0.0f;
    float mA = -1e30f, mB = -1e30f, lA = 0.0f, lB = 0.0f;

    const uint32_t krow = (uint32_t)(l8 * 128);

    auto stage = [&](int st, int kr0) {
#pragma unroll
        for (int it = 0; it < 2; it++) {
            int idx = tid + it * 256;
            int row = idx >> 3, ch = idx & 7;
            uint32_t sw = (uint32_t)(st * STG + row * 128 + ((ch ^ (row & 7)) << 4));
            size_t g = (size_t)(kr0 + row) * HD + ch * 8;
            CP16(sbase + sw + SKH, Kh + g);
            CP16(sbase + sw + SKL, Kl + g);
            CP16(sbase + sw + SVH, Vh + g);
            CP16(sbase + sw + SVL, Vl + g);
        }
    };

    stage(0, 0);
    CP_COMMIT();

    for (int kb = 0; kb < NSEQ / 64; kb++) {
        if (kb < NSEQ / 64 - 1) {
            stage((kb + 1) & 1, (kb + 1) * 64);
            CP_COMMIT();
            CP_WAIT1();
        } else {
            CP_WAIT0();
        }
        __syncthreads();
        const uint32_t stb = sbase + (uint32_t)((kb & 1) * STG);

        // ---- S = Q K^T (3 chains) ----
        float sf[8][4];
#pragma unroll
        for (int j = 0; j < 8; j++)
#pragma unroll
            for (int i = 0; i < 4; i++) sf[j][i] = 0.0f;

#pragma unroll
        for (int s = 0; s < 4; s++) {
            uint32_t kbf[8][2];
            uint32_t chsw = (uint32_t)((((2 * s + hseg) ^ l8) << 4));
#pragma unroll
            for (int j = 0; j < 8; j++)
                ldsm_x2(kbf[j][0], kbf[j][1],
                        stb + SKH + (uint32_t)(j * 1024) + krow + chsw);
#pragma unroll
            for (int j = 0; j < 8; j++) MMA16816(sf[j], qah[s], kbf[j]);

            uint32_t qal_s[4];
            *(uint4*)qal_s = *(const uint4*)(smem + QAL_OFF + warp * 2048 + s * 512 + lane * 16);
#pragma unroll
            for (int j = 0; j < 8; j++) MMA16816(sf[j], qal_s, kbf[j]);
#pragma unroll
            for (int j = 0; j < 8; j++)
                ldsm_x2(kbf[j][0], kbf[j][1],
                        stb + SKL + (uint32_t)(j * 1024) + krow + chsw);
#pragma unroll
            for (int j = 0; j < 8; j++) MMA16816(sf[j], qah[s], kbf[j]);
        }

        // ---- online softmax ----
        float mxA = sf[0][0], mxB = sf[0][2];
#pragma unroll
        for (int j = 0; j < 8; j++) {
            mxA = fmaxf(mxA, fmaxf(sf[j][0], sf[j][1]));
            mxB = fmaxf(mxB, fmaxf(sf[j][2], sf[j][3]));
        }
        mxA = fmaxf(mxA, __shfl_xor_sync(0xffffffffu, mxA, 1));
        mxA = fmaxf(mxA, __shfl_xor_sync(0xffffffffu, mxA, 2));
        mxB = fmaxf(mxB, __shfl_xor_sync(0xffffffffu, mxB, 1));
        mxB = fmaxf(mxB, __shfl_xor_sync(0xffffffffu, mxB, 2));

        float mnA = fmaxf(mA, mxA), mnB = fmaxf(mB, mxB);
        float corrA = ex2f_fast((mA - mnA) * L2E);
        float corrB = ex2f_fast((mB - mnB) * L2E);
        mA = mnA; mB = mnB;
        const float nlA = mnA * L2E, nlB = mnB * L2E;

        float sumA = 0.0f, sumB = 0.0f;
#pragma unroll
        for (int j = 0; j < 8; j++) {
            float p0 = ex2f_fast(fmaf(sf[j][0], L2E, -nlA));
            float p1 = ex2f_fast(fmaf(sf[j][1], L2E, -nlA));
            float p2 = ex2f_fast(fmaf(sf[j][2], L2E, -nlB));
            float p3 = ex2f_fast(fmaf(sf[j][3], L2E, -nlB));
            sumA += p0 + p1; sumB += p2 + p3;
            sf[j][0] = p0; sf[j][1] = p1; sf[j][2] = p2; sf[j][3] = p3;
        }
        lA = lA * corrA + sumA;
        lB = lB * corrB + sumB;

#pragma unroll
        for (int j = 0; j < 8; j++) {
            of[j][0] *= corrA; of[j][1] *= corrA;
            of[j][2] *= corrB; of[j][3] *= corrB;
        }

        // ---- O += P V (3 chains) ----
#pragma unroll
        for (int s = 0; s < 4; s++) {
            uint32_t pah[4], pal[4];
            split2(sf[2 * s][0], sf[2 * s][1], pah[0], pal[0]);
            split2(sf[2 * s][2], sf[2 * s][3], pah[1], pal[1]);
            split2(sf[2 * s + 1][0], sf[2 * s + 1][1], pah[2], pal[2]);
            split2(sf[2 * s + 1][2], sf[2 * s + 1][3], pah[3], pal[3]);

            uint32_t vrow = (uint32_t)((16 * s + 8 * hseg + l8) * 128);
            uint32_t vbf[8][2];
#pragma unroll
            for (int j = 0; j < 8; j++)
                ldsm_x2_t(vbf[j][0], vbf[j][1],
                          stb + SVH + vrow + (uint32_t)(((j ^ l8) << 4)));
#pragma unroll
            for (int j = 0; j < 8; j++) MMA16816(of[j], pah, vbf[j]);
#pragma unroll
            for (int j = 0; j < 8; j++) MMA16816(of[j], pal, vbf[j]);
#pragma unroll
            for (int j = 0; j < 8; j++)
                ldsm_x2_t(vbf[j][0], vbf[j][1],
                          stb + SVL + vrow + (uint32_t)(((j ^ l8) << 4)));
#pragma unroll
            for (int j = 0; j < 8; j++) MMA16816(of[j], pah, vbf[j]);
        }
        __syncthreads();
    }

    // ---- epilogue: write O as bf16 hi/lo [B,N,C] ----
    lA += __shfl_xor_sync(0xffffffffu, lA, 1);
    lA += __shfl_xor_sync(0xffffffffu, lA, 2);
    lB += __shfl_xor_sync(0xffffffffu, lB, 1);
    lB += __shfl_xor_sync(0xffffffffu, lB, 2);
    const float invA = 1.0f / lA, invB = 1.0f / lB;

    const int b = bh / NH, h = bh % NH;
    size_t baseA = ((size_t)b * NSEQ + rA) * CDIM + h * HD;
    size_t baseB = ((size_t)b * NSEQ + rA + 8) * CDIM + h * HD;
#pragma unroll
    for (int j = 0; j < 8; j++) {
        int c = j * 8 + kcol;
        uint32_t hv, lv;
        split2(of[j][0] * invA, of[j][1] * invA, hv, lv);
        *(uint32_t*)&g_oh[baseA + c] = hv;
        *(uint32_t*)&g_ol[baseA + c] = lv;
        split2(of[j][2] * invB, of[j][3] * invB, hv, lv);
        *(uint32_t*)&g_oh[baseB + c] = hv;
        *(uint32_t*)&g_ol[baseB + c] = lv;
    }
}

// ============================================================
// Kernel 3: proj GEMM (bf16 inputs) + bias -> out fp32
// ============================================================
__global__ __launch_bounds__(256, 2) void proj_tc_kernel(
    const float* __restrict__ bias, float* __restrict__ out)
{
    extern __shared__ char sm[];
    const uint32_t sb = smem_u32(sm);
    const int tid = threadIdx.x, warp = tid >> 5, lane = tid & 31;
    const int wm = (warp & 3) * 32, wn = (warp >> 2) * 64;
    const int row0 = blockIdx.y * 128, col0 = blockIdx.x * 128;

    float acc[2][8][4];
#pragma unroll
    for (int mi = 0; mi < 2; mi++)
#pragma unroll
        for (int j = 0; j < 8; j++)
#pragma unroll
            for (int i = 0; i < 4; i++) acc[mi][j][i] = 0.0f;

    auto stage = [&](int buf, int k0) {
        uint32_t base = sb + buf * GBUF;
#pragma unroll
        for (int it = 0; it < 2; it++) {
            int idx = tid + it * 256;
            int row = idx >> 2, ch = idx & 3;
            size_t g = (size_t)(row0 + row) * CDIM + k0 + ch * 8;
            CP16(base + GAH + row * 80 + ch * 16, g_oh + g);
            CP16(base + GAL + row * 80 + ch * 16, g_ol + g);
        }
#pragma unroll
        for (int it = 0; it < 2; it++) {
            int idx = tid + it * 256;
            int row = idx >> 4, ch = idx & 15;
            size_t g = (size_t)(k0 + row) * CDIM + col0 + ch * 8;
            uint32_t sw = (uint32_t)(row * 256 + ((ch ^ (row & 7)) << 4));
            CP16(base + GBH + sw, g_wph + g);
            CP16(base + GBL + sw, g_wpl + g);
        }
    };

    stage(0, 0);
    CP_COMMIT();

    const int NIT = CDIM / 32;
    for (int kt = 0; kt < NIT; kt++) {
        if (kt < NIT - 1) {
            stage((kt + 1) & 1, (kt + 1) * 32);
            CP_COMMIT();
            CP_WAIT1();
        } else {
            CP_WAIT0();
        }
        __syncthreads();
        gemm_compute_step(acc, sb + (uint32_t)((kt & 1) * GBUF), wm, wn, lane);
        __syncthreads();
    }

    const int gid = lane >> 2, tq = lane & 3;
#pragma unroll
    for (int j = 0; j < 8; j++) {
        int col = col0 + wn + j * 8 + tq * 2;
        float2 bv = *(const float2*)&bias[col];
#pragma unroll
        for (int mi = 0; mi < 2; mi++) {
#pragma unroll
            for (int rg = 0; rg < 2; rg++) {
                int m = row0 + wm + mi * 16 + gid + rg * 8;
                float2 o = make_float2(acc[mi][j][rg * 2] + bv.x,
                                       acc[mi][j][rg * 2 + 1] + bv.y);
                *(float2*)&out[(size_t)m * CDIM + col] = o;
            }
        }
    }
}

// ============================================================
extern "C" void kernel_launch(void* const* d_in, const int* in_sizes, int n_in,
                              void* d_out, int out_size)
{
    const float* x      = (const float*)d_in[0];
    const float* w_qkv  = (const float*)d_in[1];
    const float* w_proj = (const float*)d_in[2];
    const float* b_proj = (const float*)d_in[3];
    float* out = (float*)d_out;

    (void)in_sizes; (void)n_in; (void)out_size;

    cudaFuncSetAttribute(qkv_tc_kernel,
                         cudaFuncAttributeMaxDynamicSharedMemorySize, GEMM_SMEM);
    cudaFuncSetAttribute(attn_mma_kernel,
                         cudaFuncAttributeMaxDynamicSharedMemorySize, ATT_SMEM);
    cudaFuncSetAttribute(proj_tc_kernel,
                         cudaFuncAttributeMaxDynamicSharedMemorySize, GEMM_SMEM);

    convert_kernel<<<NCONV_BLOCKS, 256>>>(x, w_qkv, w_proj);

    qkv_tc_kernel<<<dim3(3 * CDIM / 128, (BATCH * NSEQ) / 128), 256, GEMM_SMEM>>>();

    attn_mma_kernel<<<dim3(NSEQ / 128, BH_TOT), 256, ATT_SMEM>>>();

    proj_tc_kernel<<<dim3(CDIM / 128, (BATCH * NSEQ) / 128), 256, GEMM_SMEM>>>(b_proj, out);
}

// round 7
// speedup vs baseline: 3.7804x; 1.0428x over previous
#include <cuda_runtime.h>
#include <cuda_bf16.h>
#include <cstdint>

#define BATCH 2
#define NSEQ  4096
#define CDIM  384
#define NH    6
#define HD    64
#define BH_TOT (BATCH * NH)
#define QK_SCALE 0.125f
#define L2E 1.4426950408889634f

// ================= scratch (allocation-free: __device__ globals) =============
__device__ __nv_bfloat16 g_xh[BATCH * NSEQ * CDIM];  // x as bf16 hi/lo
__device__ __nv_bfloat16 g_xl[BATCH * NSEQ * CDIM];
__device__ __nv_bfloat16 g_wqh[CDIM * 3 * CDIM];     // w_qkv hi/lo
__device__ __nv_bfloat16 g_wql[CDIM * 3 * CDIM];
__device__ __nv_bfloat16 g_wph[CDIM * CDIM];         // w_proj hi/lo
__device__ __nv_bfloat16 g_wpl[CDIM * CDIM];

__device__ __nv_bfloat16 g_qh[BH_TOT * NSEQ * HD];   // [BH,N,64] pre-scaled
__device__ __nv_bfloat16 g_ql[BH_TOT * NSEQ * HD];
__device__ __nv_bfloat16 g_kh[BH_TOT * NSEQ * HD];
__device__ __nv_bfloat16 g_kl[BH_TOT * NSEQ * HD];
__device__ __nv_bfloat16 g_vh[BH_TOT * NSEQ * HD];
__device__ __nv_bfloat16 g_vl[BH_TOT * NSEQ * HD];
__device__ __nv_bfloat16 g_oh[BATCH * NSEQ * CDIM];  // attention out hi/lo
__device__ __nv_bfloat16 g_ol[BATCH * NSEQ * CDIM];

__device__ __forceinline__ float ex2f_fast(float x) {
    float y;
    asm("ex2.approx.f32 %0, %1;" : "=f"(y) : "f"(x));
    return y;
}

// fast split: one cvt packs the hi pair, residuals exact, one cvt packs lo pair
__device__ __forceinline__ void split2(float a, float b, uint32_t& hi, uint32_t& lo) {
    asm("cvt.rn.bf16x2.f32 %0, %1, %2;" : "=r"(hi) : "f"(b), "f"(a));
    float ah = __uint_as_float(hi << 16);
    float bh = __uint_as_float(hi & 0xffff0000u);
    float al = a - ah, bl = b - bh;
    asm("cvt.rn.bf16x2.f32 %0, %1, %2;" : "=r"(lo) : "f"(bl), "f"(al));
}

__device__ __forceinline__ uint32_t smem_u32(const void* p) {
    uint32_t a;
    asm("{ .reg .u64 t; cvta.to.shared.u64 t, %1; cvt.u32.u64 %0, t; }" : "=r"(a) : "l"(p));
    return a;
}

__device__ __forceinline__ void ldsm_x2(uint32_t& r0, uint32_t& r1, uint32_t addr) {
    asm volatile("ldmatrix.sync.aligned.m8n8.x2.shared.b16 {%0,%1}, [%2];"
                 : "=r"(r0), "=r"(r1) : "r"(addr));
}
__device__ __forceinline__ void ldsm_x2_t(uint32_t& r0, uint32_t& r1, uint32_t addr) {
    asm volatile("ldmatrix.sync.aligned.m8n8.x2.trans.shared.b16 {%0,%1}, [%2];"
                 : "=r"(r0), "=r"(r1) : "r"(addr));
}
__device__ __forceinline__ void ldsm_x4(uint32_t* r, uint32_t addr) {
    asm volatile("ldmatrix.sync.aligned.m8n8.x4.shared.b16 {%0,%1,%2,%3}, [%4];"
                 : "=r"(r[0]), "=r"(r[1]), "=r"(r[2]), "=r"(r[3]) : "r"(addr));
}

#define MMA16816(d, a, b) \
    asm volatile( \
        "mma.sync.aligned.m16n8k16.row.col.f32.bf16.bf16.f32 " \
        "{%0,%1,%2,%3}, {%4,%5,%6,%7}, {%8,%9}, {%0,%1,%2,%3};" \
        : "+f"((d)[0]), "+f"((d)[1]), "+f"((d)[2]), "+f"((d)[3]) \
        : "r"((a)[0]), "r"((a)[1]), "r"((a)[2]), "r"((a)[3]), \
          "r"((b)[0]), "r"((b)[1]))

#define CP16(dst_u32, src_ptr) \
    asm volatile("cp.async.cg.shared.global [%0], [%1], 16;" :: "r"(dst_u32), "l"(src_ptr))
#define CP_COMMIT() asm volatile("cp.async.commit_group;" ::: "memory")
#define CP_WAIT1()  asm volatile("cp.async.wait_group 1;" ::: "memory")
#define CP_WAIT0()  asm volatile("cp.async.wait_group 0;" ::: "memory")

// ============================================================
// Kernel 0: fp32 -> bf16 hi/lo conversion (x, w_qkv, w_proj)
// ============================================================
#define NX4  (BATCH * NSEQ * CDIM / 4)
#define NWQ4 (CDIM * 3 * CDIM / 4)
#define NWP4 (CDIM * CDIM / 4)
#define NCONV_BLOCKS ((NX4 + NWQ4 + NWP4 + 255) / 256)

__global__ __launch_bounds__(256) void convert_kernel(
    const float* __restrict__ x, const float* __restrict__ wq,
    const float* __restrict__ wp)
{
    int i = blockIdx.x * 256 + threadIdx.x;
    const float* src;
    __nv_bfloat16 *hp, *lp;
    int off;
    if (i < NX4) { src = x; hp = g_xh; lp = g_xl; off = i; }
    else if (i < NX4 + NWQ4) { src = wq; hp = g_wqh; lp = g_wql; off = i - NX4; }
    else if (i < NX4 + NWQ4 + NWP4) { src = wp; hp = g_wph; lp = g_wpl; off = i - NX4 - NWQ4; }
    else return;
    float4 f = *(const float4*)(src + (size_t)off * 4);
    uint2 h, l;
    split2(f.x, f.y, h.x, l.x);
    split2(f.z, f.w, h.y, l.y);
    *(uint2*)(hp + (size_t)off * 4) = h;
    *(uint2*)(lp + (size_t)off * 4) = l;
}

// ============================================================
// Shared GEMM compute: 128x128 CTA, 8 warps (4m x 2n), K-step 32,
// bf16 hi/lo, cp.async double-buffered.
// ============================================================
#define GBUF 36864
#define GAH 0
#define GAL 10240
#define GBH 20480
#define GBL 28672
#define GEMM_SMEM (2 * GBUF)

__device__ __forceinline__ void gemm_compute_step(
    float acc[2][8][4], uint32_t bb, int wm, int wn, int lane)
{
    const int l8 = lane & 7, l16 = lane & 15;
#pragma unroll
    for (int s = 0; s < 2; s++) {
        uint32_t ah[2][4], al[2][4];
        uint32_t arow = (uint32_t)((wm + l8 + 8 * ((lane >> 3) & 1)) * 80 +
                                   (2 * s + (lane >> 4)) * 16);
        ldsm_x4(ah[0], bb + GAH + arow);
        ldsm_x4(ah[1], bb + GAH + arow + 16 * 80);
        ldsm_x4(al[0], bb + GAL + arow);
        ldsm_x4(al[1], bb + GAL + arow + 16 * 80);

        uint32_t bf[8][2];
        const uint32_t brow = (uint32_t)((s * 16 + l16) * 256);
#pragma unroll
        for (int j = 0; j < 8; j++) {
            int jj = (wn >> 3) + j;
            ldsm_x2_t(bf[j][0], bf[j][1],
                      bb + GBH + brow + (uint32_t)(((jj ^ l8) << 4)));
        }
#pragma unroll
        for (int j = 0; j < 8; j++) {
            MMA16816(acc[0][j], ah[0], bf[j]);
            MMA16816(acc[1][j], ah[1], bf[j]);
        }
#pragma unroll
        for (int j = 0; j < 8; j++) {
            MMA16816(acc[0][j], al[0], bf[j]);
            MMA16816(acc[1][j], al[1], bf[j]);
        }
#pragma unroll
        for (int j = 0; j < 8; j++) {
            int jj = (wn >> 3) + j;
            ldsm_x2_t(bf[j][0], bf[j][1],
                      bb + GBL + brow + (uint32_t)(((jj ^ l8) << 4)));
        }
#pragma unroll
        for (int j = 0; j < 8; j++) {
            MMA16816(acc[0][j], ah[0], bf[j]);
            MMA16816(acc[1][j], ah[1], bf[j]);
        }
    }
}

// ============================================================
// Kernel 1: QKV GEMM (bf16 inputs) -> Q(x0.125)/K/V hi/lo [BH,N,64]
// ============================================================
__global__ __launch_bounds__(256, 2) void qkv_tc_kernel()
{
    extern __shared__ char sm[];
    const uint32_t sb = smem_u32(sm);
    const int tid = threadIdx.x, warp = tid >> 5, lane = tid & 31;
    const int wm = (warp & 3) * 32, wn = (warp >> 2) * 64;
    const int row0 = blockIdx.y * 128, col0 = blockIdx.x * 128;

    float acc[2][8][4];
#pragma unroll
    for (int mi = 0; mi < 2; mi++)
#pragma unroll
        for (int j = 0; j < 8; j++)
#pragma unroll
            for (int i = 0; i < 4; i++) acc[mi][j][i] = 0.0f;

    auto stage = [&](int buf, int k0) {
        uint32_t base = sb + buf * GBUF;
#pragma unroll
        for (int it = 0; it < 2; it++) {
            int idx = tid + it * 256;
            int row = idx >> 2, ch = idx & 3;
            size_t g = (size_t)(row0 + row) * CDIM + k0 + ch * 8;
            CP16(base + GAH + row * 80 + ch * 16, g_xh + g);
            CP16(base + GAL + row * 80 + ch * 16, g_xl + g);
        }
#pragma unroll
        for (int it = 0; it < 2; it++) {
            int idx = tid + it * 256;
            int row = idx >> 4, ch = idx & 15;
            size_t g = (size_t)(k0 + row) * (3 * CDIM) + col0 + ch * 8;
            uint32_t sw = (uint32_t)(row * 256 + ((ch ^ (row & 7)) << 4));
            CP16(base + GBH + sw, g_wqh + g);
            CP16(base + GBL + sw, g_wql + g);
        }
    };

    stage(0, 0);
    CP_COMMIT();

    const int NIT = CDIM / 32;
    for (int kt = 0; kt < NIT; kt++) {
        if (kt < NIT - 1) {
            stage((kt + 1) & 1, (kt + 1) * 32);
            CP_COMMIT();
            CP_WAIT1();
        } else {
            CP_WAIT0();
        }
        __syncthreads();
        gemm_compute_step(acc, sb + (uint32_t)((kt & 1) * GBUF), wm, wn, lane);
        __syncthreads();
    }

    // epilogue: split to q/k/v hi/lo [BH,N,64]
    const int gid = lane >> 2, tq = lane & 3;
#pragma unroll
    for (int j = 0; j < 8; j++) {
        int col = col0 + wn + j * 8 + tq * 2;
        int which = col / CDIM, cm = col % CDIM;
        int h = cm / HD, d = cm % HD;
        float sc = (which == 0) ? QK_SCALE : 1.0f;
        __nv_bfloat16* hp = (which == 0) ? g_qh : (which == 1) ? g_kh : g_vh;
        __nv_bfloat16* lp = (which == 0) ? g_ql : (which == 1) ? g_kl : g_vl;
#pragma unroll
        for (int mi = 0; mi < 2; mi++) {
#pragma unroll
            for (int rg = 0; rg < 2; rg++) {
                int m = row0 + wm + mi * 16 + gid + rg * 8;
                int b = m >> 12, n = m & (NSEQ - 1);
                size_t base = (((size_t)(b * NH + h)) * NSEQ + n) * HD + d;
                uint32_t hv, lv;
                split2(acc[mi][j][rg * 2] * sc, acc[mi][j][rg * 2 + 1] * sc, hv, lv);
                *(uint32_t*)&hp[base] = hv;
                *(uint32_t*)&lp[base] = lv;
            }
        }
    }
}

// ============================================================
// Kernel 2: flash attention via mma.sync, cp.async double-buffered K/V.
// Q hi AND lo fragments parked in smem (warp-private), j-chunked
// register-lean mainloop -> fits 128 regs, true 2 CTAs/SM.
// ============================================================
#define STG 32768
#define SKH 0
#define SKL 8192
#define SVH 16384
#define SVL 24576
#define QA_OFF 65536           // per-warp 4096B: qah [s*512+lane*16], qal +2048
#define ATT_SMEM (2 * STG + 32768)

__global__ __launch_bounds__(256, 2) void attn_mma_kernel()
{
    extern __shared__ char smem[];
    const uint32_t sbase = smem_u32(smem);

    const int tid = threadIdx.x;
    const int warp = tid >> 5, lane = tid & 31;
    const int bh = blockIdx.y;
    const int r0 = blockIdx.x * 128;
    const int R = r0 + warp * 16;

    const int l8 = lane & 7;
    const int hseg = (lane >> 3) & 1;
    const int rA = R + (lane >> 2);
    const int kcol = (lane & 3) * 2;

    const __nv_bfloat16* Qh = g_qh + (size_t)bh * NSEQ * HD;
    const __nv_bfloat16* Ql = g_ql + (size_t)bh * NSEQ * HD;
    const __nv_bfloat16* Kh = g_kh + (size_t)bh * NSEQ * HD;
    const __nv_bfloat16* Kl = g_kl + (size_t)bh * NSEQ * HD;
    const __nv_bfloat16* Vh = g_vh + (size_t)bh * NSEQ * HD;
    const __nv_bfloat16* Vl = g_vl + (size_t)bh * NSEQ * HD;

    // park Q hi/lo a-fragments in warp-private smem slabs
    const uint32_t qa_base = (uint32_t)(QA_OFF + warp * 4096);
#pragma unroll
    for (int s = 0; s < 4; s++) {
        uint4 v;
        v.x = *(const uint32_t*)&Qh[(size_t)rA * HD + s * 16 + kcol];
        v.y = *(const uint32_t*)&Qh[(size_t)(rA + 8) * HD + s * 16 + kcol];
        v.z = *(const uint32_t*)&Qh[(size_t)rA * HD + s * 16 + 8 + kcol];
        v.w = *(const uint32_t*)&Qh[(size_t)(rA + 8) * HD + s * 16 + 8 + kcol];
        *(uint4*)(smem + qa_base + s * 512 + lane * 16) = v;
        v.x = *(const uint32_t*)&Ql[(size_t)rA * HD + s * 16 + kcol];
        v.y = *(const uint32_t*)&Ql[(size_t)(rA + 8) * HD + s * 16 + kcol];
        v.z = *(const uint32_t*)&Ql[(size_t)rA * HD + s * 16 + 8 + kcol];
        v.w = *(const uint32_t*)&Ql[(size_t)(rA + 8) * HD + s * 16 + 8 + kcol];
        *(uint4*)(smem + qa_base + 2048 + s * 512 + lane * 16) = v;
    }

    float of[8][4];
#pragma unroll
    for (int j = 0; j < 8; j++)
#pragma unroll
        for (int i = 0; i < 4; i++) of[j][i] = 0.0f;
    float mA = -1e30f, mB = -1e30f, lA = 0.0f, lB = 0.0f;

    const uint32_t krow = (uint32_t)(l8 * 128);

    auto stage = [&](int st, int kr0) {
#pragma unroll
        for (int it = 0; it < 2; it++) {
            int idx = tid + it * 256;
            int row = idx >> 3, ch = idx & 7;
            uint32_t sw = (uint32_t)(st * STG + row * 128 + ((ch ^ (row & 7)) << 4));
            size_t g = (size_t)(kr0 + row) * HD + ch * 8;
            CP16(sbase + sw + SKH, Kh + g);
            CP16(sbase + sw + SKL, Kl + g);
            CP16(sbase + sw + SVH, Vh + g);
            CP16(sbase + sw + SVL, Vl + g);
        }
    };

    stage(0, 0);
    CP_COMMIT();

    for (int kb = 0; kb < NSEQ / 64; kb++) {
        if (kb < NSEQ / 64 - 1) {
            stage((kb + 1) & 1, (kb + 1) * 64);
            CP_COMMIT();
            CP_WAIT1();
        } else {
            CP_WAIT0();
        }
        __syncthreads();
        const uint32_t stb = sbase + (uint32_t)((kb & 1) * STG);

        // ---- S = Q K^T (3 chains, j-chunked by 4) ----
        float sf[8][4];
#pragma unroll
        for (int j = 0; j < 8; j++)
#pragma unroll
            for (int i = 0; i < 4; i++) sf[j][i] = 0.0f;

#pragma unroll
        for (int s = 0; s < 4; s++) {
            uint32_t qh_s[4], ql_s[4];
            *(uint4*)qh_s = *(const uint4*)(smem + qa_base + s * 512 + lane * 16);
            *(uint4*)ql_s = *(const uint4*)(smem + qa_base + 2048 + s * 512 + lane * 16);
            uint32_t chsw = (uint32_t)((((2 * s + hseg) ^ l8) << 4));
#pragma unroll
            for (int jc = 0; jc < 8; jc += 4) {
                uint32_t kbf[4][2];
#pragma unroll
                for (int j = 0; j < 4; j++)
                    ldsm_x2(kbf[j][0], kbf[j][1],
                            stb + SKH + (uint32_t)((jc + j) * 1024) + krow + chsw);
#pragma unroll
                for (int j = 0; j < 4; j++) MMA16816(sf[jc + j], qh_s, kbf[j]);
#pragma unroll
                for (int j = 0; j < 4; j++) MMA16816(sf[jc + j], ql_s, kbf[j]);
#pragma unroll
                for (int j = 0; j < 4; j++)
                    ldsm_x2(kbf[j][0], kbf[j][1],
                            stb + SKL + (uint32_t)((jc + j) * 1024) + krow + chsw);
#pragma unroll
                for (int j = 0; j < 4; j++) MMA16816(sf[jc + j], qh_s, kbf[j]);
            }
        }

        // ---- online softmax ----
        float mxA = sf[0][0], mxB = sf[0][2];
#pragma unroll
        for (int j = 0; j < 8; j++) {
            mxA = fmaxf(mxA, fmaxf(sf[j][0], sf[j][1]));
            mxB = fmaxf(mxB, fmaxf(sf[j][2], sf[j][3]));
        }
        mxA = fmaxf(mxA, __shfl_xor_sync(0xffffffffu, mxA, 1));
        mxA = fmaxf(mxA, __shfl_xor_sync(0xffffffffu, mxA, 2));
        mxB = fmaxf(mxB, __shfl_xor_sync(0xffffffffu, mxB, 1));
        mxB = fmaxf(mxB, __shfl_xor_sync(0xffffffffu, mxB, 2));

        float mnA = fmaxf(mA, mxA), mnB = fmaxf(mB, mxB);
        float corrA = ex2f_fast((mA - mnA) * L2E);
        float corrB = ex2f_fast((mB - mnB) * L2E);
        mA = mnA; mB = mnB;
        const float nlA = mnA * L2E, nlB = mnB * L2E;

        float sumA = 0.0f, sumB = 0.0f;
#pragma unroll
        for (int j = 0; j < 8; j++) {
            float p0 = ex2f_fast(fmaf(sf[j][0], L2E, -nlA));
            float p1 = ex2f_fast(fmaf(sf[j][1], L2E, -nlA));
            float p2 = ex2f_fast(fmaf(sf[j][2], L2E, -nlB));
            float p3 = ex2f_fast(fmaf(sf[j][3], L2E, -nlB));
            sumA += p0 + p1; sumB += p2 + p3;
            sf[j][0] = p0; sf[j][1] = p1; sf[j][2] = p2; sf[j][3] = p3;
        }
        lA = lA * corrA + sumA;
        lB = lB * corrB + sumB;

#pragma unroll
        for (int j = 0; j < 8; j++) {
            of[j][0] *= corrA; of[j][1] *= corrA;
            of[j][2] *= corrB; of[j][3] *= corrB;
        }

        // ---- O += P V (3 chains, j-chunked by 4) ----
#pragma unroll
        for (int s = 0; s < 4; s++) {
            uint32_t pah[4], pal[4];
            split2(sf[2 * s][0], sf[2 * s][1], pah[0], pal[0]);
            split2(sf[2 * s][2], sf[2 * s][3], pah[1], pal[1]);
            split2(sf[2 * s + 1][0], sf[2 * s + 1][1], pah[2], pal[2]);
            split2(sf[2 * s + 1][2], sf[2 * s + 1][3], pah[3], pal[3]);

            uint32_t vrow = (uint32_t)((16 * s + 8 * hseg + l8) * 128);
#pragma unroll
            for (int jc = 0; jc < 8; jc += 4) {
                uint32_t vbf[4][2];
#pragma unroll
                for (int j = 0; j < 4; j++)
                    ldsm_x2_t(vbf[j][0], vbf[j][1],
                              stb + SVH + vrow + (uint32_t)((((jc + j) ^ l8) << 4)));
#pragma unroll
                for (int j = 0; j < 4; j++) MMA16816(of[jc + j], pah, vbf[j]);
#pragma unroll
                for (int j = 0; j < 4; j++) MMA16816(of[jc + j], pal, vbf[j]);
#pragma unroll
                for (int j = 0; j < 4; j++)
                    ldsm_x2_t(vbf[j][0], vbf[j][1],
                              stb + SVL + vrow + (uint32_t)((((jc + j) ^ l8) << 4)));
#pragma unroll
                for (int j = 0; j < 4; j++) MMA16816(of[jc + j], pah, vbf[j]);
            }
        }
        __syncthreads();
    }

    // ---- epilogue: write O as bf16 hi/lo [B,N,C] ----
    lA += __shfl_xor_sync(0xffffffffu, lA, 1);
    lA += __shfl_xor_sync(0xffffffffu, lA, 2);
    lB += __shfl_xor_sync(0xffffffffu, lB, 1);
    lB += __shfl_xor_sync(0xffffffffu, lB, 2);
    const float invA = 1.0f / lA, invB = 1.0f / lB;

    const int b = bh / NH, h = bh % NH;
    size_t baseA = ((size_t)b * NSEQ + rA) * CDIM + h * HD;
    size_t baseB = ((size_t)b * NSEQ + rA + 8) * CDIM + h * HD;
#pragma unroll
    for (int j = 0; j < 8; j++) {
        int c = j * 8 + kcol;
        uint32_t hv, lv;
        split2(of[j][0] * invA, of[j][1] * invA, hv, lv);
        *(uint32_t*)&g_oh[baseA + c] = hv;
        *(uint32_t*)&g_ol[baseA + c] = lv;
        split2(of[j][2] * invB, of[j][3] * invB, hv, lv);
        *(uint32_t*)&g_oh[baseB + c] = hv;
        *(uint32_t*)&g_ol[baseB + c] = lv;
    }
}

// ============================================================
// Kernel 3: proj GEMM (bf16 inputs) + bias -> out fp32
// ============================================================
__global__ __launch_bounds__(256, 2) void proj_tc_kernel(
    const float* __restrict__ bias, float* __restrict__ out)
{
    extern __shared__ char sm[];
    const uint32_t sb = smem_u32(sm);
    const int tid = threadIdx.x, warp = tid >> 5, lane = tid & 31;
    const int wm = (warp & 3) * 32, wn = (warp >> 2) * 64;
    const int row0 = blockIdx.y * 128, col0 = blockIdx.x * 128;

    float acc[2][8][4];
#pragma unroll
    for (int mi = 0; mi < 2; mi++)
#pragma unroll
        for (int j = 0; j < 8; j++)
#pragma unroll
            for (int i = 0; i < 4; i++) acc[mi][j][i] = 0.0f;

    auto stage = [&](int buf, int k0) {
        uint32_t base = sb + buf * GBUF;
#pragma unroll
        for (int it = 0; it < 2; it++) {
            int idx = tid + it * 256;
            int row = idx >> 2, ch = idx & 3;
            size_t g = (size_t)(row0 + row) * CDIM + k0 + ch * 8;
            CP16(base + GAH + row * 80 + ch * 16, g_oh + g);
            CP16(base + GAL + row * 80 + ch * 16, g_ol + g);
        }
#pragma unroll
        for (int it = 0; it < 2; it++) {
            int idx = tid + it * 256;
            int row = idx >> 4, ch = idx & 15;
            size_t g = (size_t)(k0 + row) * CDIM + col0 + ch * 8;
            uint32_t sw = (uint32_t)(row * 256 + ((ch ^ (row & 7)) << 4));
            CP16(base + GBH + sw, g_wph + g);
            CP16(base + GBL + sw, g_wpl + g);
        }
    };

    stage(0, 0);
    CP_COMMIT();

    const int NIT = CDIM / 32;
    for (int kt = 0; kt < NIT; kt++) {
        if (kt < NIT - 1) {
            stage((kt + 1) & 1, (kt + 1) * 32);
            CP_COMMIT();
            CP_WAIT1();
        } else {
            CP_WAIT0();
        }
        __syncthreads();
        gemm_compute_step(acc, sb + (uint32_t)((kt & 1) * GBUF), wm, wn, lane);
        __syncthreads();
    }

    const int gid = lane >> 2, tq = lane & 3;
#pragma unroll
    for (int j = 0; j < 8; j++) {
        int col = col0 + wn + j * 8 + tq * 2;
        float2 bv = *(const float2*)&bias[col];
#pragma unroll
        for (int mi = 0; mi < 2; mi++) {
#pragma unroll
            for (int rg = 0; rg < 2; rg++) {
                int m = row0 + wm + mi * 16 + gid + rg * 8;
                float2 o = make_float2(acc[mi][j][rg * 2] + bv.x,
                                       acc[mi][j][rg * 2 + 1] + bv.y);
                *(float2*)&out[(size_t)m * CDIM + col] = o;
            }
        }
    }
}

// ============================================================
extern "C" void kernel_launch(void* const* d_in, const int* in_sizes, int n_in,
                              void* d_out, int out_size)
{
    const float* x      = (const float*)d_in[0];
    const float* w_qkv  = (const float*)d_in[1];
    const float* w_proj = (const float*)d_in[2];
    const float* b_proj = (const float*)d_in[3];
    float* out = (float*)d_out;

    (void)in_sizes; (void)n_in; (void)out_size;

    cudaFuncSetAttribute(qkv_tc_kernel,
                         cudaFuncAttributeMaxDynamicSharedMemorySize, GEMM_SMEM);
    cudaFuncSetAttribute(attn_mma_kernel,
                         cudaFuncAttributeMaxDynamicSharedMemorySize, ATT_SMEM);
    cudaFuncSetAttribute(proj_tc_kernel,
                         cudaFuncAttributeMaxDynamicSharedMemorySize, GEMM_SMEM);

    convert_kernel<<<NCONV_BLOCKS, 256>>>(x, w_qkv, w_proj);

    qkv_tc_kernel<<<dim3(3 * CDIM / 128, (BATCH * NSEQ) / 128), 256, GEMM_SMEM>>>();

    attn_mma_kernel<<<dim3(NSEQ / 128, BH_TOT), 256, ATT_SMEM>>>();

    proj_tc_kernel<<<dim3(CDIM / 128, (BATCH * NSEQ) / 128), 256, GEMM_SMEM>>>(b_proj, out);
}

// round 8
// speedup vs baseline: 5.0045x; 1.3238x over previous
#include <cuda_runtime.h>
#include <cuda_fp16.h>
#include <cstdint>

#define BATCH 2
#define NSEQ  4096
#define CDIM  384
#define NH    6
#define HD    64
#define BH_TOT (BATCH * NH)
#define QK_SCALE 0.125f
#define L2E 1.4426950408889634f

// ================= scratch (allocation-free: __device__ globals) =============
__device__ __half g_xh[BATCH * NSEQ * CDIM];  // x as fp16 hi/lo
__device__ __half g_xl[BATCH * NSEQ * CDIM];
__device__ __half g_wqh[CDIM * 3 * CDIM];     // w_qkv hi/lo
__device__ __half g_wql[CDIM * 3 * CDIM];
__device__ __half g_wph[CDIM * CDIM];         // w_proj hi/lo
__device__ __half g_wpl[CDIM * CDIM];

__device__ __half g_qh[BH_TOT * NSEQ * HD];   // [BH,N,64] pre-scaled, hi
__device__ __half g_ql[BH_TOT * NSEQ * HD];   // Q lo (A-side corrected)
__device__ __half g_kh[BH_TOT * NSEQ * HD];   // K hi only (B-side)
__device__ __half g_vh[BH_TOT * NSEQ * HD];   // V hi only (B-side)
__device__ __half g_oh[BATCH * NSEQ * CDIM];  // attention out hi/lo
__device__ __half g_ol[BATCH * NSEQ * CDIM];

__device__ __forceinline__ float ex2f_fast(float x) {
    float y;
    asm("ex2.approx.f32 %0, %1;" : "=f"(y) : "f"(x));
    return y;
}

// fp16 split: hi pair + exact residual pair (a -> low half, b -> high half)
__device__ __forceinline__ void split2(float a, float b, uint32_t& hi, uint32_t& lo) {
    __half2 h = __floats2half2_rn(a, b);
    hi = *reinterpret_cast<uint32_t*>(&h);
    float2 hf = __half22float2(h);
    __half2 l = __floats2half2_rn(a - hf.x, b - hf.y);
    lo = *reinterpret_cast<uint32_t*>(&l);
}

__device__ __forceinline__ uint32_t smem_u32(const void* p) {
    uint32_t a;
    asm("{ .reg .u64 t; cvta.to.shared.u64 t, %1; cvt.u32.u64 %0, t; }" : "=r"(a) : "l"(p));
    return a;
}

__device__ __forceinline__ void ldsm_x2(uint32_t& r0, uint32_t& r1, uint32_t addr) {
    asm volatile("ldmatrix.sync.aligned.m8n8.x2.shared.b16 {%0,%1}, [%2];"
                 : "=r"(r0), "=r"(r1) : "r"(addr));
}
__device__ __forceinline__ void ldsm_x2_t(uint32_t& r0, uint32_t& r1, uint32_t addr) {
    asm volatile("ldmatrix.sync.aligned.m8n8.x2.trans.shared.b16 {%0,%1}, [%2];"
                 : "=r"(r0), "=r"(r1) : "r"(addr));
}
__device__ __forceinline__ void ldsm_x4(uint32_t* r, uint32_t addr) {
    asm volatile("ldmatrix.sync.aligned.m8n8.x4.shared.b16 {%0,%1,%2,%3}, [%4];"
                 : "=r"(r[0]), "=r"(r[1]), "=r"(r[2]), "=r"(r[3]) : "r"(addr));
}

#define MMA16816(d, a, b) \
    asm volatile( \
        "mma.sync.aligned.m16n8k16.row.col.f32.f16.f16.f32 " \
        "{%0,%1,%2,%3}, {%4,%5,%6,%7}, {%8,%9}, {%0,%1,%2,%3};" \
        : "+f"((d)[0]), "+f"((d)[1]), "+f"((d)[2]), "+f"((d)[3]) \
        : "r"((a)[0]), "r"((a)[1]), "r"((a)[2]), "r"((a)[3]), \
          "r"((b)[0]), "r"((b)[1]))

#define CP16(dst_u32, src_ptr) \
    asm volatile("cp.async.cg.shared.global [%0], [%1], 16;" :: "r"(dst_u32), "l"(src_ptr))
#define CP_COMMIT() asm volatile("cp.async.commit_group;" ::: "memory")
#define CP_WAIT1()  asm volatile("cp.async.wait_group 1;" ::: "memory")
#define CP_WAIT0()  asm volatile("cp.async.wait_group 0;" ::: "memory")

// ============================================================
// Kernel 0: fp32 -> fp16 hi/lo conversion (x, w_qkv, w_proj)
// ============================================================
#define NX4  (BATCH * NSEQ * CDIM / 4)
#define NWQ4 (CDIM * 3 * CDIM / 4)
#define NWP4 (CDIM * CDIM / 4)
#define NCONV_BLOCKS ((NX4 + NWQ4 + NWP4 + 255) / 256)

__global__ __launch_bounds__(256) void convert_kernel(
    const float* __restrict__ x, const float* __restrict__ wq,
    const float* __restrict__ wp)
{
    int i = blockIdx.x * 256 + threadIdx.x;
    const float* src;
    __half *hp, *lp;
    int off;
    if (i < NX4) { src = x; hp = g_xh; lp = g_xl; off = i; }
    else if (i < NX4 + NWQ4) { src = wq; hp = g_wqh; lp = g_wql; off = i - NX4; }
    else if (i < NX4 + NWQ4 + NWP4) { src = wp; hp = g_wph; lp = g_wpl; off = i - NX4 - NWQ4; }
    else return;
    float4 f = *(const float4*)(src + (size_t)off * 4);
    uint2 h, l;
    split2(f.x, f.y, h.x, l.x);
    split2(f.z, f.w, h.y, l.y);
    *(uint2*)(hp + (size_t)off * 4) = h;
    *(uint2*)(lp + (size_t)off * 4) = l;
}

// ============================================================
// Shared GEMM compute: 128x128 CTA, 8 warps (4m x 2n), K-step 32,
// fp16 hi/lo 3-chain, cp.async double-buffered.
// ============================================================
#define GBUF 36864
#define GAH 0
#define GAL 10240
#define GBH 20480
#define GBL 28672
#define GEMM_SMEM (2 * GBUF)

__device__ __forceinline__ void gemm_compute_step(
    float acc[2][8][4], uint32_t bb, int wm, int wn, int lane)
{
    const int l8 = lane & 7, l16 = lane & 15;
#pragma unroll
    for (int s = 0; s < 2; s++) {
        uint32_t ah[2][4], al[2][4];
        uint32_t arow = (uint32_t)((wm + l8 + 8 * ((lane >> 3) & 1)) * 80 +
                                   (2 * s + (lane >> 4)) * 16);
        ldsm_x4(ah[0], bb + GAH + arow);
        ldsm_x4(ah[1], bb + GAH + arow + 16 * 80);
        ldsm_x4(al[0], bb + GAL + arow);
        ldsm_x4(al[1], bb + GAL + arow + 16 * 80);

        uint32_t bf[8][2];
        const uint32_t brow = (uint32_t)((s * 16 + l16) * 256);
#pragma unroll
        for (int j = 0; j < 8; j++) {
            int jj = (wn >> 3) + j;
            ldsm_x2_t(bf[j][0], bf[j][1],
                      bb + GBH + brow + (uint32_t)(((jj ^ l8) << 4)));
        }
#pragma unroll
        for (int j = 0; j < 8; j++) {
            MMA16816(acc[0][j], ah[0], bf[j]);
            MMA16816(acc[1][j], ah[1], bf[j]);
        }
#pragma unroll
        for (int j = 0; j < 8; j++) {
            MMA16816(acc[0][j], al[0], bf[j]);
            MMA16816(acc[1][j], al[1], bf[j]);
        }
#pragma unroll
        for (int j = 0; j < 8; j++) {
            int jj = (wn >> 3) + j;
            ldsm_x2_t(bf[j][0], bf[j][1],
                      bb + GBL + brow + (uint32_t)(((jj ^ l8) << 4)));
        }
#pragma unroll
        for (int j = 0; j < 8; j++) {
            MMA16816(acc[0][j], ah[0], bf[j]);
            MMA16816(acc[1][j], ah[1], bf[j]);
        }
    }
}

// ============================================================
// Kernel 1: QKV GEMM -> Q(x0.125) hi/lo, K hi, V hi [BH,N,64]
// ============================================================
__global__ __launch_bounds__(256, 2) void qkv_tc_kernel()
{
    extern __shared__ char sm[];
    const uint32_t sb = smem_u32(sm);
    const int tid = threadIdx.x, warp = tid >> 5, lane = tid & 31;
    const int wm = (warp & 3) * 32, wn = (warp >> 2) * 64;
    const int row0 = blockIdx.y * 128, col0 = blockIdx.x * 128;

    float acc[2][8][4];
#pragma unroll
    for (int mi = 0; mi < 2; mi++)
#pragma unroll
        for (int j = 0; j < 8; j++)
#pragma unroll
            for (int i = 0; i < 4; i++) acc[mi][j][i] = 0.0f;

    auto stage = [&](int buf, int k0) {
        uint32_t base = sb + buf * GBUF;
#pragma unroll
        for (int it = 0; it < 2; it++) {
            int idx = tid + it * 256;
            int row = idx >> 2, ch = idx & 3;
            size_t g = (size_t)(row0 + row) * CDIM + k0 + ch * 8;
            CP16(base + GAH + row * 80 + ch * 16, g_xh + g);
            CP16(base + GAL + row * 80 + ch * 16, g_xl + g);
        }
#pragma unroll
        for (int it = 0; it < 2; it++) {
            int idx = tid + it * 256;
            int row = idx >> 4, ch = idx & 15;
            size_t g = (size_t)(k0 + row) * (3 * CDIM) + col0 + ch * 8;
            uint32_t sw = (uint32_t)(row * 256 + ((ch ^ (row & 7)) << 4));
            CP16(base + GBH + sw, g_wqh + g);
            CP16(base + GBL + sw, g_wql + g);
        }
    };

    stage(0, 0);
    CP_COMMIT();

    const int NIT = CDIM / 32;
    for (int kt = 0; kt < NIT; kt++) {
        if (kt < NIT - 1) {
            stage((kt + 1) & 1, (kt + 1) * 32);
            CP_COMMIT();
            CP_WAIT1();
        } else {
            CP_WAIT0();
        }
        __syncthreads();
        gemm_compute_step(acc, sb + (uint32_t)((kt & 1) * GBUF), wm, wn, lane);
        __syncthreads();
    }

    // epilogue: Q -> hi/lo (scaled); K/V -> hi only
    const int gid = lane >> 2, tq = lane & 3;
#pragma unroll
    for (int j = 0; j < 8; j++) {
        int col = col0 + wn + j * 8 + tq * 2;
        int which = col / CDIM, cm = col % CDIM;
        int h = cm / HD, d = cm % HD;
        float sc = (which == 0) ? QK_SCALE : 1.0f;
        __half* hp = (which == 0) ? g_qh : (which == 1) ? g_kh : g_vh;
#pragma unroll
        for (int mi = 0; mi < 2; mi++) {
#pragma unroll
            for (int rg = 0; rg < 2; rg++) {
                int m = row0 + wm + mi * 16 + gid + rg * 8;
                int b = m >> 12, n = m & (NSEQ - 1);
                size_t base = (((size_t)(b * NH + h)) * NSEQ + n) * HD + d;
                uint32_t hv, lv;
                split2(acc[mi][j][rg * 2] * sc, acc[mi][j][rg * 2 + 1] * sc, hv, lv);
                *(uint32_t*)&hp[base] = hv;
                if (which == 0) *(uint32_t*)&g_ql[base] = lv;
            }
        }
    }
}

// ============================================================
// Kernel 2: flash attention, fp16 2-chain (A-side corrected),
// K/V hi-only in smem, cp.async double-buffered, 2 CTAs/SM.
// ============================================================
#define STG 16384
#define SKH 0
#define SVH 8192
#define QA_OFF 32768           // per-warp 4096B: qah [s*512+lane*16], qal +2048
#define ATT_SMEM (2 * STG + 32768)

__global__ __launch_bounds__(256, 2) void attn_mma_kernel()
{
    extern __shared__ char smem[];
    const uint32_t sbase = smem_u32(smem);

    const int tid = threadIdx.x;
    const int warp = tid >> 5, lane = tid & 31;
    const int bh = blockIdx.y;
    const int r0 = blockIdx.x * 128;
    const int R = r0 + warp * 16;

    const int l8 = lane & 7;
    const int hseg = (lane >> 3) & 1;
    const int rA = R + (lane >> 2);
    const int kcol = (lane & 3) * 2;

    const __half* Qh = g_qh + (size_t)bh * NSEQ * HD;
    const __half* Ql = g_ql + (size_t)bh * NSEQ * HD;
    const __half* Kh = g_kh + (size_t)bh * NSEQ * HD;
    const __half* Vh = g_vh + (size_t)bh * NSEQ * HD;

    // park Q hi/lo a-fragments in warp-private smem slabs
    const uint32_t qa_base = (uint32_t)(QA_OFF + warp * 4096);
#pragma unroll
    for (int s = 0; s < 4; s++) {
        uint4 v;
        v.x = *(const uint32_t*)&Qh[(size_t)rA * HD + s * 16 + kcol];
        v.y = *(const uint32_t*)&Qh[(size_t)(rA + 8) * HD + s * 16 + kcol];
        v.z = *(const uint32_t*)&Qh[(size_t)rA * HD + s * 16 + 8 + kcol];
        v.w = *(const uint32_t*)&Qh[(size_t)(rA + 8) * HD + s * 16 + 8 + kcol];
        *(uint4*)(smem + qa_base + s * 512 + lane * 16) = v;
        v.x = *(const uint32_t*)&Ql[(size_t)rA * HD + s * 16 + kcol];
        v.y = *(const uint32_t*)&Ql[(size_t)(rA + 8) * HD + s * 16 + kcol];
        v.z = *(const uint32_t*)&Ql[(size_t)rA * HD + s * 16 + 8 + kcol];
        v.w = *(const uint32_t*)&Ql[(size_t)(rA + 8) * HD + s * 16 + 8 + kcol];
        *(uint4*)(smem + qa_base + 2048 + s * 512 + lane * 16) = v;
    }

    float of[8][4];
#pragma unroll
    for (int j = 0; j < 8; j++)
#pragma unroll
        for (int i = 0; i < 4; i++) of[j][i] = 0.0f;
    float mA = -1e30f, mB = -1e30f, lA = 0.0f, lB = 0.0f;

    const uint32_t krow = (uint32_t)(l8 * 128);

    auto stage = [&](int st, int kr0) {
#pragma unroll
        for (int it = 0; it < 2; it++) {
            int idx = tid + it * 256;
            int row = idx >> 3, ch = idx & 7;
            uint32_t sw = (uint32_t)(st * STG + row * 128 + ((ch ^ (row & 7)) << 4));
            size_t g = (size_t)(kr0 + row) * HD + ch * 8;
            CP16(sbase + sw + SKH, Kh + g);
            CP16(sbase + sw + SVH, Vh + g);
        }
    };

    stage(0, 0);
    CP_COMMIT();

    for (int kb = 0; kb < NSEQ / 64; kb++) {
        if (kb < NSEQ / 64 - 1) {
            stage((kb + 1) & 1, (kb + 1) * 64);
            CP_COMMIT();
            CP_WAIT1();
        } else {
            CP_WAIT0();
        }
        __syncthreads();
        const uint32_t stb = sbase + (uint32_t)((kb & 1) * STG);

        // ---- S = Qh K^T + Ql K^T (2 chains, j-chunked by 4) ----
        float sf[8][4];
#pragma unroll
        for (int j = 0; j < 8; j++)
#pragma unroll
            for (int i = 0; i < 4; i++) sf[j][i] = 0.0f;

#pragma unroll
        for (int s = 0; s < 4; s++) {
            uint32_t qh_s[4], ql_s[4];
            *(uint4*)qh_s = *(const uint4*)(smem + qa_base + s * 512 + lane * 16);
            *(uint4*)ql_s = *(const uint4*)(smem + qa_base + 2048 + s * 512 + lane * 16);
            uint32_t chsw = (uint32_t)((((2 * s + hseg) ^ l8) << 4));
#pragma unroll
            for (int jc = 0; jc < 8; jc += 4) {
                uint32_t kbf[4][2];
#pragma unroll
                for (int j = 0; j < 4; j++)
                    ldsm_x2(kbf[j][0], kbf[j][1],
                            stb + SKH + (uint32_t)((jc + j) * 1024) + krow + chsw);
#pragma unroll
                for (int j = 0; j < 4; j++) MMA16816(sf[jc + j], qh_s, kbf[j]);
#pragma unroll
                for (int j = 0; j < 4; j++) MMA16816(sf[jc + j], ql_s, kbf[j]);
            }
        }

        // ---- online softmax ----
        float mxA = sf[0][0], mxB = sf[0][2];
#pragma unroll
        for (int j = 0; j < 8; j++) {
            mxA = fmaxf(mxA, fmaxf(sf[j][0], sf[j][1]));
            mxB = fmaxf(mxB, fmaxf(sf[j][2], sf[j][3]));
        }
        mxA = fmaxf(mxA, __shfl_xor_sync(0xffffffffu, mxA, 1));
        mxA = fmaxf(mxA, __shfl_xor_sync(0xffffffffu, mxA, 2));
        mxB = fmaxf(mxB, __shfl_xor_sync(0xffffffffu, mxB, 1));
        mxB = fmaxf(mxB, __shfl_xor_sync(0xffffffffu, mxB, 2));

        float mnA = fmaxf(mA, mxA), mnB = fmaxf(mB, mxB);
        float corrA = ex2f_fast((mA - mnA) * L2E);
        float corrB = ex2f_fast((mB - mnB) * L2E);
        mA = mnA; mB = mnB;
        const float nlA = mnA * L2E, nlB = mnB * L2E;

        float sumA = 0.0f, sumB = 0.0f;
#pragma unroll
        for (int j = 0; j < 8; j++) {
            float p0 = ex2f_fast(fmaf(sf[j][0], L2E, -nlA));
            float p1 = ex2f_fast(fmaf(sf[j][1], L2E, -nlA));
            float p2 = ex2f_fast(fmaf(sf[j][2], L2E, -nlB));
            float p3 = ex2f_fast(fmaf(sf[j][3], L2E, -nlB));
            sumA += p0 + p1; sumB += p2 + p3;
            sf[j][0] = p0; sf[j][1] = p1; sf[j][2] = p2; sf[j][3] = p3;
        }
        lA = lA * corrA + sumA;
        lB = lB * corrB + sumB;

#pragma unroll
        for (int j = 0; j < 8; j++) {
            of[j][0] *= corrA; of[j][1] *= corrA;
            of[j][2] *= corrB; of[j][3] *= corrB;
        }

        // ---- O += Ph V + Pl V (2 chains, j-chunked by 4) ----
#pragma unroll
        for (int s = 0; s < 4; s++) {
            uint32_t pah[4], pal[4];
            split2(sf[2 * s][0], sf[2 * s][1], pah[0], pal[0]);
            split2(sf[2 * s][2], sf[2 * s][3], pah[1], pal[1]);
            split2(sf[2 * s + 1][0], sf[2 * s + 1][1], pah[2], pal[2]);
            split2(sf[2 * s + 1][2], sf[2 * s + 1][3], pah[3], pal[3]);

            uint32_t vrow = (uint32_t)((16 * s + 8 * hseg + l8) * 128);
#pragma unroll
            for (int jc = 0; jc < 8; jc += 4) {
                uint32_t vbf[4][2];
#pragma unroll
                for (int j = 0; j < 4; j++)
                    ldsm_x2_t(vbf[j][0], vbf[j][1],
                              stb + SVH + vrow + (uint32_t)((((jc + j) ^ l8) << 4)));
#pragma unroll
                for (int j = 0; j < 4; j++) MMA16816(of[jc + j], pah, vbf[j]);
#pragma unroll
                for (int j = 0; j < 4; j++) MMA16816(of[jc + j], pal, vbf[j]);
            }
        }
        __syncthreads();
    }

    // ---- epilogue: write O as fp16 hi/lo [B,N,C] ----
    lA += __shfl_xor_sync(0xffffffffu, lA, 1);
    lA += __shfl_xor_sync(0xffffffffu, lA, 2);
    lB += __shfl_xor_sync(0xffffffffu, lB, 1);
    lB += __shfl_xor_sync(0xffffffffu, lB, 2);
    const float invA = 1.0f / lA, invB = 1.0f / lB;

    const int b = bh / NH, h = bh % NH;
    size_t baseA = ((size_t)b * NSEQ + rA) * CDIM + h * HD;
    size_t baseB = ((size_t)b * NSEQ + rA + 8) * CDIM + h * HD;
#pragma unroll
    for (int j = 0; j < 8; j++) {
        int c = j * 8 + kcol;
        uint32_t hv, lv;
        split2(of[j][0] * invA, of[j][1] * invA, hv, lv);
        *(uint32_t*)&g_oh[baseA + c] = hv;
        *(uint32_t*)&g_ol[baseA + c] = lv;
        split2(of[j][2] * invB, of[j][3] * invB, hv, lv);
        *(uint32_t*)&g_oh[baseB + c] = hv;
        *(uint32_t*)&g_ol[baseB + c] = lv;
    }
}

// ============================================================
// Kernel 3: proj GEMM (fp16 3-chain) + bias -> out fp32
// ============================================================
__global__ __launch_bounds__(256, 2) void proj_tc_kernel(
    const float* __restrict__ bias, float* __restrict__ out)
{
    extern __shared__ char sm[];
    const uint32_t sb = smem_u32(sm);
    const int tid = threadIdx.x, warp = tid >> 5, lane = tid & 31;
    const int wm = (warp & 3) * 32, wn = (warp >> 2) * 64;
    const int row0 = blockIdx.y * 128, col0 = blockIdx.x * 128;

    float acc[2][8][4];
#pragma unroll
    for (int mi = 0; mi < 2; mi++)
#pragma unroll
        for (int j = 0; j < 8; j++)
#pragma unroll
            for (int i = 0; i < 4; i++) acc[mi][j][i] = 0.0f;

    auto stage = [&](int buf, int k0) {
        uint32_t base = sb + buf * GBUF;
#pragma unroll
        for (int it = 0; it < 2; it++) {
            int idx = tid + it * 256;
            int row = idx >> 2, ch = idx & 3;
            size_t g = (size_t)(row0 + row) * CDIM + k0 + ch * 8;
            CP16(base + GAH + row * 80 + ch * 16, g_oh + g);
            CP16(base + GAL + row * 80 + ch * 16, g_ol + g);
        }
#pragma unroll
        for (int it = 0; it < 2; it++) {
            int idx = tid + it * 256;
            int row = idx >> 4, ch = idx & 15;
            size_t g = (size_t)(k0 + row) * CDIM + col0 + ch * 8;
            uint32_t sw = (uint32_t)(row * 256 + ((ch ^ (row & 7)) << 4));
            CP16(base + GBH + sw, g_wph + g);
            CP16(base + GBL + sw, g_wpl + g);
        }
    };

    stage(0, 0);
    CP_COMMIT();

    const int NIT = CDIM / 32;
    for (int kt = 0; kt < NIT; kt++) {
        if (kt < NIT - 1) {
            stage((kt + 1) & 1, (kt + 1) * 32);
            CP_COMMIT();
            CP_WAIT1();
        } else {
            CP_WAIT0();
        }
        __syncthreads();
        gemm_compute_step(acc, sb + (uint32_t)((kt & 1) * GBUF), wm, wn, lane);
        __syncthreads();
    }

    const int gid = lane >> 2, tq = lane & 3;
#pragma unroll
    for (int j = 0; j < 8; j++) {
        int col = col0 + wn + j * 8 + tq * 2;
        float2 bv = *(const float2*)&bias[col];
#pragma unroll
        for (int mi = 0; mi < 2; mi++) {
#pragma unroll
            for (int rg = 0; rg < 2; rg++) {
                int m = row0 + wm + mi * 16 + gid + rg * 8;
                float2 o = make_float2(acc[mi][j][rg * 2] + bv.x,
                                       acc[mi][j][rg * 2 + 1] + bv.y);
                *(float2*)&out[(size_t)m * CDIM + col] = o;
            }
        }
    }
}

// ============================================================
extern "C" void kernel_launch(void* const* d_in, const int* in_sizes, int n_in,
                              void* d_out, int out_size)
{
    const float* x      = (const float*)d_in[0];
    const float* w_qkv  = (const float*)d_in[1];
    const float* w_proj = (const float*)d_in[2];
    const float* b_proj = (const float*)d_in[3];
    float* out = (float*)d_out;

    (void)in_sizes; (void)n_in; (void)out_size;

    cudaFuncSetAttribute(qkv_tc_kernel,
                         cudaFuncAttributeMaxDynamicSharedMemorySize, GEMM_SMEM);
    cudaFuncSetAttribute(attn_mma_kernel,
                         cudaFuncAttributeMaxDynamicSharedMemorySize, ATT_SMEM);
    cudaFuncSetAttribute(proj_tc_kernel,
                         cudaFuncAttributeMaxDynamicSharedMemorySize, GEMM_SMEM);

    convert_kernel<<<NCONV_BLOCKS, 256>>>(x, w_qkv, w_proj);

    qkv_tc_kernel<<<dim3(3 * CDIM / 128, (BATCH * NSEQ) / 128), 256, GEMM_SMEM>>>();

    attn_mma_kernel<<<dim3(NSEQ / 128, BH_TOT), 256, ATT_SMEM>>>();

    proj_tc_kernel<<<dim3(CDIM / 128, (BATCH * NSEQ) / 128), 256, GEMM_SMEM>>>(b_proj, out);
}

// round 10
// speedup vs baseline: 6.7824x; 1.3552x over previous
#include <cuda_runtime.h>
#include <cuda_fp16.h>
#include <cstdint>

#define BATCH 2
#define NSEQ  4096
#define CDIM  384
#define NH    6
#define HD    64
#define BH_TOT (BATCH * NH)
#define QK_SCALE 0.125f
#define L2E 1.4426950408889634f

// ================= scratch (allocation-free: __device__ globals) =============
__device__ __half g_xh[BATCH * NSEQ * CDIM];  // x as fp16 hi/lo
__device__ __half g_xl[BATCH * NSEQ * CDIM];
__device__ __half g_wqh[CDIM * 3 * CDIM];     // w_qkv hi/lo
__device__ __half g_wql[CDIM * 3 * CDIM];
__device__ __half g_wph[CDIM * CDIM];         // w_proj hi/lo
__device__ __half g_wpl[CDIM * CDIM];

__device__ __half g_qh[BH_TOT * NSEQ * HD];   // [BH,N,64] pre-scaled, hi only
__device__ __half g_kh[BH_TOT * NSEQ * HD];   // K hi only
__device__ __half g_vh[BH_TOT * NSEQ * HD];   // V hi only
__device__ __half g_oh[BATCH * NSEQ * CDIM];  // attention out hi/lo
__device__ __half g_ol[BATCH * NSEQ * CDIM];

__device__ __forceinline__ float ex2f_fast(float x) {
    float y;
    asm("ex2.approx.f32 %0, %1;" : "=f"(y) : "f"(x));
    return y;
}

// fp16 split: hi pair + exact residual pair
__device__ __forceinline__ void split2(float a, float b, uint32_t& hi, uint32_t& lo) {
    __half2 h = __floats2half2_rn(a, b);
    hi = *reinterpret_cast<uint32_t*>(&h);
    float2 hf = __half22float2(h);
    __half2 l = __floats2half2_rn(a - hf.x, b - hf.y);
    lo = *reinterpret_cast<uint32_t*>(&l);
}

__device__ __forceinline__ uint32_t pack_h2(float a, float b) {
    __half2 h = __floats2half2_rn(a, b);
    return *reinterpret_cast<uint32_t*>(&h);
}

__device__ __forceinline__ uint32_t smem_u32(const void* p) {
    uint32_t a;
    asm("{ .reg .u64 t; cvta.to.shared.u64 t, %1; cvt.u32.u64 %0, t; }" : "=r"(a) : "l"(p));
    return a;
}

__device__ __forceinline__ void ldsm_x2(uint32_t& r0, uint32_t& r1, uint32_t addr) {
    asm volatile("ldmatrix.sync.aligned.m8n8.x2.shared.b16 {%0,%1}, [%2];"
                 : "=r"(r0), "=r"(r1) : "r"(addr));
}
__device__ __forceinline__ void ldsm_x2_t(uint32_t& r0, uint32_t& r1, uint32_t addr) {
    asm volatile("ldmatrix.sync.aligned.m8n8.x2.trans.shared.b16 {%0,%1}, [%2];"
                 : "=r"(r0), "=r"(r1) : "r"(addr));
}
__device__ __forceinline__ void ldsm_x4(uint32_t* r, uint32_t addr) {
    asm volatile("ldmatrix.sync.aligned.m8n8.x4.shared.b16 {%0,%1,%2,%3}, [%4];"
                 : "=r"(r[0]), "=r"(r[1]), "=r"(r[2]), "=r"(r[3]) : "r"(addr));
}

#define MMA16816(d, a, b) \
    asm volatile( \
        "mma.sync.aligned.m16n8k16.row.col.f32.f16.f16.f32 " \
        "{%0,%1,%2,%3}, {%4,%5,%6,%7}, {%8,%9}, {%0,%1,%2,%3};" \
        : "+f"((d)[0]), "+f"((d)[1]), "+f"((d)[2]), "+f"((d)[3]) \
        : "r"((a)[0]), "r"((a)[1]), "r"((a)[2]), "r"((a)[3]), \
          "r"((b)[0]), "r"((b)[1]))

#define CP16(dst_u32, src_ptr) \
    asm volatile("cp.async.cg.shared.global [%0], [%1], 16;" :: "r"(dst_u32), "l"(src_ptr))
#define CP_COMMIT() asm volatile("cp.async.commit_group;" ::: "memory")
#define CP_WAIT1()  asm volatile("cp.async.wait_group 1;" ::: "memory")
#define CP_WAIT0()  asm volatile("cp.async.wait_group 0;" ::: "memory")

// ============================================================
// Kernel 0: fp32 -> fp16 hi/lo conversion (x, w_qkv, w_proj)
// ============================================================
#define NX4  (BATCH * NSEQ * CDIM / 4)
#define NWQ4 (CDIM * 3 * CDIM / 4)
#define NWP4 (CDIM * CDIM / 4)
#define NCONV_BLOCKS ((NX4 + NWQ4 + NWP4 + 255) / 256)

__global__ __launch_bounds__(256) void convert_kernel(
    const float* __restrict__ x, const float* __restrict__ wq,
    const float* __restrict__ wp)
{
    int i = blockIdx.x * 256 + threadIdx.x;
    const float* src;
    __half *hp, *lp;
    int off;
    if (i < NX4) { src = x; hp = g_xh; lp = g_xl; off = i; }
    else if (i < NX4 + NWQ4) { src = wq; hp = g_wqh; lp = g_wql; off = i - NX4; }
    else if (i < NX4 + NWQ4 + NWP4) { src = wp; hp = g_wph; lp = g_wpl; off = i - NX4 - NWQ4; }
    else return;
    float4 f = *(const float4*)(src + (size_t)off * 4);
    uint2 h, l;
    split2(f.x, f.y, h.x, l.x);
    split2(f.z, f.w, h.y, l.y);
    *(uint2*)(hp + (size_t)off * 4) = h;
    *(uint2*)(lp + (size_t)off * 4) = l;
}

// ============================================================
// Shared GEMM compute: 128x128 CTA, 8 warps (4m x 2n), K-step 32,
// fp16 hi/lo 3-chain, cp.async double-buffered.
// ============================================================
#define GBUF 36864
#define GAH 0
#define GAL 10240
#define GBH 20480
#define GBL 28672
#define GEMM_SMEM (2 * GBUF)

__device__ __forceinline__ void gemm_compute_step(
    float acc[2][8][4], uint32_t bb, int wm, int wn, int lane)
{
    const int l8 = lane & 7, l16 = lane & 15;
#pragma unroll
    for (int s = 0; s < 2; s++) {
        uint32_t ah[2][4], al[2][4];
        uint32_t arow = (uint32_t)((wm + l8 + 8 * ((lane >> 3) & 1)) * 80 +
                                   (2 * s + (lane >> 4)) * 16);
        ldsm_x4(ah[0], bb + GAH + arow);
        ldsm_x4(ah[1], bb + GAH + arow + 16 * 80);
        ldsm_x4(al[0], bb + GAL + arow);
        ldsm_x4(al[1], bb + GAL + arow + 16 * 80);

        uint32_t bf[8][2];
        const uint32_t brow = (uint32_t)((s * 16 + l16) * 256);
#pragma unroll
        for (int j = 0; j < 8; j++) {
            int jj = (wn >> 3) + j;
            ldsm_x2_t(bf[j][0], bf[j][1],
                      bb + GBH + brow + (uint32_t)(((jj ^ l8) << 4)));
        }
#pragma unroll
        for (int j = 0; j < 8; j++) {
            MMA16816(acc[0][j], ah[0], bf[j]);
            MMA16816(acc[1][j], ah[1], bf[j]);
        }
#pragma unroll
        for (int j = 0; j < 8; j++) {
            MMA16816(acc[0][j], al[0], bf[j]);
            MMA16816(acc[1][j], al[1], bf[j]);
        }
#pragma unroll
        for (int j = 0; j < 8; j++) {
            int jj = (wn >> 3) + j;
            ldsm_x2_t(bf[j][0], bf[j][1],
                      bb + GBL + brow + (uint32_t)(((jj ^ l8) << 4)));
        }
#pragma unroll
        for (int j = 0; j < 8; j++) {
            MMA16816(acc[0][j], ah[0], bf[j]);
            MMA16816(acc[1][j], ah[1], bf[j]);
        }
    }
}

// ============================================================
// Kernel 1: QKV GEMM -> Q(x0.125)/K/V hi [BH,N,64]
// ============================================================
__global__ __launch_bounds__(256, 2) void qkv_tc_kernel()
{
    extern __shared__ char sm[];
    const uint32_t sb = smem_u32(sm);
    const int tid = threadIdx.x, warp = tid >> 5, lane = tid & 31;
    const int wm = (warp & 3) * 32, wn = (warp >> 2) * 64;
    const int row0 = blockIdx.y * 128, col0 = blockIdx.x * 128;

    float acc[2][8][4];
#pragma unroll
    for (int mi = 0; mi < 2; mi++)
#pragma unroll
        for (int j = 0; j < 8; j++)
#pragma unroll
            for (int i = 0; i < 4; i++) acc[mi][j][i] = 0.0f;

    auto stage = [&](int buf, int k0) {
        uint32_t base = sb + buf * GBUF;
#pragma unroll
        for (int it = 0; it < 2; it++) {
            int idx = tid + it * 256;
            int row = idx >> 2, ch = idx & 3;
            size_t g = (size_t)(row0 + row) * CDIM + k0 + ch * 8;
            CP16(base + GAH + row * 80 + ch * 16, g_xh + g);
            CP16(base + GAL + row * 80 + ch * 16, g_xl + g);
        }
#pragma unroll
        for (int it = 0; it < 2; it++) {
            int idx = tid + it * 256;
            int row = idx >> 4, ch = idx & 15;
            size_t g = (size_t)(k0 + row) * (3 * CDIM) + col0 + ch * 8;
            uint32_t sw = (uint32_t)(row * 256 + ((ch ^ (row & 7)) << 4));
            CP16(base + GBH + sw, g_wqh + g);
            CP16(base + GBL + sw, g_wql + g);
        }
    };

    stage(0, 0);
    CP_COMMIT();

    const int NIT = CDIM / 32;
    for (int kt = 0; kt < NIT; kt++) {
        if (kt < NIT - 1) {
            stage((kt + 1) & 1, (kt + 1) * 32);
            CP_COMMIT();
            CP_WAIT1();
        } else {
            CP_WAIT0();
        }
        __syncthreads();
        gemm_compute_step(acc, sb + (uint32_t)((kt & 1) * GBUF), wm, wn, lane);
        __syncthreads();
    }

    // epilogue: hi only
    const int gid = lane >> 2, tq = lane & 3;
#pragma unroll
    for (int j = 0; j < 8; j++) {
        int col = col0 + wn + j * 8 + tq * 2;
        int which = col / CDIM, cm = col % CDIM;
        int h = cm / HD, d = cm % HD;
        float sc = (which == 0) ? QK_SCALE : 1.0f;
        __half* hp = (which == 0) ? g_qh : (which == 1) ? g_kh : g_vh;
#pragma unroll
        for (int mi = 0; mi < 2; mi++) {
#pragma unroll
            for (int rg = 0; rg < 2; rg++) {
                int m = row0 + wm + mi * 16 + gid + rg * 8;
                int b = m >> 12, n = m & (NSEQ - 1);
                size_t base = (((size_t)(b * NH + h)) * NSEQ + n) * HD + d;
                *(uint32_t*)&hp[base] =
                    pack_h2(acc[mi][j][rg * 2] * sc, acc[mi][j][rg * 2 + 1] * sc);
            }
        }
    }
}

// ============================================================
// Kernel 2: flash attention, single-chain fp16,
// K/V hi-only in smem, cp.async double-buffered, 2 CTAs/SM.
// ============================================================
#define STG 16384
#define SKH 0
#define SVH 8192
#define ATT_SMEM (2 * STG)

__global__ __launch_bounds__(256, 2) void attn_mma_kernel()
{
    extern __shared__ char smem[];
    const uint32_t sbase = smem_u32(smem);

    const int tid = threadIdx.x;
    const int warp = tid >> 5, lane = tid & 31;
    const int bh = blockIdx.y;
    const int r0 = blockIdx.x * 128;
    const int R = r0 + warp * 16;

    const int l8 = lane & 7;
    const int hseg = (lane >> 3) & 1;
    const int rA = R + (lane >> 2);
    const int kcol = (lane & 3) * 2;

    const __half* Qh = g_qh + (size_t)bh * NSEQ * HD;
    const __half* Kh = g_kh + (size_t)bh * NSEQ * HD;
    const __half* Vh = g_vh + (size_t)bh * NSEQ * HD;

    // Q hi a-fragments in registers
    uint32_t qah[4][4];
#pragma unroll
    for (int s = 0; s < 4; s++) {
        qah[s][0] = *(const uint32_t*)&Qh[(size_t)rA * HD + s * 16 + kcol];
        qah[s][1] = *(const uint32_t*)&Qh[(size_t)(rA + 8) * HD + s * 16 + kcol];
        qah[s][2] = *(const uint32_t*)&Qh[(size_t)rA * HD + s * 16 + 8 + kcol];
        qah[s][3] = *(const uint32_t*)&Qh[(size_t)(rA + 8) * HD + s * 16 + 8 + kcol];
    }

    float of[8][4];
#pragma unroll
    for (int j = 0; j < 8; j++)
#pragma unroll
        for (int i = 0; i < 4; i++) of[j][i] = 0.0f;
    float mA = -1e30f, mB = -1e30f, lA = 0.0f, lB = 0.0f;

    const uint32_t krow = (uint32_t)(l8 * 128);

    auto stage = [&](int st, int kr0) {
#pragma unroll
        for (int it = 0; it < 2; it++) {
            int idx = tid + it * 256;
            int row = idx >> 3, ch = idx & 7;
            uint32_t sw = (uint32_t)(st * STG + row * 128 + ((ch ^ (row & 7)) << 4));
            size_t g = (size_t)(kr0 + row) * HD + ch * 8;
            CP16(sbase + sw + SKH, Kh + g);
            CP16(sbase + sw + SVH, Vh + g);
        }
    };

    stage(0, 0);
    CP_COMMIT();

    for (int kb = 0; kb < NSEQ / 64; kb++) {
        if (kb < NSEQ / 64 - 1) {
            stage((kb + 1) & 1, (kb + 1) * 64);
            CP_COMMIT();
            CP_WAIT1();
        } else {
            CP_WAIT0();
        }
        __syncthreads();
        const uint32_t stb = sbase + (uint32_t)((kb & 1) * STG);

        // ---- S = Q K^T (single chain) ----
        float sf[8][4];
#pragma unroll
        for (int j = 0; j < 8; j++)
#pragma unroll
            for (int i = 0; i < 4; i++) sf[j][i] = 0.0f;

#pragma unroll
        for (int s = 0; s < 4; s++) {
            uint32_t chsw = (uint32_t)((((2 * s + hseg) ^ l8) << 4));
#pragma unroll
            for (int jc = 0; jc < 8; jc += 4) {
                uint32_t kbf[4][2];
#pragma unroll
                for (int j = 0; j < 4; j++)
                    ldsm_x2(kbf[j][0], kbf[j][1],
                            stb + SKH + (uint32_t)((jc + j) * 1024) + krow + chsw);
#pragma unroll
                for (int j = 0; j < 4; j++) MMA16816(sf[jc + j], qah[s], kbf[j]);
            }
        }

        // ---- online softmax ----
        float mxA = sf[0][0], mxB = sf[0][2];
#pragma unroll
        for (int j = 0; j < 8; j++) {
            mxA = fmaxf(mxA, fmaxf(sf[j][0], sf[j][1]));
            mxB = fmaxf(mxB, fmaxf(sf[j][2], sf[j][3]));
        }
        mxA = fmaxf(mxA, __shfl_xor_sync(0xffffffffu, mxA, 1));
        mxA = fmaxf(mxA, __shfl_xor_sync(0xffffffffu, mxA, 2));
        mxB = fmaxf(mxB, __shfl_xor_sync(0xffffffffu, mxB, 1));
        mxB = fmaxf(mxB, __shfl_xor_sync(0xffffffffu, mxB, 2));

        float mnA = fmaxf(mA, mxA), mnB = fmaxf(mB, mxB);
        float corrA = ex2f_fast((mA - mnA) * L2E);
        float corrB = ex2f_fast((mB - mnB) * L2E);
        mA = mnA; mB = mnB;
        const float nlA = mnA * L2E, nlB = mnB * L2E;

        float sumA = 0.0f, sumB = 0.0f;
#pragma unroll
        for (int j = 0; j < 8; j++) {
            float p0 = ex2f_fast(fmaf(sf[j][0], L2E, -nlA));
            float p1 = ex2f_fast(fmaf(sf[j][1], L2E, -nlA));
            float p2 = ex2f_fast(fmaf(sf[j][2], L2E, -nlB));
            float p3 = ex2f_fast(fmaf(sf[j][3], L2E, -nlB));
            sumA += p0 + p1; sumB += p2 + p3;
            sf[j][0] = p0; sf[j][1] = p1; sf[j][2] = p2; sf[j][3] = p3;
        }
        lA = lA * corrA + sumA;
        lB = lB * corrB + sumB;

#pragma unroll
        for (int j = 0; j < 8; j++) {
            of[j][0] *= corrA; of[j][1] *= corrA;
            of[j][2] *= corrB; of[j][3] *= corrB;
        }

        // ---- O += P V (single chain) ----
#pragma unroll
        for (int s = 0; s < 4; s++) {
            uint32_t pah[4];
            pah[0] = pack_h2(sf[2 * s][0], sf[2 * s][1]);
            pah[1] = pack_h2(sf[2 * s][2], sf[2 * s][3]);
            pah[2] = pack_h2(sf[2 * s + 1][0], sf[2 * s + 1][1]);
            pah[3] = pack_h2(sf[2 * s + 1][2], sf[2 * s + 1][3]);

            uint32_t vrow = (uint32_t)((16 * s + 8 * hseg + l8) * 128);
#pragma unroll
            for (int jc = 0; jc < 8; jc += 4) {
                uint32_t vbf[4][2];
#pragma unroll
                for (int j = 0; j < 4; j++)
                    ldsm_x2_t(vbf[j][0], vbf[j][1],
                              stb + SVH + vrow + (uint32_t)((((jc + j) ^ l8) << 4)));
#pragma unroll
                for (int j = 0; j < 4; j++) MMA16816(of[jc + j], pah, vbf[j]);
            }
        }
        __syncthreads();
    }

    // ---- epilogue: write O as fp16 hi/lo [B,N,C] ----
    lA += __shfl_xor_sync(0xffffffffu, lA, 1);
    lA += __shfl_xor_sync(0xffffffffu, lA, 2);
    lB += __shfl_xor_sync(0xffffffffu, lB, 1);
    lB += __shfl_xor_sync(0xffffffffu, lB, 2);
    const float invA = 1.0f / lA, invB = 1.0f / lB;

    const int b = bh / NH, h = bh % NH;
    size_t baseA = ((size_t)b * NSEQ + rA) * CDIM + h * HD;
    size_t baseB = ((size_t)b * NSEQ + rA + 8) * CDIM + h * HD;
#pragma unroll
    for (int j = 0; j < 8; j++) {
        int c = j * 8 + kcol;
        uint32_t hv, lv;
        split2(of[j][0] * invA, of[j][1] * invA, hv, lv);
        *(uint32_t*)&g_oh[baseA + c] = hv;
        *(uint32_t*)&g_ol[baseA + c] = lv;
        split2(of[j][2] * invB, of[j][3] * invB, hv, lv);
        *(uint32_t*)&g_oh[baseB + c] = hv;
        *(uint32_t*)&g_ol[baseB + c] = lv;
    }
}

// ============================================================
// Kernel 3: proj GEMM (fp16 3-chain) + bias -> out fp32
// ============================================================
__global__ __launch_bounds__(256, 2) void proj_tc_kernel(
    const float* __restrict__ bias, float* __restrict__ out)
{
    extern __shared__ char sm[];
    const uint32_t sb = smem_u32(sm);
    const int tid = threadIdx.x, warp = tid >> 5, lane = tid & 31;
    const int wm = (warp & 3) * 32, wn = (warp >> 2) * 64;
    const int row0 = blockIdx.y * 128, col0 = blockIdx.x * 128;

    float acc[2][8][4];
#pragma unroll
    for (int mi = 0; mi < 2; mi++)
#pragma unroll
        for (int j = 0; j < 8; j++)
#pragma unroll
            for (int i = 0; i < 4; i++) acc[mi][j][i] = 0.0f;

    auto stage = [&](int buf, int k0) {
        uint32_t base = sb + buf * GBUF;
#pragma unroll
        for (int it = 0; it < 2; it++) {
            int idx = tid + it * 256;
            int row = idx >> 2, ch = idx & 3;
            size_t g = (size_t)(row0 + row) * CDIM + k0 + ch * 8;
            CP16(base + GAH + row * 80 + ch * 16, g_oh + g);
            CP16(base + GAL + row * 80 + ch * 16, g_ol + g);
        }
#pragma unroll
        for (int it = 0; it < 2; it++) {
            int idx = tid + it * 256;
            int row = idx >> 4, ch = idx & 15;
            size_t g = (size_t)(k0 + row) * CDIM + col0 + ch * 8;
            uint32_t sw = (uint32_t)(row * 256 + ((ch ^ (row & 7)) << 4));
            CP16(base + GBH + sw, g_wph + g);
            CP16(base + GBL + sw, g_wpl + g);
        }
    };

    stage(0, 0);
    CP_COMMIT();

    const int NIT = CDIM / 32;
    for (int kt = 0; kt < NIT; kt++) {
        if (kt < NIT - 1) {
            stage((kt + 1) & 1, (kt + 1) * 32);
            CP_COMMIT();
            CP_WAIT1();
        } else {
            CP_WAIT0();
        }
        __syncthreads();
        gemm_compute_step(acc, sb + (uint32_t)((kt & 1) * GBUF), wm, wn, lane);
        __syncthreads();
    }

    const int gid = lane >> 2, tq = lane & 3;
#pragma unroll
    for (int j = 0; j < 8; j++) {
        int col = col0 + wn + j * 8 + tq * 2;
        float2 bv = *(const float2*)&bias[col];
#pragma unroll
        for (int mi = 0; mi < 2; mi++) {
#pragma unroll
            for (int rg = 0; rg < 2; rg++) {
                int m = row0 + wm + mi * 16 + gid + rg * 8;
                float2 o = make_float2(acc[mi][j][rg * 2] + bv.x,
                                       acc[mi][j][rg * 2 + 1] + bv.y);
                *(float2*)&out[(size_t)m * CDIM + col] = o;
            }
        }
    }
}

// ============================================================
extern "C" void kernel_launch(void* const* d_in, const int* in_sizes, int n_in,
                              void* d_out, int out_size)
{
    const float* x      = (const float*)d_in[0];
    const float* w_qkv  = (const float*)d_in[1];
    const float* w_proj = (const float*)d_in[2];
    const float* b_proj = (const float*)d_in[3];
    float* out = (float*)d_out;

    (void)in_sizes; (void)n_in; (void)out_size;

    cudaFuncSetAttribute(qkv_tc_kernel,
                         cudaFuncAttributeMaxDynamicSharedMemorySize, GEMM_SMEM);
    cudaFuncSetAttribute(attn_mma_kernel,
                         cudaFuncAttributeMaxDynamicSharedMemorySize, ATT_SMEM);
    cudaFuncSetAttribute(proj_tc_kernel,
                         cudaFuncAttributeMaxDynamicSharedMemorySize, GEMM_SMEM);

    convert_kernel<<<NCONV_BLOCKS, 256>>>(x, w_qkv, w_proj);

    qkv_tc_kernel<<<dim3(3 * CDIM / 128, (BATCH * NSEQ) / 128), 256, GEMM_SMEM>>>();

    attn_mma_kernel<<<dim3(NSEQ / 128, BH_TOT), 256, ATT_SMEM>>>();

    proj_tc_kernel<<<dim3(CDIM / 128, (BATCH * NSEQ) / 128), 256, GEMM_SMEM>>>(b_proj, out);
}

// round 11
// speedup vs baseline: 7.7134x; 1.1373x over previous
#include <cuda_runtime.h>
#include <cuda_fp16.h>
#include <cstdint>

#define BATCH 2
#define NSEQ  4096
#define CDIM  384
#define NH    6
#define HD    64
#define BH_TOT (BATCH * NH)
#define QK_SCALE 0.125f
#define L2E 1.4426950408889634f
#define NSPLIT 3
#define NKB (NSEQ / 64)

// ================= scratch (allocation-free: __device__ globals) =============
__device__ __half g_xh[BATCH * NSEQ * CDIM];  // x as fp16 hi/lo
__device__ __half g_xl[BATCH * NSEQ * CDIM];
__device__ __half g_wqh[CDIM * 3 * CDIM];     // w_qkv hi only
__device__ __half g_wph[CDIM * CDIM];         // w_proj hi only

__device__ __half g_qh[BH_TOT * NSEQ * HD];   // [BH,N,64] pre-scaled, hi only
__device__ __half g_kh[BH_TOT * NSEQ * HD];   // K hi only
__device__ __half g_vh[BH_TOT * NSEQ * HD];   // V hi only

__device__ float  g_opart[NSPLIT * BH_TOT * NSEQ * HD];  // split-KV partial O
__device__ float2 g_ml[NSPLIT * BH_TOT * NSEQ];          // per-row (m, l)

__device__ __half g_oh[BATCH * NSEQ * CDIM];  // attention out hi/lo
__device__ __half g_ol[BATCH * NSEQ * CDIM];

__device__ __forceinline__ float ex2f_fast(float x) {
    float y;
    asm("ex2.approx.f32 %0, %1;" : "=f"(y) : "f"(x));
    return y;
}

// fp16 split: hi pair + exact residual pair
__device__ __forceinline__ void split2(float a, float b, uint32_t& hi, uint32_t& lo) {
    __half2 h = __floats2half2_rn(a, b);
    hi = *reinterpret_cast<uint32_t*>(&h);
    float2 hf = __half22float2(h);
    __half2 l = __floats2half2_rn(a - hf.x, b - hf.y);
    lo = *reinterpret_cast<uint32_t*>(&l);
}

__device__ __forceinline__ uint32_t pack_h2(float a, float b) {
    __half2 h = __floats2half2_rn(a, b);
    return *reinterpret_cast<uint32_t*>(&h);
}

__device__ __forceinline__ uint32_t smem_u32(const void* p) {
    uint32_t a;
    asm("{ .reg .u64 t; cvta.to.shared.u64 t, %1; cvt.u32.u64 %0, t; }" : "=r"(a) : "l"(p));
    return a;
}

__device__ __forceinline__ void ldsm_x2(uint32_t& r0, uint32_t& r1, uint32_t addr) {
    asm volatile("ldmatrix.sync.aligned.m8n8.x2.shared.b16 {%0,%1}, [%2];"
                 : "=r"(r0), "=r"(r1) : "r"(addr));
}
__device__ __forceinline__ void ldsm_x2_t(uint32_t& r0, uint32_t& r1, uint32_t addr) {
    asm volatile("ldmatrix.sync.aligned.m8n8.x2.trans.shared.b16 {%0,%1}, [%2];"
                 : "=r"(r0), "=r"(r1) : "r"(addr));
}
__device__ __forceinline__ void ldsm_x4(uint32_t* r, uint32_t addr) {
    asm volatile("ldmatrix.sync.aligned.m8n8.x4.shared.b16 {%0,%1,%2,%3}, [%4];"
                 : "=r"(r[0]), "=r"(r[1]), "=r"(r[2]), "=r"(r[3]) : "r"(addr));
}

#define MMA16816(d, a, b) \
    asm volatile( \
        "mma.sync.aligned.m16n8k16.row.col.f32.f16.f16.f32 " \
        "{%0,%1,%2,%3}, {%4,%5,%6,%7}, {%8,%9}, {%0,%1,%2,%3};" \
        : "+f"((d)[0]), "+f"((d)[1]), "+f"((d)[2]), "+f"((d)[3]) \
        : "r"((a)[0]), "r"((a)[1]), "r"((a)[2]), "r"((a)[3]), \
          "r"((b)[0]), "r"((b)[1]))

#define CP16(dst_u32, src_ptr) \
    asm volatile("cp.async.cg.shared.global [%0], [%1], 16;" :: "r"(dst_u32), "l"(src_ptr))
#define CP_COMMIT() asm volatile("cp.async.commit_group;" ::: "memory")
#define CP_WAIT1()  asm volatile("cp.async.wait_group 1;" ::: "memory")
#define CP_WAIT0()  asm volatile("cp.async.wait_group 0;" ::: "memory")

// ============================================================
// Kernel 0: fp32 -> fp16 conversion. x: hi+lo; wq/wp: hi only.
// ============================================================
#define NX4  (BATCH * NSEQ * CDIM / 4)
#define NWQ4 (CDIM * 3 * CDIM / 4)
#define NWP4 (CDIM * CDIM / 4)
#define NCONV_BLOCKS ((NX4 + NWQ4 + NWP4 + 255) / 256)

__global__ __launch_bounds__(256) void convert_kernel(
    const float* __restrict__ x, const float* __restrict__ wq,
    const float* __restrict__ wp)
{
    int i = blockIdx.x * 256 + threadIdx.x;
    if (i < NX4) {
        float4 f = *(const float4*)(x + (size_t)i * 4);
        uint2 h, l;
        split2(f.x, f.y, h.x, l.x);
        split2(f.z, f.w, h.y, l.y);
        *(uint2*)(g_xh + (size_t)i * 4) = h;
        *(uint2*)(g_xl + (size_t)i * 4) = l;
    } else if (i < NX4 + NWQ4) {
        int off = i - NX4;
        float4 f = *(const float4*)(wq + (size_t)off * 4);
        uint2 h;
        h.x = pack_h2(f.x, f.y);
        h.y = pack_h2(f.z, f.w);
        *(uint2*)(g_wqh + (size_t)off * 4) = h;
    } else if (i < NX4 + NWQ4 + NWP4) {
        int off = i - NX4 - NWQ4;
        float4 f = *(const float4*)(wp + (size_t)off * 4);
        uint2 h;
        h.x = pack_h2(f.x, f.y);
        h.y = pack_h2(f.z, f.w);
        *(uint2*)(g_wph + (size_t)off * 4) = h;
    }
}

// ============================================================
// Shared GEMM compute: 128x128 CTA, 8 warps (4m x 2n), K-step 32,
// 2-chain (A hi/lo x B hi), cp.async double-buffered.
// ============================================================
#define GAH 0
#define GAL 10240
#define GBH 20480
#define GBUF 28672
#define GEMM_SMEM (2 * GBUF)

__device__ __forceinline__ void gemm_compute_step(
    float acc[2][8][4], uint32_t bb, int wm, int wn, int lane)
{
    const int l8 = lane & 7, l16 = lane & 15;
#pragma unroll
    for (int s = 0; s < 2; s++) {
        uint32_t ah[2][4], al[2][4];
        uint32_t arow = (uint32_t)((wm + l8 + 8 * ((lane >> 3) & 1)) * 80 +
                                   (2 * s + (lane >> 4)) * 16);
        ldsm_x4(ah[0], bb + GAH + arow);
        ldsm_x4(ah[1], bb + GAH + arow + 16 * 80);
        ldsm_x4(al[0], bb + GAL + arow);
        ldsm_x4(al[1], bb + GAL + arow + 16 * 80);

        uint32_t bf[8][2];
        const uint32_t brow = (uint32_t)((s * 16 + l16) * 256);
#pragma unroll
        for (int j = 0; j < 8; j++) {
            int jj = (wn >> 3) + j;
            ldsm_x2_t(bf[j][0], bf[j][1],
                      bb + GBH + brow + (uint32_t)(((jj ^ l8) << 4)));
        }
#pragma unroll
        for (int j = 0; j < 8; j++) {
            MMA16816(acc[0][j], ah[0], bf[j]);
            MMA16816(acc[1][j], ah[1], bf[j]);
        }
#pragma unroll
        for (int j = 0; j < 8; j++) {
            MMA16816(acc[0][j], al[0], bf[j]);
            MMA16816(acc[1][j], al[1], bf[j]);
        }
    }
}

// ============================================================
// Kernel 1: QKV GEMM -> Q(x0.125)/K/V hi [BH,N,64]
// ============================================================
__global__ __launch_bounds__(256, 2) void qkv_tc_kernel()
{
    extern __shared__ char sm[];
    const uint32_t sb = smem_u32(sm);
    const int tid = threadIdx.x, warp = tid >> 5, lane = tid & 31;
    const int wm = (warp & 3) * 32, wn = (warp >> 2) * 64;
    const int row0 = blockIdx.y * 128, col0 = blockIdx.x * 128;

    float acc[2][8][4];
#pragma unroll
    for (int mi = 0; mi < 2; mi++)
#pragma unroll
        for (int j = 0; j < 8; j++)
#pragma unroll
            for (int i = 0; i < 4; i++) acc[mi][j][i] = 0.0f;

    auto stage = [&](int buf, int k0) {
        uint32_t base = sb + buf * GBUF;
#pragma unroll
        for (int it = 0; it < 2; it++) {
            int idx = tid + it * 256;
            int row = idx >> 2, ch = idx & 3;
            size_t g = (size_t)(row0 + row) * CDIM + k0 + ch * 8;
            CP16(base + GAH + row * 80 + ch * 16, g_xh + g);
            CP16(base + GAL + row * 80 + ch * 16, g_xl + g);
        }
#pragma unroll
        for (int it = 0; it < 2; it++) {
            int idx = tid + it * 256;
            int row = idx >> 4, ch = idx & 15;
            size_t g = (size_t)(k0 + row) * (3 * CDIM) + col0 + ch * 8;
            uint32_t sw = (uint32_t)(row * 256 + ((ch ^ (row & 7)) << 4));
            CP16(base + GBH + sw, g_wqh + g);
        }
    };

    stage(0, 0);
    CP_COMMIT();

    const int NIT = CDIM / 32;
    for (int kt = 0; kt < NIT; kt++) {
        if (kt < NIT - 1) {
            stage((kt + 1) & 1, (kt + 1) * 32);
            CP_COMMIT();
            CP_WAIT1();
        } else {
            CP_WAIT0();
        }
        __syncthreads();
        gemm_compute_step(acc, sb + (uint32_t)((kt & 1) * GBUF), wm, wn, lane);
        __syncthreads();
    }

    // epilogue: hi only
    const int gid = lane >> 2, tq = lane & 3;
#pragma unroll
    for (int j = 0; j < 8; j++) {
        int col = col0 + wn + j * 8 + tq * 2;
        int which = col / CDIM, cm = col % CDIM;
        int h = cm / HD, d = cm % HD;
        float sc = (which == 0) ? QK_SCALE : 1.0f;
        __half* hp = (which == 0) ? g_qh : (which == 1) ? g_kh : g_vh;
#pragma unroll
        for (int mi = 0; mi < 2; mi++) {
#pragma unroll
            for (int rg = 0; rg < 2; rg++) {
                int m = row0 + wm + mi * 16 + gid + rg * 8;
                int b = m >> 12, n = m & (NSEQ - 1);
                size_t base = (((size_t)(b * NH + h)) * NSEQ + n) * HD + d;
                *(uint32_t*)&hp[base] =
                    pack_h2(acc[mi][j][rg * 2] * sc, acc[mi][j][rg * 2 + 1] * sc);
            }
        }
    }
}

// ============================================================
// Kernel 2: flash attention, single-chain fp16, 3-way split-KV.
// Each CTA covers keys [kb0*64, kb1*64); writes partial O + (m,l).
// ============================================================
#define STG 16384
#define SKH 0
#define SVH 8192
#define ATT_SMEM (2 * STG)

__global__ __launch_bounds__(256, 2) void attn_mma_kernel()
{
    extern __shared__ char smem[];
    const uint32_t sbase = smem_u32(smem);

    const int tid = threadIdx.x;
    const int warp = tid >> 5, lane = tid & 31;
    const int bh = blockIdx.y;
    const int z = blockIdx.z;
    const int r0 = blockIdx.x * 128;
    const int R = r0 + warp * 16;

    const int l8 = lane & 7;
    const int hseg = (lane >> 3) & 1;
    const int rA = R + (lane >> 2);
    const int kcol = (lane & 3) * 2;

    const int kb0 = (z * NKB) / NSPLIT;
    const int kb1 = ((z + 1) * NKB) / NSPLIT;
    const int nb = kb1 - kb0;

    const __half* Qh = g_qh + (size_t)bh * NSEQ * HD;
    const __half* Kh = g_kh + (size_t)bh * NSEQ * HD;
    const __half* Vh = g_vh + (size_t)bh * NSEQ * HD;

    // Q hi a-fragments in registers
    uint32_t qah[4][4];
#pragma unroll
    for (int s = 0; s < 4; s++) {
        qah[s][0] = *(const uint32_t*)&Qh[(size_t)rA * HD + s * 16 + kcol];
        qah[s][1] = *(const uint32_t*)&Qh[(size_t)(rA + 8) * HD + s * 16 + kcol];
        qah[s][2] = *(const uint32_t*)&Qh[(size_t)rA * HD + s * 16 + 8 + kcol];
        qah[s][3] = *(const uint32_t*)&Qh[(size_t)(rA + 8) * HD + s * 16 + 8 + kcol];
    }

    float of[8][4];
#pragma unroll
    for (int j = 0; j < 8; j++)
#pragma unroll
        for (int i = 0; i < 4; i++) of[j][i] = 0.0f;
    float mA = -1e30f, mB = -1e30f, lA = 0.0f, lB = 0.0f;

    const uint32_t krow = (uint32_t)(l8 * 128);

    auto stage = [&](int st, int kr0) {
#pragma unroll
        for (int it = 0; it < 2; it++) {
            int idx = tid + it * 256;
            int row = idx >> 3, ch = idx & 7;
            uint32_t sw = (uint32_t)(st * STG + row * 128 + ((ch ^ (row & 7)) << 4));
            size_t g = (size_t)(kr0 + row) * HD + ch * 8;
            CP16(sbase + sw + SKH, Kh + g);
            CP16(sbase + sw + SVH, Vh + g);
        }
    };

    stage(0, kb0 * 64);
    CP_COMMIT();

    for (int it = 0; it < nb; it++) {
        if (it < nb - 1) {
            stage((it + 1) & 1, (kb0 + it + 1) * 64);
            CP_COMMIT();
            CP_WAIT1();
        } else {
            CP_WAIT0();
        }
        __syncthreads();
        const uint32_t stb = sbase + (uint32_t)((it & 1) * STG);

        // ---- S = Q K^T (single chain) ----
        float sf[8][4];
#pragma unroll
        for (int j = 0; j < 8; j++)
#pragma unroll
            for (int i = 0; i < 4; i++) sf[j][i] = 0.0f;

#pragma unroll
        for (int s = 0; s < 4; s++) {
            uint32_t chsw = (uint32_t)((((2 * s + hseg) ^ l8) << 4));
#pragma unroll
            for (int jc = 0; jc < 8; jc += 4) {
                uint32_t kbf[4][2];
#pragma unroll
                for (int j = 0; j < 4; j++)
                    ldsm_x2(kbf[j][0], kbf[j][1],
                            stb + SKH + (uint32_t)((jc + j) * 1024) + krow + chsw);
#pragma unroll
                for (int j = 0; j < 4; j++) MMA16816(sf[jc + j], qah[s], kbf[j]);
            }
        }

        // ---- online softmax ----
        float mxA = sf[0][0], mxB = sf[0][2];
#pragma unroll
        for (int j = 0; j < 8; j++) {
            mxA = fmaxf(mxA, fmaxf(sf[j][0], sf[j][1]));
            mxB = fmaxf(mxB, fmaxf(sf[j][2], sf[j][3]));
        }
        mxA = fmaxf(mxA, __shfl_xor_sync(0xffffffffu, mxA, 1));
        mxA = fmaxf(mxA, __shfl_xor_sync(0xffffffffu, mxA, 2));
        mxB = fmaxf(mxB, __shfl_xor_sync(0xffffffffu, mxB, 1));
        mxB = fmaxf(mxB, __shfl_xor_sync(0xffffffffu, mxB, 2));

        float mnA = fmaxf(mA, mxA), mnB = fmaxf(mB, mxB);
        float corrA = ex2f_fast((mA - mnA) * L2E);
        float corrB = ex2f_fast((mB - mnB) * L2E);
        mA = mnA; mB = mnB;
        const float nlA = mnA * L2E, nlB = mnB * L2E;

        float sumA = 0.0f, sumB = 0.0f;
#pragma unroll
        for (int j = 0; j < 8; j++) {
            float p0 = ex2f_fast(fmaf(sf[j][0], L2E, -nlA));
            float p1 = ex2f_fast(fmaf(sf[j][1], L2E, -nlA));
            float p2 = ex2f_fast(fmaf(sf[j][2], L2E, -nlB));
            float p3 = ex2f_fast(fmaf(sf[j][3], L2E, -nlB));
            sumA += p0 + p1; sumB += p2 + p3;
            sf[j][0] = p0; sf[j][1] = p1; sf[j][2] = p2; sf[j][3] = p3;
        }
        lA = lA * corrA + sumA;
        lB = lB * corrB + sumB;

#pragma unroll
        for (int j = 0; j < 8; j++) {
            of[j][0] *= corrA; of[j][1] *= corrA;
            of[j][2] *= corrB; of[j][3] *= corrB;
        }

        // ---- O += P V (single chain) ----
#pragma unroll
        for (int s = 0; s < 4; s++) {
            uint32_t pah[4];
            pah[0] = pack_h2(sf[2 * s][0], sf[2 * s][1]);
            pah[1] = pack_h2(sf[2 * s][2], sf[2 * s][3]);
            pah[2] = pack_h2(sf[2 * s + 1][0], sf[2 * s + 1][1]);
            pah[3] = pack_h2(sf[2 * s + 1][2], sf[2 * s + 1][3]);

            uint32_t vrow = (uint32_t)((16 * s + 8 * hseg + l8) * 128);
#pragma unroll
            for (int jc = 0; jc < 8; jc += 4) {
                uint32_t vbf[4][2];
#pragma unroll
                for (int j = 0; j < 4; j++)
                    ldsm_x2_t(vbf[j][0], vbf[j][1],
                              stb + SVH + vrow + (uint32_t)((((jc + j) ^ l8) << 4)));
#pragma unroll
                for (int j = 0; j < 4; j++) MMA16816(of[jc + j], pah, vbf[j]);
            }
        }
        __syncthreads();
    }

    // ---- epilogue: write PARTIAL O (un-normalized) + (m, l) ----
    lA += __shfl_xor_sync(0xffffffffu, lA, 1);
    lA += __shfl_xor_sync(0xffffffffu, lA, 2);
    lB += __shfl_xor_sync(0xffffffffu, lB, 1);
    lB += __shfl_xor_sync(0xffffffffu, lB, 2);

    float* opart = g_opart + (size_t)z * BH_TOT * NSEQ * HD + (size_t)bh * NSEQ * HD;
#pragma unroll
    for (int j = 0; j < 8; j++) {
        int c = j * 8 + kcol;
        float2 oa = make_float2(of[j][0], of[j][1]);
        float2 ob = make_float2(of[j][2], of[j][3]);
        *(float2*)&opart[(size_t)rA * HD + c] = oa;
        *(float2*)&opart[(size_t)(rA + 8) * HD + c] = ob;
    }
    if ((lane & 3) == 0) {
        size_t mlbase = (size_t)z * BH_TOT * NSEQ + (size_t)bh * NSEQ;
        g_ml[mlbase + rA] = make_float2(mA, lA);
        g_ml[mlbase + rA + 8] = make_float2(mB, lB);
    }
}

// ============================================================
// Kernel 2b: combine split-KV partials -> g_oh/g_ol [B,N,C]
// 16 threads per row, 4 d-values per thread.
// ============================================================
#define NCOMB_BLOCKS (BH_TOT * NSEQ * 16 / 256)

__global__ __launch_bounds__(256) void combine_kernel()
{
    int idx = blockIdx.x * 256 + threadIdx.x;
    int row = idx >> 4;                 // bh*NSEQ + n
    int dq = (idx & 15) * 4;

    float2 ml0 = g_ml[row];
    float2 ml1 = g_ml[BH_TOT * NSEQ + row];
    float2 ml2 = g_ml[2 * BH_TOT * NSEQ + row];
    float ms = fmaxf(ml0.x, fmaxf(ml1.x, ml2.x));
    float w0 = ex2f_fast((ml0.x - ms) * L2E);
    float w1 = ex2f_fast((ml1.x - ms) * L2E);
    float w2 = ex2f_fast((ml2.x - ms) * L2E);
    float inv = 1.0f / (ml0.y * w0 + ml1.y * w1 + ml2.y * w2);

    size_t pbase = (size_t)row * HD + dq;
    float4 o0 = *(const float4*)&g_opart[pbase];
    float4 o1 = *(const float4*)&g_opart[(size_t)BH_TOT * NSEQ * HD + pbase];
    float4 o2 = *(const float4*)&g_opart[2 * (size_t)BH_TOT * NSEQ * HD + pbase];

    float4 o;
    o.x = (o0.x * w0 + o1.x * w1 + o2.x * w2) * inv;
    o.y = (o0.y * w0 + o1.y * w1 + o2.y * w2) * inv;
    o.z = (o0.z * w0 + o1.z * w1 + o2.z * w2) * inv;
    o.w = (o0.w * w0 + o1.w * w1 + o2.w * w2) * inv;

    int bh = row >> 12;                 // row / NSEQ
    int n = row & (NSEQ - 1);
    int b = bh / NH, h = bh % NH;
    size_t obase = ((size_t)b * NSEQ + n) * CDIM + h * HD + dq;

    uint32_t h0, l0, h1, l1;
    split2(o.x, o.y, h0, l0);
    split2(o.z, o.w, h1, l1);
    uint2 uh; uh.x = h0; uh.y = h1;
    uint2 ul; ul.x = l0; ul.y = l1;
    *(uint2*)&g_oh[obase] = uh;
    *(uint2*)&g_ol[obase] = ul;
}

// ============================================================
// Kernel 3: proj GEMM (2-chain) + bias -> out fp32
// ============================================================
__global__ __launch_bounds__(256, 2) void proj_tc_kernel(
    const float* __restrict__ bias, float* __restrict__ out)
{
    extern __shared__ char sm[];
    const uint32_t sb = smem_u32(sm);
    const int tid = threadIdx.x, warp = tid >> 5, lane = tid & 31;
    const int wm = (warp & 3) * 32, wn = (warp >> 2) * 64;
    const int row0 = blockIdx.y * 128, col0 = blockIdx.x * 128;

    float acc[2][8][4];
#pragma unroll
    for (int mi = 0; mi < 2; mi++)
#pragma unroll
        for (int j = 0; j < 8; j++)
#pragma unroll
            for (int i = 0; i < 4; i++) acc[mi][j][i] = 0.0f;

    auto stage = [&](int buf, int k0) {
        uint32_t base = sb + buf * GBUF;
#pragma unroll
        for (int it = 0; it < 2; it++) {
            int idx = tid + it * 256;
            int row = idx >> 2, ch = idx & 3;
            size_t g = (size_t)(row0 + row) * CDIM + k0 + ch * 8;
            CP16(base + GAH + row * 80 + ch * 16, g_oh + g);
            CP16(base + GAL + row * 80 + ch * 16, g_ol + g);
        }
#pragma unroll
        for (int it = 0; it < 2; it++) {
            int idx = tid + it * 256;
            int row = idx >> 4, ch = idx & 15;
            size_t g = (size_t)(k0 + row) * CDIM + col0 + ch * 8;
            uint32_t sw = (uint32_t)(row * 256 + ((ch ^ (row & 7)) << 4));
            CP16(base + GBH + sw, g_wph + g);
        }
    };

    stage(0, 0);
    CP_COMMIT();

    const int NIT = CDIM / 32;
    for (int kt = 0; kt < NIT; kt++) {
        if (kt < NIT - 1) {
            stage((kt + 1) & 1, (kt + 1) * 32);
            CP_COMMIT();
            CP_WAIT1();
        } else {
            CP_WAIT0();
        }
        __syncthreads();
        gemm_compute_step(acc, sb + (uint32_t)((kt & 1) * GBUF), wm, wn, lane);
        __syncthreads();
    }

    const int gid = lane >> 2, tq = lane & 3;
#pragma unroll
    for (int j = 0; j < 8; j++) {
        int col = col0 + wn + j * 8 + tq * 2;
        float2 bv = *(const float2*)&bias[col];
#pragma unroll
        for (int mi = 0; mi < 2; mi++) {
#pragma unroll
            for (int rg = 0; rg < 2; rg++) {
                int m = row0 + wm + mi * 16 + gid + rg * 8;
                float2 o = make_float2(acc[mi][j][rg * 2] + bv.x,
                                       acc[mi][j][rg * 2 + 1] + bv.y);
                *(float2*)&out[(size_t)m * CDIM + col] = o;
            }
        }
    }
}

// ============================================================
extern "C" void kernel_launch(void* const* d_in, const int* in_sizes, int n_in,
                              void* d_out, int out_size)
{
    const float* x      = (const float*)d_in[0];
    const float* w_qkv  = (const float*)d_in[1];
    const float* w_proj = (const float*)d_in[2];
    const float* b_proj = (const float*)d_in[3];
    float* out = (float*)d_out;

    (void)in_sizes; (void)n_in; (void)out_size;

    cudaFuncSetAttribute(qkv_tc_kernel,
                         cudaFuncAttributeMaxDynamicSharedMemorySize, GEMM_SMEM);
    cudaFuncSetAttribute(attn_mma_kernel,
                         cudaFuncAttributeMaxDynamicSharedMemorySize, ATT_SMEM);
    cudaFuncSetAttribute(proj_tc_kernel,
                         cudaFuncAttributeMaxDynamicSharedMemorySize, GEMM_SMEM);

    convert_kernel<<<NCONV_BLOCKS, 256>>>(x, w_qkv, w_proj);

    qkv_tc_kernel<<<dim3(3 * CDIM / 128, (BATCH * NSEQ) / 128), 256, GEMM_SMEM>>>();

    attn_mma_kernel<<<dim3(NSEQ / 128, BH_TOT, NSPLIT), 256, ATT_SMEM>>>();

    combine_kernel<<<NCOMB_BLOCKS, 256>>>();

    proj_tc_kernel<<<dim3(CDIM / 128, (BATCH * NSEQ) / 128), 256, GEMM_SMEM>>>(b_proj, out);
}

// round 12
// speedup vs baseline: 8.0225x; 1.0401x over previous
#include <cuda_runtime.h>
#include <cuda_fp16.h>
#include <cstdint>

#define BATCH 2
#define NSEQ  4096
#define CDIM  384
#define NH    6
#define HD    64
#define BH_TOT (BATCH * NH)
#define QK_SCALE 0.125f
#define L2E 1.4426950408889634f
#define NSPLIT 3
#define NKB (NSEQ / 64)

// ================= scratch (allocation-free: __device__ globals) =============
__device__ __half g_xh[BATCH * NSEQ * CDIM];  // x as fp16 hi/lo
__device__ __half g_xl[BATCH * NSEQ * CDIM];
__device__ __half g_wqh[CDIM * 3 * CDIM];     // w_qkv hi only
__device__ __half g_wph[CDIM * CDIM];         // w_proj hi only

__device__ __half g_qh[BH_TOT * NSEQ * HD];   // [BH,N,64] pre-scaled, hi only
__device__ __half g_kh[BH_TOT * NSEQ * HD];   // K hi only
__device__ __half g_vh[BH_TOT * NSEQ * HD];   // V hi only

__device__ float  g_opart[NSPLIT * BH_TOT * NSEQ * HD];  // split-KV partial O
__device__ float2 g_ml[NSPLIT * BH_TOT * NSEQ];          // per-row (m, l)

__device__ __half g_oh[BATCH * NSEQ * CDIM];  // attention out hi/lo
__device__ __half g_ol[BATCH * NSEQ * CDIM];

__device__ __forceinline__ float ex2f_fast(float x) {
    float y;
    asm("ex2.approx.f32 %0, %1;" : "=f"(y) : "f"(x));
    return y;
}

// fp16 split: hi pair + exact residual pair
__device__ __forceinline__ void split2(float a, float b, uint32_t& hi, uint32_t& lo) {
    __half2 h = __floats2half2_rn(a, b);
    hi = *reinterpret_cast<uint32_t*>(&h);
    float2 hf = __half22float2(h);
    __half2 l = __floats2half2_rn(a - hf.x, b - hf.y);
    lo = *reinterpret_cast<uint32_t*>(&l);
}

__device__ __forceinline__ uint32_t pack_h2(float a, float b) {
    __half2 h = __floats2half2_rn(a, b);
    return *reinterpret_cast<uint32_t*>(&h);
}

__device__ __forceinline__ uint32_t smem_u32(const void* p) {
    uint32_t a;
    asm("{ .reg .u64 t; cvta.to.shared.u64 t, %1; cvt.u32.u64 %0, t; }" : "=r"(a) : "l"(p));
    return a;
}

__device__ __forceinline__ void ldsm_x4(uint32_t* r, uint32_t addr) {
    asm volatile("ldmatrix.sync.aligned.m8n8.x4.shared.b16 {%0,%1,%2,%3}, [%4];"
                 : "=r"(r[0]), "=r"(r[1]), "=r"(r[2]), "=r"(r[3]) : "r"(addr));
}
__device__ __forceinline__ void ldsm_x4_t(uint32_t* r, uint32_t addr) {
    asm volatile("ldmatrix.sync.aligned.m8n8.x4.trans.shared.b16 {%0,%1,%2,%3}, [%4];"
                 : "=r"(r[0]), "=r"(r[1]), "=r"(r[2]), "=r"(r[3]) : "r"(addr));
}

#define MMA16816(d, a, b) \
    asm volatile( \
        "mma.sync.aligned.m16n8k16.row.col.f32.f16.f16.f32 " \
        "{%0,%1,%2,%3}, {%4,%5,%6,%7}, {%8,%9}, {%0,%1,%2,%3};" \
        : "+f"((d)[0]), "+f"((d)[1]), "+f"((d)[2]), "+f"((d)[3]) \
        : "r"((a)[0]), "r"((a)[1]), "r"((a)[2]), "r"((a)[3]), \
          "r"((b)[0]), "r"((b)[1]))

#define CP16(dst_u32, src_ptr) \
    asm volatile("cp.async.cg.shared.global [%0], [%1], 16;" :: "r"(dst_u32), "l"(src_ptr))
#define CP_COMMIT() asm volatile("cp.async.commit_group;" ::: "memory")
#define CP_WAIT1()  asm volatile("cp.async.wait_group 1;" ::: "memory")
#define CP_WAIT0()  asm volatile("cp.async.wait_group 0;" ::: "memory")

// ============================================================
// Kernel 0: fp32 -> fp16 conversion. x: hi+lo; wq/wp: hi only.
// ============================================================
#define NX4  (BATCH * NSEQ * CDIM / 4)
#define NWQ4 (CDIM * 3 * CDIM / 4)
#define NWP4 (CDIM * CDIM / 4)
#define NCONV_BLOCKS ((NX4 + NWQ4 + NWP4 + 255) / 256)

__global__ __launch_bounds__(256) void convert_kernel(
    const float* __restrict__ x, const float* __restrict__ wq,
    const float* __restrict__ wp)
{
    int i = blockIdx.x * 256 + threadIdx.x;
    if (i < NX4) {
        float4 f = *(const float4*)(x + (size_t)i * 4);
        uint2 h, l;
        split2(f.x, f.y, h.x, l.x);
        split2(f.z, f.w, h.y, l.y);
        *(uint2*)(g_xh + (size_t)i * 4) = h;
        *(uint2*)(g_xl + (size_t)i * 4) = l;
    } else if (i < NX4 + NWQ4) {
        int off = i - NX4;
        float4 f = *(const float4*)(wq + (size_t)off * 4);
        uint2 h;
        h.x = pack_h2(f.x, f.y);
        h.y = pack_h2(f.z, f.w);
        *(uint2*)(g_wqh + (size_t)off * 4) = h;
    } else if (i < NX4 + NWQ4 + NWP4) {
        int off = i - NX4 - NWQ4;
        float4 f = *(const float4*)(wp + (size_t)off * 4);
        uint2 h;
        h.x = pack_h2(f.x, f.y);
        h.y = pack_h2(f.z, f.w);
        *(uint2*)(g_wph + (size_t)off * 4) = h;
    }
}

// ============================================================
// Shared GEMM compute: 128x128 CTA, 8 warps (4m x 2n), K-step 32,
// 2-chain (A hi/lo x B hi), cp.async double-buffered, ldsm.x4.
// ============================================================
#define GAH 0
#define GAL 10240
#define GBH 20480
#define GBUF 28672
#define GEMM_SMEM (2 * GBUF)

__device__ __forceinline__ void gemm_compute_step(
    float acc[2][8][4], uint32_t bb, int wm, int wn, int lane)
{
    const int l8 = lane & 7, l16 = lane & 15;
    const int jsel = lane >> 4;
#pragma unroll
    for (int s = 0; s < 2; s++) {
        uint32_t ah[2][4], al[2][4];
        uint32_t arow = (uint32_t)((wm + l8 + 8 * ((lane >> 3) & 1)) * 80 +
                                   (2 * s + (lane >> 4)) * 16);
        ldsm_x4(ah[0], bb + GAH + arow);
        ldsm_x4(ah[1], bb + GAH + arow + 16 * 80);
        ldsm_x4(al[0], bb + GAL + arow);
        ldsm_x4(al[1], bb + GAL + arow + 16 * 80);

        uint32_t bf[8][2];
        const uint32_t brow = (uint32_t)((s * 16 + l16) * 256);
#pragma unroll
        for (int j = 0; j < 8; j += 2) {
            int jj = (wn >> 3) + j + jsel;
            uint32_t r[4];
            ldsm_x4_t(r, bb + GBH + brow + (uint32_t)(((jj ^ l8) << 4)));
            bf[j][0] = r[0]; bf[j][1] = r[1];
            bf[j + 1][0] = r[2]; bf[j + 1][1] = r[3];
        }
#pragma unroll
        for (int j = 0; j < 8; j++) {
            MMA16816(acc[0][j], ah[0], bf[j]);
            MMA16816(acc[1][j], ah[1], bf[j]);
        }
#pragma unroll
        for (int j = 0; j < 8; j++) {
            MMA16816(acc[0][j], al[0], bf[j]);
            MMA16816(acc[1][j], al[1], bf[j]);
        }
    }
}

// ============================================================
// Kernel 1: QKV GEMM -> Q(x0.125)/K/V hi [BH,N,64]
// ============================================================
__global__ __launch_bounds__(256, 2) void qkv_tc_kernel()
{
    extern __shared__ char sm[];
    const uint32_t sb = smem_u32(sm);
    const int tid = threadIdx.x, warp = tid >> 5, lane = tid & 31;
    const int wm = (warp & 3) * 32, wn = (warp >> 2) * 64;
    const int row0 = blockIdx.y * 128, col0 = blockIdx.x * 128;

    float acc[2][8][4];
#pragma unroll
    for (int mi = 0; mi < 2; mi++)
#pragma unroll
        for (int j = 0; j < 8; j++)
#pragma unroll
            for (int i = 0; i < 4; i++) acc[mi][j][i] = 0.0f;

    auto stage = [&](int buf, int k0) {
        uint32_t base = sb + buf * GBUF;
#pragma unroll
        for (int it = 0; it < 2; it++) {
            int idx = tid + it * 256;
            int row = idx >> 2, ch = idx & 3;
            size_t g = (size_t)(row0 + row) * CDIM + k0 + ch * 8;
            CP16(base + GAH + row * 80 + ch * 16, g_xh + g);
            CP16(base + GAL + row * 80 + ch * 16, g_xl + g);
        }
#pragma unroll
        for (int it = 0; it < 2; it++) {
            int idx = tid + it * 256;
            int row = idx >> 4, ch = idx & 15;
            size_t g = (size_t)(k0 + row) * (3 * CDIM) + col0 + ch * 8;
            uint32_t sw = (uint32_t)(row * 256 + ((ch ^ (row & 7)) << 4));
            CP16(base + GBH + sw, g_wqh + g);
        }
    };

    stage(0, 0);
    CP_COMMIT();

    const int NIT = CDIM / 32;
    for (int kt = 0; kt < NIT; kt++) {
        if (kt < NIT - 1) {
            stage((kt + 1) & 1, (kt + 1) * 32);
            CP_COMMIT();
            CP_WAIT1();
        } else {
            CP_WAIT0();
        }
        __syncthreads();
        gemm_compute_step(acc, sb + (uint32_t)((kt & 1) * GBUF), wm, wn, lane);
        __syncthreads();
    }

    // epilogue: hi only
    const int gid = lane >> 2, tq = lane & 3;
#pragma unroll
    for (int j = 0; j < 8; j++) {
        int col = col0 + wn + j * 8 + tq * 2;
        int which = col / CDIM, cm = col % CDIM;
        int h = cm / HD, d = cm % HD;
        float sc = (which == 0) ? QK_SCALE : 1.0f;
        __half* hp = (which == 0) ? g_qh : (which == 1) ? g_kh : g_vh;
#pragma unroll
        for (int mi = 0; mi < 2; mi++) {
#pragma unroll
            for (int rg = 0; rg < 2; rg++) {
                int m = row0 + wm + mi * 16 + gid + rg * 8;
                int b = m >> 12, n = m & (NSEQ - 1);
                size_t base = (((size_t)(b * NH + h)) * NSEQ + n) * HD + d;
                *(uint32_t*)&hp[base] =
                    pack_h2(acc[mi][j][rg * 2] * sc, acc[mi][j][rg * 2 + 1] * sc);
            }
        }
    }
}

// ============================================================
// Kernel 2: flash attention, single-chain fp16, 3-way split-KV,
// ldsm.x4 fragment loads.
// ============================================================
#define STG 16384
#define SKH 0
#define SVH 8192
#define ATT_SMEM (2 * STG)

__global__ __launch_bounds__(256, 2) void attn_mma_kernel()
{
    extern __shared__ char smem[];
    const uint32_t sbase = smem_u32(smem);

    const int tid = threadIdx.x;
    const int warp = tid >> 5, lane = tid & 31;
    const int bh = blockIdx.y;
    const int z = blockIdx.z;
    const int r0 = blockIdx.x * 128;
    const int R = r0 + warp * 16;

    const int l8 = lane & 7;
    const int hseg = (lane >> 3) & 1;
    const int jsel = lane >> 4;
    const int rA = R + (lane >> 2);
    const int kcol = (lane & 3) * 2;

    const int kb0 = (z * NKB) / NSPLIT;
    const int kb1 = ((z + 1) * NKB) / NSPLIT;
    const int nb = kb1 - kb0;

    const __half* Qh = g_qh + (size_t)bh * NSEQ * HD;
    const __half* Kh = g_kh + (size_t)bh * NSEQ * HD;
    const __half* Vh = g_vh + (size_t)bh * NSEQ * HD;

    // Q hi a-fragments in registers
    uint32_t qah[4][4];
#pragma unroll
    for (int s = 0; s < 4; s++) {
        qah[s][0] = *(const uint32_t*)&Qh[(size_t)rA * HD + s * 16 + kcol];
        qah[s][1] = *(const uint32_t*)&Qh[(size_t)(rA + 8) * HD + s * 16 + kcol];
        qah[s][2] = *(const uint32_t*)&Qh[(size_t)rA * HD + s * 16 + 8 + kcol];
        qah[s][3] = *(const uint32_t*)&Qh[(size_t)(rA + 8) * HD + s * 16 + 8 + kcol];
    }

    float of[8][4];
#pragma unroll
    for (int j = 0; j < 8; j++)
#pragma unroll
        for (int i = 0; i < 4; i++) of[j][i] = 0.0f;
    float mA = -1e30f, mB = -1e30f, lA = 0.0f, lB = 0.0f;

    const uint32_t krow = (uint32_t)(l8 * 128);

    auto stage = [&](int st, int kr0) {
#pragma unroll
        for (int it = 0; it < 2; it++) {
            int idx = tid + it * 256;
            int row = idx >> 3, ch = idx & 7;
            uint32_t sw = (uint32_t)(st * STG + row * 128 + ((ch ^ (row & 7)) << 4));
            size_t g = (size_t)(kr0 + row) * HD + ch * 8;
            CP16(sbase + sw + SKH, Kh + g);
            CP16(sbase + sw + SVH, Vh + g);
        }
    };

    stage(0, kb0 * 64);
    CP_COMMIT();

    for (int it = 0; it < nb; it++) {
        if (it < nb - 1) {
            stage((it + 1) & 1, (kb0 + it + 1) * 64);
            CP_COMMIT();
            CP_WAIT1();
        } else {
            CP_WAIT0();
        }
        __syncthreads();
        const uint32_t stb = sbase + (uint32_t)((it & 1) * STG);

        // ---- S = Q K^T (single chain, ldsm.x4) ----
        float sf[8][4];
#pragma unroll
        for (int j = 0; j < 8; j++)
#pragma unroll
            for (int i = 0; i < 4; i++) sf[j][i] = 0.0f;

#pragma unroll
        for (int s = 0; s < 4; s++) {
            uint32_t chsw = (uint32_t)((((2 * s + hseg) ^ l8) << 4));
#pragma unroll
            for (int jc = 0; jc < 8; jc += 4) {
                uint32_t kbf[4][2];
#pragma unroll
                for (int jj = 0; jj < 4; jj += 2) {
                    uint32_t r[4];
                    ldsm_x4(r, stb + SKH + (uint32_t)((jc + jj + jsel) * 1024) + krow + chsw);
                    kbf[jj][0] = r[0]; kbf[jj][1] = r[1];
                    kbf[jj + 1][0] = r[2]; kbf[jj + 1][1] = r[3];
                }
#pragma unroll
                for (int j = 0; j < 4; j++) MMA16816(sf[jc + j], qah[s], kbf[j]);
            }
        }

        // ---- online softmax ----
        float mxA = sf[0][0], mxB = sf[0][2];
#pragma unroll
        for (int j = 0; j < 8; j++) {
            mxA = fmaxf(mxA, fmaxf(sf[j][0], sf[j][1]));
            mxB = fmaxf(mxB, fmaxf(sf[j][2], sf[j][3]));
        }
        mxA = fmaxf(mxA, __shfl_xor_sync(0xffffffffu, mxA, 1));
        mxA = fmaxf(mxA, __shfl_xor_sync(0xffffffffu, mxA, 2));
        mxB = fmaxf(mxB, __shfl_xor_sync(0xffffffffu, mxB, 1));
        mxB = fmaxf(mxB, __shfl_xor_sync(0xffffffffu, mxB, 2));

        float mnA = fmaxf(mA, mxA), mnB = fmaxf(mB, mxB);
        float corrA = ex2f_fast((mA - mnA) * L2E);
        float corrB = ex2f_fast((mB - mnB) * L2E);
        mA = mnA; mB = mnB;
        const float nlA = mnA * L2E, nlB = mnB * L2E;

        float sumA = 0.0f, sumB = 0.0f;
#pragma unroll
        for (int j = 0; j < 8; j++) {
            float p0 = ex2f_fast(fmaf(sf[j][0], L2E, -nlA));
            float p1 = ex2f_fast(fmaf(sf[j][1], L2E, -nlA));
            float p2 = ex2f_fast(fmaf(sf[j][2], L2E, -nlB));
            float p3 = ex2f_fast(fmaf(sf[j][3], L2E, -nlB));
            sumA += p0 + p1; sumB += p2 + p3;
            sf[j][0] = p0; sf[j][1] = p1; sf[j][2] = p2; sf[j][3] = p3;
        }
        lA = lA * corrA + sumA;
        lB = lB * corrB + sumB;

#pragma unroll
        for (int j = 0; j < 8; j++) {
            of[j][0] *= corrA; of[j][1] *= corrA;
            of[j][2] *= corrB; of[j][3] *= corrB;
        }

        // ---- O += P V (single chain, ldsm.x4.trans) ----
#pragma unroll
        for (int s = 0; s < 4; s++) {
            uint32_t pah[4];
            pah[0] = pack_h2(sf[2 * s][0], sf[2 * s][1]);
            pah[1] = pack_h2(sf[2 * s][2], sf[2 * s][3]);
            pah[2] = pack_h2(sf[2 * s + 1][0], sf[2 * s + 1][1]);
            pah[3] = pack_h2(sf[2 * s + 1][2], sf[2 * s + 1][3]);

            uint32_t vrow = (uint32_t)((16 * s + 8 * hseg + l8) * 128);
#pragma unroll
            for (int jc = 0; jc < 8; jc += 4) {
                uint32_t vbf[4][2];
#pragma unroll
                for (int jj = 0; jj < 4; jj += 2) {
                    uint32_t r[4];
                    ldsm_x4_t(r, stb + SVH + vrow +
                              (uint32_t)((((jc + jj + jsel) ^ l8) << 4)));
                    vbf[jj][0] = r[0]; vbf[jj][1] = r[1];
                    vbf[jj + 1][0] = r[2]; vbf[jj + 1][1] = r[3];
                }
#pragma unroll
                for (int j = 0; j < 4; j++) MMA16816(of[jc + j], pah, vbf[j]);
            }
        }
        __syncthreads();
    }

    // ---- epilogue: write PARTIAL O (un-normalized) + (m, l) ----
    lA += __shfl_xor_sync(0xffffffffu, lA, 1);
    lA += __shfl_xor_sync(0xffffffffu, lA, 2);
    lB += __shfl_xor_sync(0xffffffffu, lB, 1);
    lB += __shfl_xor_sync(0xffffffffu, lB, 2);

    float* opart = g_opart + (size_t)z * BH_TOT * NSEQ * HD + (size_t)bh * NSEQ * HD;
#pragma unroll
    for (int j = 0; j < 8; j++) {
        int c = j * 8 + kcol;
        float2 oa = make_float2(of[j][0], of[j][1]);
        float2 ob = make_float2(of[j][2], of[j][3]);
        *(float2*)&opart[(size_t)rA * HD + c] = oa;
        *(float2*)&opart[(size_t)(rA + 8) * HD + c] = ob;
    }
    if ((lane & 3) == 0) {
        size_t mlbase = (size_t)z * BH_TOT * NSEQ + (size_t)bh * NSEQ;
        g_ml[mlbase + rA] = make_float2(mA, lA);
        g_ml[mlbase + rA + 8] = make_float2(mB, lB);
    }
}

// ============================================================
// Kernel 2b: combine split-KV partials -> g_oh/g_ol [B,N,C]
// ============================================================
#define NCOMB_BLOCKS (BH_TOT * NSEQ * 16 / 256)

__global__ __launch_bounds__(256) void combine_kernel()
{
    int idx = blockIdx.x * 256 + threadIdx.x;
    int row = idx >> 4;                 // bh*NSEQ + n
    int dq = (idx & 15) * 4;

    float2 ml0 = g_ml[row];
    float2 ml1 = g_ml[BH_TOT * NSEQ + row];
    float2 ml2 = g_ml[2 * BH_TOT * NSEQ + row];
    float ms = fmaxf(ml0.x, fmaxf(ml1.x, ml2.x));
    float w0 = ex2f_fast((ml0.x - ms) * L2E);
    float w1 = ex2f_fast((ml1.x - ms) * L2E);
    float w2 = ex2f_fast((ml2.x - ms) * L2E);
    float inv = 1.0f / (ml0.y * w0 + ml1.y * w1 + ml2.y * w2);

    size_t pbase = (size_t)row * HD + dq;
    float4 o0 = *(const float4*)&g_opart[pbase];
    float4 o1 = *(const float4*)&g_opart[(size_t)BH_TOT * NSEQ * HD + pbase];
    float4 o2 = *(const float4*)&g_opart[2 * (size_t)BH_TOT * NSEQ * HD + pbase];

    float4 o;
    o.x = (o0.x * w0 + o1.x * w1 + o2.x * w2) * inv;
    o.y = (o0.y * w0 + o1.y * w1 + o2.y * w2) * inv;
    o.z = (o0.z * w0 + o1.z * w1 + o2.z * w2) * inv;
    o.w = (o0.w * w0 + o1.w * w1 + o2.w * w2) * inv;

    int bh = row >> 12;                 // row / NSEQ
    int n = row & (NSEQ - 1);
    int b = bh / NH, h = bh % NH;
    size_t obase = ((size_t)b * NSEQ + n) * CDIM + h * HD + dq;

    uint32_t h0, l0, h1, l1;
    split2(o.x, o.y, h0, l0);
    split2(o.z, o.w, h1, l1);
    uint2 uh; uh.x = h0; uh.y = h1;
    uint2 ul; ul.x = l0; ul.y = l1;
    *(uint2*)&g_oh[obase] = uh;
    *(uint2*)&g_ol[obase] = ul;
}

// ============================================================
// Kernel 3: proj GEMM (2-chain) + bias -> out fp32
// ============================================================
__global__ __launch_bounds__(256, 2) void proj_tc_kernel(
    const float* __restrict__ bias, float* __restrict__ out)
{
    extern __shared__ char sm[];
    const uint32_t sb = smem_u32(sm);
    const int tid = threadIdx.x, warp = tid >> 5, lane = tid & 31;
    const int wm = (warp & 3) * 32, wn = (warp >> 2) * 64;
    const int row0 = blockIdx.y * 128, col0 = blockIdx.x * 128;

    float acc[2][8][4];
#pragma unroll
    for (int mi = 0; mi < 2; mi++)
#pragma unroll
        for (int j = 0; j < 8; j++)
#pragma unroll
            for (int i = 0; i < 4; i++) acc[mi][j][i] = 0.0f;

    auto stage = [&](int buf, int k0) {
        uint32_t base = sb + buf * GBUF;
#pragma unroll
        for (int it = 0; it < 2; it++) {
            int idx = tid + it * 256;
            int row = idx >> 2, ch = idx & 3;
            size_t g = (size_t)(row0 + row) * CDIM + k0 + ch * 8;
            CP16(base + GAH + row * 80 + ch * 16, g_oh + g);
            CP16(base + GAL + row * 80 + ch * 16, g_ol + g);
        }
#pragma unroll
        for (int it = 0; it < 2; it++) {
            int idx = tid + it * 256;
            int row = idx >> 4, ch = idx & 15;
            size_t g = (size_t)(k0 + row) * CDIM + col0 + ch * 8;
            uint32_t sw = (uint32_t)(row * 256 + ((ch ^ (row & 7)) << 4));
            CP16(base + GBH + sw, g_wph + g);
        }
    };

    stage(0, 0);
    CP_COMMIT();

    const int NIT = CDIM / 32;
    for (int kt = 0; kt < NIT; kt++) {
        if (kt < NIT - 1) {
            stage((kt + 1) & 1, (kt + 1) * 32);
            CP_COMMIT();
            CP_WAIT1();
        } else {
            CP_WAIT0();
        }
        __syncthreads();
        gemm_compute_step(acc, sb + (uint32_t)((kt & 1) * GBUF), wm, wn, lane);
        __syncthreads();
    }

    const int gid = lane >> 2, tq = lane & 3;
#pragma unroll
    for (int j = 0; j < 8; j++) {
        int col = col0 + wn + j * 8 + tq * 2;
        float2 bv = *(const float2*)&bias[col];
#pragma unroll
        for (int mi = 0; mi < 2; mi++) {
#pragma unroll
            for (int rg = 0; rg < 2; rg++) {
                int m = row0 + wm + mi * 16 + gid + rg * 8;
                float2 o = make_float2(acc[mi][j][rg * 2] + bv.x,
                                       acc[mi][j][rg * 2 + 1] + bv.y);
                *(float2*)&out[(size_t)m * CDIM + col] = o;
            }
        }
    }
}

// ============================================================
extern "C" void kernel_launch(void* const* d_in, const int* in_sizes, int n_in,
                              void* d_out, int out_size)
{
    const float* x      = (const float*)d_in[0];
    const float* w_qkv  = (const float*)d_in[1];
    const float* w_proj = (const float*)d_in[2];
    const float* b_proj = (const float*)d_in[3];
    float* out = (float*)d_out;

    (void)in_sizes; (void)n_in; (void)out_size;

    cudaFuncSetAttribute(qkv_tc_kernel,
                         cudaFuncAttributeMaxDynamicSharedMemorySize, GEMM_SMEM);
    cudaFuncSetAttribute(attn_mma_kernel,
                         cudaFuncAttributeMaxDynamicSharedMemorySize, ATT_SMEM);
    cudaFuncSetAttribute(proj_tc_kernel,
                         cudaFuncAttributeMaxDynamicSharedMemorySize, GEMM_SMEM);

    convert_kernel<<<NCONV_BLOCKS, 256>>>(x, w_qkv, w_proj);

    qkv_tc_kernel<<<dim3(3 * CDIM / 128, (BATCH * NSEQ) / 128), 256, GEMM_SMEM>>>();

    attn_mma_kernel<<<dim3(NSEQ / 128, BH_TOT, NSPLIT), 256, ATT_SMEM>>>();

    combine_kernel<<<NCOMB_BLOCKS, 256>>>();

    proj_tc_kernel<<<dim3(CDIM / 128, (BATCH * NSEQ) / 128), 256, GEMM_SMEM>>>(b_proj, out);
}

// round 13
// speedup vs baseline: 8.0350x; 1.0016x over previous
#include <cuda_runtime.h>
#include <cuda_fp16.h>
#include <cstdint>

#define BATCH 2
#define NSEQ  4096
#define CDIM  384
#define NH    6
#define HD    64
#define BH_TOT (BATCH * NH)
#define QK_SCALE 0.125f
#define L2E 1.4426950408889634f
#define NSPLIT 3
#define NKB (NSEQ / 64)

// ================= scratch (allocation-free: __device__ globals) =============
__device__ __half g_xh[BATCH * NSEQ * CDIM];  // x as fp16 hi/lo
__device__ __half g_xl[BATCH * NSEQ * CDIM];
__device__ __half g_wqh[CDIM * 3 * CDIM];     // w_qkv hi only
__device__ __half g_wph[CDIM * CDIM];         // w_proj hi only

__device__ __half g_qh[BH_TOT * NSEQ * HD];   // [BH,N,64] pre-scaled, hi only
__device__ __half g_kh[BH_TOT * NSEQ * HD];   // K hi only
__device__ __half g_vh[BH_TOT * NSEQ * HD];   // V hi only

__device__ float  g_opart[NSPLIT * BH_TOT * NSEQ * HD];  // split-KV partial O
__device__ float2 g_ml[NSPLIT * BH_TOT * NSEQ];          // per-row (m, l)

__device__ __half g_oh[BATCH * NSEQ * CDIM];  // attention out hi/lo
__device__ __half g_ol[BATCH * NSEQ * CDIM];

__device__ __forceinline__ float ex2f_fast(float x) {
    float y;
    asm("ex2.approx.f32 %0, %1;" : "=f"(y) : "f"(x));
    return y;
}

// packed fp16x2 exp2
__device__ __forceinline__ uint32_t ex2_h2(uint32_t t) {
    uint32_t y;
    asm("ex2.approx.f16x2 %0, %1;" : "=r"(y) : "r"(t));
    return y;
}

// fp16 split: hi pair + exact residual pair
__device__ __forceinline__ void split2(float a, float b, uint32_t& hi, uint32_t& lo) {
    __half2 h = __floats2half2_rn(a, b);
    hi = *reinterpret_cast<uint32_t*>(&h);
    float2 hf = __half22float2(h);
    __half2 l = __floats2half2_rn(a - hf.x, b - hf.y);
    lo = *reinterpret_cast<uint32_t*>(&l);
}

__device__ __forceinline__ uint32_t pack_h2(float a, float b) {
    __half2 h = __floats2half2_rn(a, b);
    return *reinterpret_cast<uint32_t*>(&h);
}

__device__ __forceinline__ float2 unpack_h2(uint32_t u) {
    __half2 h = *reinterpret_cast<__half2*>(&u);
    return __half22float2(h);
}

__device__ __forceinline__ uint32_t smem_u32(const void* p) {
    uint32_t a;
    asm("{ .reg .u64 t; cvta.to.shared.u64 t, %1; cvt.u32.u64 %0, t; }" : "=r"(a) : "l"(p));
    return a;
}

__device__ __forceinline__ void ldsm_x4(uint32_t* r, uint32_t addr) {
    asm volatile("ldmatrix.sync.aligned.m8n8.x4.shared.b16 {%0,%1,%2,%3}, [%4];"
                 : "=r"(r[0]), "=r"(r[1]), "=r"(r[2]), "=r"(r[3]) : "r"(addr));
}
__device__ __forceinline__ void ldsm_x4_t(uint32_t* r, uint32_t addr) {
    asm volatile("ldmatrix.sync.aligned.m8n8.x4.trans.shared.b16 {%0,%1,%2,%3}, [%4];"
                 : "=r"(r[0]), "=r"(r[1]), "=r"(r[2]), "=r"(r[3]) : "r"(addr));
}

#define MMA16816(d, a, b) \
    asm volatile( \
        "mma.sync.aligned.m16n8k16.row.col.f32.f16.f16.f32 " \
        "{%0,%1,%2,%3}, {%4,%5,%6,%7}, {%8,%9}, {%0,%1,%2,%3};" \
        : "+f"((d)[0]), "+f"((d)[1]), "+f"((d)[2]), "+f"((d)[3]) \
        : "r"((a)[0]), "r"((a)[1]), "r"((a)[2]), "r"((a)[3]), \
          "r"((b)[0]), "r"((b)[1]))

#define CP16(dst_u32, src_ptr) \
    asm volatile("cp.async.cg.shared.global [%0], [%1], 16;" :: "r"(dst_u32), "l"(src_ptr))
#define CP_COMMIT() asm volatile("cp.async.commit_group;" ::: "memory")
#define CP_WAIT1()  asm volatile("cp.async.wait_group 1;" ::: "memory")
#define CP_WAIT0()  asm volatile("cp.async.wait_group 0;" ::: "memory")

// ============================================================
// Kernel 0: fp32 -> fp16 conversion. x: hi+lo; wq/wp: hi only.
// ============================================================
#define NX4  (BATCH * NSEQ * CDIM / 4)
#define NWQ4 (CDIM * 3 * CDIM / 4)
#define NWP4 (CDIM * CDIM / 4)
#define NCONV_BLOCKS ((NX4 + NWQ4 + NWP4 + 255) / 256)

__global__ __launch_bounds__(256) void convert_kernel(
    const float* __restrict__ x, const float* __restrict__ wq,
    const float* __restrict__ wp)
{
    int i = blockIdx.x * 256 + threadIdx.x;
    if (i < NX4) {
        float4 f = *(const float4*)(x + (size_t)i * 4);
        uint2 h, l;
        split2(f.x, f.y, h.x, l.x);
        split2(f.z, f.w, h.y, l.y);
        *(uint2*)(g_xh + (size_t)i * 4) = h;
        *(uint2*)(g_xl + (size_t)i * 4) = l;
    } else if (i < NX4 + NWQ4) {
        int off = i - NX4;
        float4 f = *(const float4*)(wq + (size_t)off * 4);
        uint2 h;
        h.x = pack_h2(f.x, f.y);
        h.y = pack_h2(f.z, f.w);
        *(uint2*)(g_wqh + (size_t)off * 4) = h;
    } else if (i < NX4 + NWQ4 + NWP4) {
        int off = i - NX4 - NWQ4;
        float4 f = *(const float4*)(wp + (size_t)off * 4);
        uint2 h;
        h.x = pack_h2(f.x, f.y);
        h.y = pack_h2(f.z, f.w);
        *(uint2*)(g_wph + (size_t)off * 4) = h;
    }
}

// ============================================================
// Shared GEMM compute: 128x128 CTA, 8 warps (4m x 2n), K-step 32,
// 2-chain (A hi/lo x B hi), cp.async double-buffered, ldsm.x4.
// ============================================================
#define GAH 0
#define GAL 10240
#define GBH 20480
#define GBUF 28672
#define GEMM_SMEM (2 * GBUF)

__device__ __forceinline__ void gemm_compute_step(
    float acc[2][8][4], uint32_t bb, int wm, int wn, int lane)
{
    const int l8 = lane & 7, l16 = lane & 15;
    const int jsel = lane >> 4;
#pragma unroll
    for (int s = 0; s < 2; s++) {
        uint32_t ah[2][4], al[2][4];
        uint32_t arow = (uint32_t)((wm + l8 + 8 * ((lane >> 3) & 1)) * 80 +
                                   (2 * s + (lane >> 4)) * 16);
        ldsm_x4(ah[0], bb + GAH + arow);
        ldsm_x4(ah[1], bb + GAH + arow + 16 * 80);
        ldsm_x4(al[0], bb + GAL + arow);
        ldsm_x4(al[1], bb + GAL + arow + 16 * 80);

        uint32_t bf[8][2];
        const uint32_t brow = (uint32_t)((s * 16 + l16) * 256);
#pragma unroll
        for (int j = 0; j < 8; j += 2) {
            int jj = (wn >> 3) + j + jsel;
            uint32_t r[4];
            ldsm_x4_t(r, bb + GBH + brow + (uint32_t)(((jj ^ l8) << 4)));
            bf[j][0] = r[0]; bf[j][1] = r[1];
            bf[j + 1][0] = r[2]; bf[j + 1][1] = r[3];
        }
#pragma unroll
        for (int j = 0; j < 8; j++) {
            MMA16816(acc[0][j], ah[0], bf[j]);
            MMA16816(acc[1][j], ah[1], bf[j]);
        }
#pragma unroll
        for (int j = 0; j < 8; j++) {
            MMA16816(acc[0][j], al[0], bf[j]);
            MMA16816(acc[1][j], al[1], bf[j]);
        }
    }
}

// ============================================================
// Kernel 1: QKV GEMM -> Q(x0.125)/K/V hi [BH,N,64]
// ============================================================
__global__ __launch_bounds__(256, 2) void qkv_tc_kernel()
{
    extern __shared__ char sm[];
    const uint32_t sb = smem_u32(sm);
    const int tid = threadIdx.x, warp = tid >> 5, lane = tid & 31;
    const int wm = (warp & 3) * 32, wn = (warp >> 2) * 64;
    const int row0 = blockIdx.y * 128, col0 = blockIdx.x * 128;

    float acc[2][8][4];
#pragma unroll
    for (int mi = 0; mi < 2; mi++)
#pragma unroll
        for (int j = 0; j < 8; j++)
#pragma unroll
            for (int i = 0; i < 4; i++) acc[mi][j][i] = 0.0f;

    auto stage = [&](int buf, int k0) {
        uint32_t base = sb + buf * GBUF;
#pragma unroll
        for (int it = 0; it < 2; it++) {
            int idx = tid + it * 256;
            int row = idx >> 2, ch = idx & 3;
            size_t g = (size_t)(row0 + row) * CDIM + k0 + ch * 8;
            CP16(base + GAH + row * 80 + ch * 16, g_xh + g);
            CP16(base + GAL + row * 80 + ch * 16, g_xl + g);
        }
#pragma unroll
        for (int it = 0; it < 2; it++) {
            int idx = tid + it * 256;
            int row = idx >> 4, ch = idx & 15;
            size_t g = (size_t)(k0 + row) * (3 * CDIM) + col0 + ch * 8;
            uint32_t sw = (uint32_t)(row * 256 + ((ch ^ (row & 7)) << 4));
            CP16(base + GBH + sw, g_wqh + g);
        }
    };

    stage(0, 0);
    CP_COMMIT();

    const int NIT = CDIM / 32;
    for (int kt = 0; kt < NIT; kt++) {
        if (kt < NIT - 1) {
            stage((kt + 1) & 1, (kt + 1) * 32);
            CP_COMMIT();
            CP_WAIT1();
        } else {
            CP_WAIT0();
        }
        __syncthreads();
        gemm_compute_step(acc, sb + (uint32_t)((kt & 1) * GBUF), wm, wn, lane);
        __syncthreads();
    }

    // epilogue: hi only
    const int gid = lane >> 2, tq = lane & 3;
#pragma unroll
    for (int j = 0; j < 8; j++) {
        int col = col0 + wn + j * 8 + tq * 2;
        int which = col / CDIM, cm = col % CDIM;
        int h = cm / HD, d = cm % HD;
        float sc = (which == 0) ? QK_SCALE : 1.0f;
        __half* hp = (which == 0) ? g_qh : (which == 1) ? g_kh : g_vh;
#pragma unroll
        for (int mi = 0; mi < 2; mi++) {
#pragma unroll
            for (int rg = 0; rg < 2; rg++) {
                int m = row0 + wm + mi * 16 + gid + rg * 8;
                int b = m >> 12, n = m & (NSEQ - 1);
                size_t base = (((size_t)(b * NH + h)) * NSEQ + n) * HD + d;
                *(uint32_t*)&hp[base] =
                    pack_h2(acc[mi][j][rg * 2] * sc, acc[mi][j][rg * 2 + 1] * sc);
            }
        }
    }
}

// ============================================================
// Kernel 2: flash attention, single-chain fp16, 3-way split-KV,
// ldsm.x4 loads, fp16x2 softmax exp, ballot-guarded rescale.
// ============================================================
#define STG 16384
#define SKH 0
#define SVH 8192
#define ATT_SMEM (2 * STG)

__global__ __launch_bounds__(256, 2) void attn_mma_kernel()
{
    extern __shared__ char smem[];
    const uint32_t sbase = smem_u32(smem);

    const int tid = threadIdx.x;
    const int warp = tid >> 5, lane = tid & 31;
    const int bh = blockIdx.y;
    const int z = blockIdx.z;
    const int r0 = blockIdx.x * 128;
    const int R = r0 + warp * 16;

    const int l8 = lane & 7;
    const int hseg = (lane >> 3) & 1;
    const int jsel = lane >> 4;
    const int rA = R + (lane >> 2);
    const int kcol = (lane & 3) * 2;

    const int kb0 = (z * NKB) / NSPLIT;
    const int kb1 = ((z + 1) * NKB) / NSPLIT;
    const int nb = kb1 - kb0;

    const __half* Qh = g_qh + (size_t)bh * NSEQ * HD;
    const __half* Kh = g_kh + (size_t)bh * NSEQ * HD;
    const __half* Vh = g_vh + (size_t)bh * NSEQ * HD;

    // Q hi a-fragments in registers
    uint32_t qah[4][4];
#pragma unroll
    for (int s = 0; s < 4; s++) {
        qah[s][0] = *(const uint32_t*)&Qh[(size_t)rA * HD + s * 16 + kcol];
        qah[s][1] = *(const uint32_t*)&Qh[(size_t)(rA + 8) * HD + s * 16 + kcol];
        qah[s][2] = *(const uint32_t*)&Qh[(size_t)rA * HD + s * 16 + 8 + kcol];
        qah[s][3] = *(const uint32_t*)&Qh[(size_t)(rA + 8) * HD + s * 16 + 8 + kcol];
    }

    float of[8][4];
#pragma unroll
    for (int j = 0; j < 8; j++)
#pragma unroll
        for (int i = 0; i < 4; i++) of[j][i] = 0.0f;
    float mA = -1e30f, mB = -1e30f, lA = 0.0f, lB = 0.0f;

    const uint32_t krow = (uint32_t)(l8 * 128);

    auto stage = [&](int st, int kr0) {
#pragma unroll
        for (int it = 0; it < 2; it++) {
            int idx = tid + it * 256;
            int row = idx >> 3, ch = idx & 7;
            uint32_t sw = (uint32_t)(st * STG + row * 128 + ((ch ^ (row & 7)) << 4));
            size_t g = (size_t)(kr0 + row) * HD + ch * 8;
            CP16(sbase + sw + SKH, Kh + g);
            CP16(sbase + sw + SVH, Vh + g);
        }
    };

    stage(0, kb0 * 64);
    CP_COMMIT();

    for (int it = 0; it < nb; it++) {
        if (it < nb - 1) {
            stage((it + 1) & 1, (kb0 + it + 1) * 64);
            CP_COMMIT();
            CP_WAIT1();
        } else {
            CP_WAIT0();
        }
        __syncthreads();
        const uint32_t stb = sbase + (uint32_t)((it & 1) * STG);

        // ---- S = Q K^T (single chain, ldsm.x4) ----
        float sf[8][4];
#pragma unroll
        for (int j = 0; j < 8; j++)
#pragma unroll
            for (int i = 0; i < 4; i++) sf[j][i] = 0.0f;

#pragma unroll
        for (int s = 0; s < 4; s++) {
            uint32_t chsw = (uint32_t)((((2 * s + hseg) ^ l8) << 4));
#pragma unroll
            for (int jc = 0; jc < 8; jc += 4) {
                uint32_t kbf[4][2];
#pragma unroll
                for (int jj = 0; jj < 4; jj += 2) {
                    uint32_t r[4];
                    ldsm_x4(r, stb + SKH + (uint32_t)((jc + jj + jsel) * 1024) + krow + chsw);
                    kbf[jj][0] = r[0]; kbf[jj][1] = r[1];
                    kbf[jj + 1][0] = r[2]; kbf[jj + 1][1] = r[3];
                }
#pragma unroll
                for (int j = 0; j < 4; j++) MMA16816(sf[jc + j], qah[s], kbf[j]);
            }
        }

        // ---- online softmax (fp16x2 exp) ----
        float mxA = sf[0][0], mxB = sf[0][2];
#pragma unroll
        for (int j = 0; j < 8; j++) {
            mxA = fmaxf(mxA, fmaxf(sf[j][0], sf[j][1]));
            mxB = fmaxf(mxB, fmaxf(sf[j][2], sf[j][3]));
        }
        mxA = fmaxf(mxA, __shfl_xor_sync(0xffffffffu, mxA, 1));
        mxA = fmaxf(mxA, __shfl_xor_sync(0xffffffffu, mxA, 2));
        mxB = fmaxf(mxB, __shfl_xor_sync(0xffffffffu, mxB, 1));
        mxB = fmaxf(mxB, __shfl_xor_sync(0xffffffffu, mxB, 2));

        float mnA = fmaxf(mA, mxA), mnB = fmaxf(mB, mxB);
        float corrA = ex2f_fast((mA - mnA) * L2E);
        float corrB = ex2f_fast((mB - mnB) * L2E);
        mA = mnA; mB = mnB;
        const float nlA = mnA * L2E, nlB = mnB * L2E;

        // P in packed fp16 directly (also the PV MMA operand)
        uint32_t pA[8], pB[8];
        float sumA = 0.0f, sumB = 0.0f;
#pragma unroll
        for (int j = 0; j < 8; j++) {
            float t0 = fmaf(sf[j][0], L2E, -nlA);
            float t1 = fmaf(sf[j][1], L2E, -nlA);
            float t2 = fmaf(sf[j][2], L2E, -nlB);
            float t3 = fmaf(sf[j][3], L2E, -nlB);
            pA[j] = ex2_h2(pack_h2(t0, t1));
            pB[j] = ex2_h2(pack_h2(t2, t3));
            float2 fa = unpack_h2(pA[j]);
            float2 fb = unpack_h2(pB[j]);
            sumA += fa.x + fa.y;
            sumB += fb.x + fb.y;
        }
        lA = lA * corrA + sumA;
        lB = lB * corrB + sumB;

        // rescale O only if any lane's max moved (warp-uniform branch)
        if (__ballot_sync(0xffffffffu, (corrA != 1.0f) || (corrB != 1.0f))) {
#pragma unroll
            for (int j = 0; j < 8; j++) {
                of[j][0] *= corrA; of[j][1] *= corrA;
                of[j][2] *= corrB; of[j][3] *= corrB;
            }
        }

        // ---- O += P V (single chain, ldsm.x4.trans) ----
#pragma unroll
        for (int s = 0; s < 4; s++) {
            uint32_t pah[4];
            pah[0] = pA[2 * s];
            pah[1] = pB[2 * s];
            pah[2] = pA[2 * s + 1];
            pah[3] = pB[2 * s + 1];

            uint32_t vrow = (uint32_t)((16 * s + 8 * hseg + l8) * 128);
#pragma unroll
            for (int jc = 0; jc < 8; jc += 4) {
                uint32_t vbf[4][2];
#pragma unroll
                for (int jj = 0; jj < 4; jj += 2) {
                    uint32_t r[4];
                    ldsm_x4_t(r, stb + SVH + vrow +
                              (uint32_t)((((jc + jj + jsel) ^ l8) << 4)));
                    vbf[jj][0] = r[0]; vbf[jj][1] = r[1];
                    vbf[jj + 1][0] = r[2]; vbf[jj + 1][1] = r[3];
                }
#pragma unroll
                for (int j = 0; j < 4; j++) MMA16816(of[jc + j], pah, vbf[j]);
            }
        }
        __syncthreads();
    }

    // ---- epilogue: write PARTIAL O (un-normalized) + (m, l) ----
    lA += __shfl_xor_sync(0xffffffffu, lA, 1);
    lA += __shfl_xor_sync(0xffffffffu, lA, 2);
    lB += __shfl_xor_sync(0xffffffffu, lB, 1);
    lB += __shfl_xor_sync(0xffffffffu, lB, 2);

    float* opart = g_opart + (size_t)z * BH_TOT * NSEQ * HD + (size_t)bh * NSEQ * HD;
#pragma unroll
    for (int j = 0; j < 8; j++) {
        int c = j * 8 + kcol;
        float2 oa = make_float2(of[j][0], of[j][1]);
        float2 ob = make_float2(of[j][2], of[j][3]);
        *(float2*)&opart[(size_t)rA * HD + c] = oa;
        *(float2*)&opart[(size_t)(rA + 8) * HD + c] = ob;
    }
    if ((lane & 3) == 0) {
        size_t mlbase = (size_t)z * BH_TOT * NSEQ + (size_t)bh * NSEQ;
        g_ml[mlbase + rA] = make_float2(mA, lA);
        g_ml[mlbase + rA + 8] = make_float2(mB, lB);
    }
}

// ============================================================
// Kernel 2b: combine split-KV partials -> g_oh/g_ol [B,N,C]
// ============================================================
#define NCOMB_BLOCKS (BH_TOT * NSEQ * 16 / 256)

__global__ __launch_bounds__(256) void combine_kernel()
{
    int idx = blockIdx.x * 256 + threadIdx.x;
    int row = idx >> 4;                 // bh*NSEQ + n
    int dq = (idx & 15) * 4;

    float2 ml0 = g_ml[row];
    float2 ml1 = g_ml[BH_TOT * NSEQ + row];
    float2 ml2 = g_ml[2 * BH_TOT * NSEQ + row];
    float ms = fmaxf(ml0.x, fmaxf(ml1.x, ml2.x));
    float w0 = ex2f_fast((ml0.x - ms) * L2E);
    float w1 = ex2f_fast((ml1.x - ms) * L2E);
    float w2 = ex2f_fast((ml2.x - ms) * L2E);
    float inv = 1.0f / (ml0.y * w0 + ml1.y * w1 + ml2.y * w2);

    size_t pbase = (size_t)row * HD + dq;
    float4 o0 = *(const float4*)&g_opart[pbase];
    float4 o1 = *(const float4*)&g_opart[(size_t)BH_TOT * NSEQ * HD + pbase];
    float4 o2 = *(const float4*)&g_opart[2 * (size_t)BH_TOT * NSEQ * HD + pbase];

    float4 o;
    o.x = (o0.x * w0 + o1.x * w1 + o2.x * w2) * inv;
    o.y = (o0.y * w0 + o1.y * w1 + o2.y * w2) * inv;
    o.z = (o0.z * w0 + o1.z * w1 + o2.z * w2) * inv;
    o.w = (o0.w * w0 + o1.w * w1 + o2.w * w2) * inv;

    int bh = row >> 12;                 // row / NSEQ
    int n = row & (NSEQ - 1);
    int b = bh / NH, h = bh % NH;
    size_t obase = ((size_t)b * NSEQ + n) * CDIM + h * HD + dq;

    uint32_t h0, l0, h1, l1;
    split2(o.x, o.y, h0, l0);
    split2(o.z, o.w, h1, l1);
    uint2 uh; uh.x = h0; uh.y = h1;
    uint2 ul; ul.x = l0; ul.y = l1;
    *(uint2*)&g_oh[obase] = uh;
    *(uint2*)&g_ol[obase] = ul;
}

// ============================================================
// Kernel 3: proj GEMM (2-chain) + bias -> out fp32
// ============================================================
__global__ __launch_bounds__(256, 2) void proj_tc_kernel(
    const float* __restrict__ bias, float* __restrict__ out)
{
    extern __shared__ char sm[];
    const uint32_t sb = smem_u32(sm);
    const int tid = threadIdx.x, warp = tid >> 5, lane = tid & 31;
    const int wm = (warp & 3) * 32, wn = (warp >> 2) * 64;
    const int row0 = blockIdx.y * 128, col0 = blockIdx.x * 128;

    float acc[2][8][4];
#pragma unroll
    for (int mi = 0; mi < 2; mi++)
#pragma unroll
        for (int j = 0; j < 8; j++)
#pragma unroll
            for (int i = 0; i < 4; i++) acc[mi][j][i] = 0.0f;

    auto stage = [&](int buf, int k0) {
        uint32_t base = sb + buf * GBUF;
#pragma unroll
        for (int it = 0; it < 2; it++) {
            int idx = tid + it * 256;
            int row = idx >> 2, ch = idx & 3;
            size_t g = (size_t)(row0 + row) * CDIM + k0 + ch * 8;
            CP16(base + GAH + row * 80 + ch * 16, g_oh + g);
            CP16(base + GAL + row * 80 + ch * 16, g_ol + g);
        }
#pragma unroll
        for (int it = 0; it < 2; it++) {
            int idx = tid + it * 256;
            int row = idx >> 4, ch = idx & 15;
            size_t g = (size_t)(k0 + row) * CDIM + col0 + ch * 8;
            uint32_t sw = (uint32_t)(row * 256 + ((ch ^ (row & 7)) << 4));
            CP16(base + GBH + sw, g_wph + g);
        }
    };

    stage(0, 0);
    CP_COMMIT();

    const int NIT = CDIM / 32;
    for (int kt = 0; kt < NIT; kt++) {
        if (kt < NIT - 1) {
            stage((kt + 1) & 1, (kt + 1) * 32);
            CP_COMMIT();
            CP_WAIT1();
        } else {
            CP_WAIT0();
        }
        __syncthreads();
        gemm_compute_step(acc, sb + (uint32_t)((kt & 1) * GBUF), wm, wn, lane);
        __syncthreads();
    }

    const int gid = lane >> 2, tq = lane & 3;
#pragma unroll
    for (int j = 0; j < 8; j++) {
        int col = col0 + wn + j * 8 + tq * 2;
        float2 bv = *(const float2*)&bias[col];
#pragma unroll
        for (int mi = 0; mi < 2; mi++) {
#pragma unroll
            for (int rg = 0; rg < 2; rg++) {
                int m = row0 + wm + mi * 16 + gid + rg * 8;
                float2 o = make_float2(acc[mi][j][rg * 2] + bv.x,
                                       acc[mi][j][rg * 2 + 1] + bv.y);
                *(float2*)&out[(size_t)m * CDIM + col] = o;
            }
        }
    }
}

// ============================================================
extern "C" void kernel_launch(void* const* d_in, const int* in_sizes, int n_in,
                              void* d_out, int out_size)
{
    const float* x      = (const float*)d_in[0];
    const float* w_qkv  = (const float*)d_in[1];
    const float* w_proj = (const float*)d_in[2];
    const float* b_proj = (const float*)d_in[3];
    float* out = (float*)d_out;

    (void)in_sizes; (void)n_in; (void)out_size;

    cudaFuncSetAttribute(qkv_tc_kernel,
                         cudaFuncAttributeMaxDynamicSharedMemorySize, GEMM_SMEM);
    cudaFuncSetAttribute(attn_mma_kernel,
                         cudaFuncAttributeMaxDynamicSharedMemorySize, ATT_SMEM);
    cudaFuncSetAttribute(proj_tc_kernel,
                         cudaFuncAttributeMaxDynamicSharedMemorySize, GEMM_SMEM);

    convert_kernel<<<NCONV_BLOCKS, 256>>>(x, w_qkv, w_proj);

    qkv_tc_kernel<<<dim3(3 * CDIM / 128, (BATCH * NSEQ) / 128), 256, GEMM_SMEM>>>();

    attn_mma_kernel<<<dim3(NSEQ / 128, BH_TOT, NSPLIT), 256, ATT_SMEM>>>();

    combine_kernel<<<NCOMB_BLOCKS, 256>>>();

    proj_tc_kernel<<<dim3(CDIM / 128, (BATCH * NSEQ) / 128), 256, GEMM_SMEM>>>(b_proj, out);
}